// round 2
// baseline (speedup 1.0000x reference)
#include <cuda_runtime.h>
#include <cstdint>
#include <cstdio>

// Problem dims
#define BB   32
#define TT   64
#define EE   256
#define UU   512
#define DD   512
#define VV   32000
#define NTOK 2048      // B*T
#define G4U  2048      // 4*U
#define G2U  1024      // 2*U
#define G4D  2048      // 4*D

// ---------------- scratch (__device__ globals: allocation-free) ----------------
__device__ float g_xe  [NTOK * EE];        // [t*B+b][E]
__device__ float g_Zf  [NTOK * G4U];       // xe@Wxf + bf
__device__ float g_Zb  [NTOK * G4U];       // xe@Wxb + bb
__device__ float g_a   [NTOK * G2U];       // [t*B+b][hf(512) | hb(512)]
__device__ float g_aW1 [NTOK * 10];        // a@W1[:1024] + b1
__device__ float g_aWxd[NTOK * G4D];       // a@Wxd
__device__ float g_hd  [BB * DD];          // current decoder h
__device__ float g_Hd  [NTOK * DD];        // all decoder h, [t*B+b][D]
__device__ int   g_ebar[2][TT];
__device__ int   g_efin[2];
__device__ int   g_dbar[TT];
__device__ int   g_dfin;

__device__ __forceinline__ float sigf(float x) { return 1.f / (1.f + expf(-x)); }

__device__ __forceinline__ void bar_sync(int* slot, int n) {
    __threadfence();
    __syncthreads();
    if (threadIdx.x == 0) {
        atomicAdd(slot, 1);
        while (*(volatile int*)slot < n) { }
    }
    __syncthreads();
}

__device__ __forceinline__ uint32_t f2tf(float x) {
    uint32_t r;
    asm("cvt.rna.tf32.f32 %0, %1;" : "=r"(r) : "f"(x));
    return r;
}

// ---------------- embedding gather: xe[t*B+b][:] = emb[x[b][t]] ----------------
__global__ void k_embed(const int* __restrict__ x, const float* __restrict__ emb) {
    int row = blockIdx.x;            // t*B + b
    int t = row >> 5, b = row & 31;
    int tok = x[b * TT + t];
    const float4* src = reinterpret_cast<const float4*>(emb + (size_t)tok * EE);
    float4* dst = reinterpret_cast<float4*>(g_xe + (size_t)row * EE);
    dst[threadIdx.x] = src[threadIdx.x];   // 64 threads * float4 = 256 floats
}

// ---------------- generic tf32 GEMM: C[M,N] = A[M,K] @ B[K,N] (+bias), optional row remap
// BM=128, BN=128, BK=32, 256 threads, warp grid 4(M) x 2(N), warp tile 32x64.
__global__ __launch_bounds__(256) void k_gemm_tf32(
    const float* __restrict__ A, const float* __restrict__ Bm,
    const float* __restrict__ bias, float* __restrict__ C,
    int M, int N, int K, int remap)
{
    __shared__ uint32_t As[128][33];
    __shared__ uint32_t Bs[32][132];
    int tid  = threadIdx.x;
    int lane = tid & 31, warp = tid >> 5;
    int gid  = lane >> 2, tig = lane & 3;
    int wm   = warp & 3,  wn  = warp >> 2;
    int m0 = blockIdx.y << 7, n0 = blockIdx.x << 7;

    float acc[2][8][4];
#pragma unroll
    for (int a = 0; a < 2; a++)
#pragma unroll
        for (int b = 0; b < 8; b++)
#pragma unroll
            for (int c = 0; c < 4; c++) acc[a][b][c] = 0.f;

    for (int k0 = 0; k0 < K; k0 += 32) {
#pragma unroll
        for (int i = 0; i < 4; i++) {
            int idx = tid + (i << 8);
            int r = idx >> 3, c4 = (idx & 7) << 2;
            const float4 v = *reinterpret_cast<const float4*>(A + (size_t)(m0 + r) * K + k0 + c4);
            As[r][c4 + 0] = f2tf(v.x); As[r][c4 + 1] = f2tf(v.y);
            As[r][c4 + 2] = f2tf(v.z); As[r][c4 + 3] = f2tf(v.w);
        }
#pragma unroll
        for (int i = 0; i < 4; i++) {
            int idx = tid + (i << 8);
            int r = idx >> 5, c4 = (idx & 31) << 2;
            const float4 v = *reinterpret_cast<const float4*>(Bm + (size_t)(k0 + r) * N + n0 + c4);
            Bs[r][c4 + 0] = f2tf(v.x); Bs[r][c4 + 1] = f2tf(v.y);
            Bs[r][c4 + 2] = f2tf(v.z); Bs[r][c4 + 3] = f2tf(v.w);
        }
        __syncthreads();
#pragma unroll
        for (int kk = 0; kk < 32; kk += 8) {
            uint32_t af[2][4];
#pragma unroll
            for (int mt = 0; mt < 2; mt++) {
                int rb = (wm << 5) + (mt << 4);
                af[mt][0] = As[rb + gid    ][kk + tig];
                af[mt][1] = As[rb + gid + 8][kk + tig];
                af[mt][2] = As[rb + gid    ][kk + tig + 4];
                af[mt][3] = As[rb + gid + 8][kk + tig + 4];
            }
#pragma unroll
            for (int nt = 0; nt < 8; nt++) {
                uint32_t b0 = Bs[kk + tig    ][(wn << 6) + (nt << 3) + gid];
                uint32_t b1 = Bs[kk + tig + 4][(wn << 6) + (nt << 3) + gid];
#pragma unroll
                for (int mt = 0; mt < 2; mt++) {
                    asm volatile(
                        "mma.sync.aligned.m16n8k8.row.col.f32.tf32.tf32.f32 "
                        "{%0,%1,%2,%3}, {%4,%5,%6,%7}, {%8,%9}, {%0,%1,%2,%3};\n"
                        : "+f"(acc[mt][nt][0]), "+f"(acc[mt][nt][1]),
                          "+f"(acc[mt][nt][2]), "+f"(acc[mt][nt][3])
                        : "r"(af[mt][0]), "r"(af[mt][1]), "r"(af[mt][2]), "r"(af[mt][3]),
                          "r"(b0), "r"(b1));
                }
            }
        }
        __syncthreads();
    }
#pragma unroll
    for (int mt = 0; mt < 2; mt++) {
#pragma unroll
        for (int nt = 0; nt < 8; nt++) {
            int col = n0 + (wn << 6) + (nt << 3) + (tig << 1);
            float b0v = bias ? bias[col]     : 0.f;
            float b1v = bias ? bias[col + 1] : 0.f;
            int r0 = m0 + (wm << 5) + (mt << 4) + gid;
            int r1 = r0 + 8;
            int or0 = remap ? ((r0 & 31) * TT + (r0 >> 5)) : r0;
            int or1 = remap ? ((r1 & 31) * TT + (r1 >> 5)) : r1;
            float2 v0 = make_float2(acc[mt][nt][0] + b0v, acc[mt][nt][1] + b1v);
            float2 v1 = make_float2(acc[mt][nt][2] + b0v, acc[mt][nt][3] + b1v);
            *reinterpret_cast<float2*>(C + (size_t)or0 * N + col) = v0;
            *reinterpret_cast<float2*>(C + (size_t)or1 * N + col) = v1;
        }
    }
}

// ---------------- persistent bidirectional encoder LSTM ----------------
// 128 blocks: 0..63 forward, 64..127 backward. Each block owns 8 b x 32 d cells.
__global__ __launch_bounds__(256) void k_encoder(const float* __restrict__ Whf,
                                                 const float* __restrict__ Whb)
{
    int g   = blockIdx.x & 63;
    int dir = blockIdx.x >> 6;
    const float* Wh = dir ? Whb : Whf;
    const float* Z  = dir ? g_Zb : g_Zf;
    int tid = threadIdx.x;
    int dl = tid & 31, bl = tid >> 5;
    int bc = g & 3, dc = g >> 2;
    int b = bc * 8 + bl;
    int d = dc * 32 + dl;
    int aoff = dir * UU;
    int* bar = &g_ebar[dir][0];

    __shared__ float hsm[8][UU];    // this block's 8 batch rows of prev h
    float c = 0.f;

    for (int s = 0; s < TT; s++) {
        int t = dir ? (TT - 1 - s) : s;
        if (s > 0) {
            bar_sync(&bar[s], 64);
            int tp = dir ? (t + 1) : (t - 1);
            for (int i = tid; i < 8 * UU; i += 256) {
                int rb = i >> 9, k = i & (UU - 1);
                hsm[rb][k] = __ldcg(&g_a[(size_t)(tp * BB + bc * 8 + rb) * G2U + aoff + k]);
            }
            __syncthreads();
        }
        size_t zrow = (size_t)(t * BB + b) * G4U;
        float zi = Z[zrow + d];
        float zf = Z[zrow + UU + d];
        float zg = Z[zrow + 2 * UU + d];
        float zo = Z[zrow + 3 * UU + d];
        if (s > 0) {
#pragma unroll 4
            for (int k = 0; k < UU; k++) {
                float h = hsm[bl][k];
                const float* w = Wh + (size_t)k * G4U + d;
                zi += h * w[0];
                zf += h * w[UU];
                zg += h * w[2 * UU];
                zo += h * w[3 * UU];
            }
        }
        float ct = sigf(zf) * c + sigf(zi) * tanhf(zg);
        float h  = sigf(zo) * tanhf(ct);
        c = ct;
        g_a[(size_t)(t * BB + b) * G2U + aoff + d] = h;
    }
    __syncthreads();
    if (tid == 0) {
        __threadfence();
        if (atomicAdd(&g_efin[dir], 1) == 63) {
            for (int i = 0; i < TT; i++) bar[i] = 0;
            g_efin[dir] = 0;
        }
    }
}

// ---------------- aW1 = a @ W1[:1024] + b1  (tiny: [2048,10], K=1024) ----------------
__global__ __launch_bounds__(128) void k_aw1(const float* __restrict__ W1,
                                             const float* __restrict__ b1)
{
    __shared__ float red[128][10];
    int r = blockIdx.x;
    int tid = threadIdx.x;
    float acc[10];
#pragma unroll
    for (int j = 0; j < 10; j++) acc[j] = 0.f;
    for (int k = tid; k < G2U; k += 128) {
        float av = g_a[(size_t)r * G2U + k];
#pragma unroll
        for (int j = 0; j < 10; j++) acc[j] += av * W1[(size_t)k * 10 + j];
    }
#pragma unroll
    for (int j = 0; j < 10; j++) red[tid][j] = acc[j];
    __syncthreads();
    for (int s = 64; s > 0; s >>= 1) {
        if (tid < s)
#pragma unroll
            for (int j = 0; j < 10; j++) red[tid][j] += red[tid + s][j];
        __syncthreads();
    }
    if (tid < 10) g_aW1[(size_t)r * 10 + tid] = red[0][tid] + b1[tid];
}

// ---------------- persistent attention decoder ----------------
// 128 blocks x 256 threads. Block owns 4 b x 32 d cells (128 cells), 2-way k-split.
__global__ __launch_bounds__(256) void k_decoder(
    const float* __restrict__ W1, const float* __restrict__ W2,
    const float* __restrict__ b2, const float* __restrict__ Whd,
    const float* __restrict__ bd)
{
    int g = blockIdx.x;
    int bc = g & 7;            // 8 chunks of 4 b
    int dc = g >> 3;           // 16 chunks of 32 d
    int tid = threadIdx.x;
    int cell = tid & 127, half = tid >> 7;
    int bl = cell >> 5, dl = cell & 31;
    int b = bc * 4 + bl;
    int d = dc * 32 + dl;
    int warp = tid >> 5, lane = tid & 31;

    __shared__ float hsm[4][DD];       // 8KB: this block's 4 batch rows of decoder h
    __shared__ float hW1s[4][10];
    __shared__ float hpart[40][4];
    __shared__ float es[4][TT];
    __shared__ float scs[4][TT];
    __shared__ float gpart[128][4];

    float c = 0.f;
    if (half == 0) g_hd[(size_t)b * DD + d] = 0.f;   // init decoder state

    for (int t = 0; t < TT; t++) {
        bar_sync(&g_dbar[t], 128);
        // stage this block's h rows (L2-fresh)
        for (int i = tid; i < 4 * DD; i += 256) {
            int rb = i >> 9, k = i & (DD - 1);
            hsm[rb][k] = __ldcg(&g_hd[(size_t)(bc * 4 + rb) * DD + k]);
        }
        __syncthreads();
        // hW1[4][10] = h @ W1[1024:1536]
        if (tid < 160) {
            int p = tid >> 2, q = tid & 3;
            int bb = p / 10, j = p % 10;
            float a0 = 0.f;
            int k0 = q * 128;
            for (int k = k0; k < k0 + 128; k++)
                a0 += hsm[bb][k] * W1[(size_t)(G2U + k) * 10 + j];
            hpart[p][q] = a0;
        }
        __syncthreads();
        if (tid < 40) {
            int bb = tid / 10, j = tid % 10;
            hW1s[bb][j] = hpart[tid][0] + hpart[tid][1] + hpart[tid][2] + hpart[tid][3];
        }
        __syncthreads();
        // attention energies: e[bb][s] = relu(tanh(aW1 + hW1) @ W2 + b2)
        {
            int bb = tid >> 6, s = tid & 63;
            int bg = bc * 4 + bb;
            const float* aw = &g_aW1[(size_t)(s * BB + bg) * 10];
            float v = b2[0];
#pragma unroll
            for (int j = 0; j < 10; j++) v += tanhf(aw[j] + hW1s[bb][j]) * W2[j];
            es[bb][s] = fmaxf(v, 0.f);
        }
        __syncthreads();
        // softmax over s, one warp per batch row
        if (warp < 4) {
            int bb = warp;
            float v0 = es[bb][lane], v1 = es[bb][lane + 32];
            float mx = fmaxf(v0, v1);
#pragma unroll
            for (int o = 16; o > 0; o >>= 1) mx = fmaxf(mx, __shfl_xor_sync(0xffffffffu, mx, o));
            float e0 = expf(v0 - mx), e1 = expf(v1 - mx);
            float sm = e0 + e1;
#pragma unroll
            for (int o = 16; o > 0; o >>= 1) sm += __shfl_xor_sync(0xffffffffu, sm, o);
            float inv = 1.f / sm;
            scs[bb][lane] = e0 * inv;
            scs[bb][lane + 32] = e1 * inv;
        }
        __syncthreads();
        // gates: z = sum_s score*aWxd + h@Whd  (k-split across halves)
        float a0 = 0.f, a1 = 0.f, a2 = 0.f, a3 = 0.f;
        {
            int s0 = half * 32;
#pragma unroll 4
            for (int s = s0; s < s0 + 32; s++) {
                float sc = scs[bl][s];
                const float* aw = &g_aWxd[(size_t)(s * BB + b) * G4D + d];
                a0 += sc * aw[0];
                a1 += sc * aw[DD];
                a2 += sc * aw[2 * DD];
                a3 += sc * aw[3 * DD];
            }
            int k0 = half * 256;
#pragma unroll 4
            for (int k = k0; k < k0 + 256; k++) {
                float hk = hsm[bl][k];
                const float* w = Whd + (size_t)k * G4D + d;
                a0 += hk * w[0];
                a1 += hk * w[DD];
                a2 += hk * w[2 * DD];
                a3 += hk * w[3 * DD];
            }
        }
        if (half == 1) {
            gpart[cell][0] = a0; gpart[cell][1] = a1;
            gpart[cell][2] = a2; gpart[cell][3] = a3;
        }
        __syncthreads();
        if (half == 0) {
            float zi = a0 + gpart[cell][0] + bd[d];
            float zf = a1 + gpart[cell][1] + bd[DD + d];
            float zg = a2 + gpart[cell][2] + bd[2 * DD + d];
            float zo = a3 + gpart[cell][3] + bd[3 * DD + d];
            float ct = sigf(zf) * c + sigf(zi) * tanhf(zg);
            float h  = sigf(zo) * tanhf(ct);
            c = ct;
            g_hd[(size_t)b * DD + d] = h;
            g_Hd[(size_t)(t * BB + b) * DD + d] = h;
        }
    }
    __syncthreads();
    if (tid == 0) {
        __threadfence();
        if (atomicAdd(&g_dfin, 1) == 127) {
            for (int i = 0; i < TT; i++) g_dbar[i] = 0;
            g_dfin = 0;
        }
    }
}

// ---------------- in-place row softmax over V (row staged in 128KB smem) ----------------
__global__ void k_softmax_v(float* __restrict__ out) {
    extern __shared__ float row[];
    __shared__ float red[256];
    int r = blockIdx.x;
    float* p = out + (size_t)r * VV;
    int tid = threadIdx.x;
    float mx = -3.4e38f;
    for (int i = tid; i < VV; i += 256) {
        float v = p[i];
        row[i] = v;
        mx = fmaxf(mx, v);
    }
    red[tid] = mx; __syncthreads();
    for (int s = 128; s > 0; s >>= 1) {
        if (tid < s) red[tid] = fmaxf(red[tid], red[tid + s]);
        __syncthreads();
    }
    mx = red[0]; __syncthreads();
    float sum = 0.f;
    for (int i = tid; i < VV; i += 256) {
        float e = expf(row[i] - mx);
        row[i] = e;
        sum += e;
    }
    red[tid] = sum; __syncthreads();
    for (int s = 128; s > 0; s >>= 1) {
        if (tid < s) red[tid] += red[tid + s];
        __syncthreads();
    }
    float inv = 1.f / red[0];
    for (int i = tid; i < VV; i += 256) p[i] = row[i] * inv;
}

// ---------------- host driver ----------------
extern "C" void kernel_launch(void* const* d_in, const int* in_sizes, int n_in,
                              void* d_out, int out_size)
{
    (void)in_sizes; (void)n_in; (void)out_size;
    const int*   x   = (const int*)  d_in[0];
    const float* emb = (const float*)d_in[1];
    const float* Wxf = (const float*)d_in[2];
    const float* Whf = (const float*)d_in[3];
    const float* bf  = (const float*)d_in[4];
    const float* Wxb = (const float*)d_in[5];
    const float* Whb = (const float*)d_in[6];
    const float* bbv = (const float*)d_in[7];
    const float* W1  = (const float*)d_in[8];
    const float* b1  = (const float*)d_in[9];
    const float* W2  = (const float*)d_in[10];
    const float* b2  = (const float*)d_in[11];
    const float* Wxd = (const float*)d_in[12];
    const float* Whd = (const float*)d_in[13];
    const float* bd  = (const float*)d_in[14];
    const float* Wo  = (const float*)d_in[15];
    const float* bo  = (const float*)d_in[16];
    float* out = (float*)d_out;

    float *p_xe, *p_Zf, *p_Zb, *p_a, *p_aWxd, *p_Hd;
    cudaGetSymbolAddress((void**)&p_xe,   g_xe);
    cudaGetSymbolAddress((void**)&p_Zf,   g_Zf);
    cudaGetSymbolAddress((void**)&p_Zb,   g_Zb);
    cudaGetSymbolAddress((void**)&p_a,    g_a);
    cudaGetSymbolAddress((void**)&p_aWxd, g_aWxd);
    cudaGetSymbolAddress((void**)&p_Hd,   g_Hd);
    cudaFuncSetAttribute(k_softmax_v, cudaFuncAttributeMaxDynamicSharedMemorySize, VV * 4);

    k_embed<<<NTOK, 64>>>(x, emb);
    k_gemm_tf32<<<dim3(G4U / 128, NTOK / 128), 256>>>(p_xe, Wxf, bf,  p_Zf, NTOK, G4U, EE, 0);
    k_gemm_tf32<<<dim3(G4U / 128, NTOK / 128), 256>>>(p_xe, Wxb, bbv, p_Zb, NTOK, G4U, EE, 0);
    k_encoder<<<128, 256>>>(Whf, Whb);
    k_gemm_tf32<<<dim3(G4D / 128, NTOK / 128), 256>>>(p_a, Wxd, nullptr, p_aWxd, NTOK, G4D, G2U, 0);
    k_aw1<<<NTOK, 128>>>(W1, b1);
    k_decoder<<<128, 256>>>(W1, W2, b2, Whd, bd);
    k_gemm_tf32<<<dim3(VV / 128, NTOK / 128), 256>>>(p_Hd, Wo, bo, out, NTOK, VV, DD, 1);
    k_softmax_v<<<NTOK, 256, VV * 4>>>(out);
}

// round 3
// speedup vs baseline: 1.1892x; 1.1892x over previous
#include <cuda_runtime.h>
#include <cstdint>

#define BB   32
#define TT   64
#define EE   256
#define UU   512
#define DD   512
#define VV   32000
#define NTOK 2048
#define G4U  2048
#define G2U  1024

// ---------------- scratch ----------------
__device__ float g_xe  [NTOK * EE];
__device__ float g_Zf  [NTOK * G4U];     // xe@Wxf + bf
__device__ float g_Zb  [NTOK * G4U];     // xe@Wxb + bb
__device__ float g_a   [NTOK * G2U];     // encoder outputs [t*B+b][hf|hb]
__device__ float g_aW1 [NTOK * 10];      // a@W1[:1024] + b1
__device__ float g_aWxd[NTOK * G4U];     // a@Wxd
__device__ float g_Hd  [NTOK * DD];      // decoder h, time-indexed
__device__ float g_W1T [10 * 512];       // W1[1024:1536,:].T
__device__ int   g_ebar[2][TT];
__device__ int   g_efin[2];
__device__ int   g_dbar[TT];
__device__ int   g_dfin;

__device__ __forceinline__ float sigf(float x) { return 1.f / (1.f + __expf(-x)); }
__device__ __forceinline__ float tanh_fast(float x) {
    float r; asm("tanh.approx.f32 %0, %1;" : "=f"(r) : "f"(x)); return r;
}

__device__ __forceinline__ void bar_sync(int* slot, int n) {
    __threadfence();
    __syncthreads();
    if (threadIdx.x == 0) {
        atomicAdd(slot, 1);
        while (*(volatile int*)slot < n) { }
    }
    __syncthreads();
}

__device__ __forceinline__ void mma8(float* c, uint32_t a0, uint32_t a1, uint32_t a2, uint32_t a3,
                                     uint32_t b0, uint32_t b1) {
    asm volatile(
        "mma.sync.aligned.m16n8k8.row.col.f32.tf32.tf32.f32 "
        "{%0,%1,%2,%3}, {%4,%5,%6,%7}, {%8,%9}, {%0,%1,%2,%3};\n"
        : "+f"(c[0]), "+f"(c[1]), "+f"(c[2]), "+f"(c[3])
        : "r"(a0), "r"(a1), "r"(a2), "r"(a3), "r"(b0), "r"(b1));
}

// ---------------- embedding gather ----------------
__global__ void k_embed(const int* __restrict__ x, const float* __restrict__ emb) {
    int row = blockIdx.x;            // t*B + b
    int t = row >> 5, b = row & 31;
    int tok = x[b * TT + t];
    const float4* src = reinterpret_cast<const float4*>(emb + (size_t)tok * EE);
    float4* dst = reinterpret_cast<float4*>(g_xe + (size_t)row * EE);
    dst[threadIdx.x] = src[threadIdx.x];
}

// ---------------- W1 decoder-half transpose ----------------
__global__ void k_w1t(const float* __restrict__ W1) {
    int j = blockIdx.x;
    for (int k = threadIdx.x; k < 512; k += blockDim.x)
        g_W1T[j * 512 + k] = W1[(size_t)(G2U + k) * 10 + j];
}

// ---------------- pipelined tf32 GEMM: C = A[M,K]@B[K,N] (+bias), optional remap ----------------
// BM=BN=128, BK=32, 256 threads, double-buffered cp.async, conflict-free pitches.
__global__ __launch_bounds__(256) void k_gemm(
    const float* __restrict__ A, const float* __restrict__ B,
    const float* __restrict__ bias, float* __restrict__ C,
    int M, int N, int K, int remap)
{
    extern __shared__ char gsm[];
    uint32_t (*As)[128][40]  = (uint32_t(*)[128][40])gsm;
    uint32_t (*Bs)[32][136]  = (uint32_t(*)[32][136])(gsm + 2 * 128 * 40 * 4);
    int tid = threadIdx.x, lane = tid & 31, warp = tid >> 5;
    int gid = lane >> 2, tig = lane & 3;
    int wm = warp & 3, wn = warp >> 2;
    int m0 = blockIdx.y << 7, n0 = blockIdx.x << 7;
    int ntile = K >> 5;
    float acc[2][8][4] = {};

    auto issue = [&](int kt) {
        int st = kt & 1;
        int k0 = kt << 5;
#pragma unroll
        for (int i = 0; i < 4; i++) {
            int idx = tid + (i << 8);
            int r = idx >> 3, c4 = (idx & 7) << 2;
            uint32_t d = (uint32_t)__cvta_generic_to_shared(&As[st][r][c4]);
            const float* s = A + (size_t)(m0 + r) * K + k0 + c4;
            asm volatile("cp.async.cg.shared.global [%0], [%1], 16;\n" :: "r"(d), "l"(s));
        }
#pragma unroll
        for (int i = 0; i < 4; i++) {
            int idx = tid + (i << 8);
            int r = idx >> 5, c4 = (idx & 31) << 2;
            uint32_t d = (uint32_t)__cvta_generic_to_shared(&Bs[st][r][c4]);
            const float* s = B + (size_t)(k0 + r) * N + n0 + c4;
            asm volatile("cp.async.cg.shared.global [%0], [%1], 16;\n" :: "r"(d), "l"(s));
        }
        asm volatile("cp.async.commit_group;\n");
    };

    issue(0);
    for (int kt = 0; kt < ntile; kt++) {
        if (kt + 1 < ntile) { issue(kt + 1); asm volatile("cp.async.wait_group 1;\n"); }
        else                 { asm volatile("cp.async.wait_group 0;\n"); }
        __syncthreads();
        int st = kt & 1;
#pragma unroll
        for (int kk = 0; kk < 32; kk += 8) {
            uint32_t af[2][4];
#pragma unroll
            for (int mt = 0; mt < 2; mt++) {
                int rb = (wm << 5) + (mt << 4);
                af[mt][0] = As[st][rb + gid    ][kk + tig];
                af[mt][1] = As[st][rb + gid + 8][kk + tig];
                af[mt][2] = As[st][rb + gid    ][kk + tig + 4];
                af[mt][3] = As[st][rb + gid + 8][kk + tig + 4];
            }
#pragma unroll
            for (int nt = 0; nt < 8; nt++) {
                uint32_t b0 = Bs[st][kk + tig    ][(wn << 6) + (nt << 3) + gid];
                uint32_t b1 = Bs[st][kk + tig + 4][(wn << 6) + (nt << 3) + gid];
#pragma unroll
                for (int mt = 0; mt < 2; mt++)
                    mma8(acc[mt][nt], af[mt][0], af[mt][1], af[mt][2], af[mt][3], b0, b1);
            }
        }
        __syncthreads();
    }
#pragma unroll
    for (int mt = 0; mt < 2; mt++) {
#pragma unroll
        for (int nt = 0; nt < 8; nt++) {
            int col = n0 + (wn << 6) + (nt << 3) + (tig << 1);
            float b0v = bias ? bias[col]     : 0.f;
            float b1v = bias ? bias[col + 1] : 0.f;
            int r0 = m0 + (wm << 5) + (mt << 4) + gid;
            int r1 = r0 + 8;
            int or0 = remap ? ((r0 & 31) * TT + (r0 >> 5)) : r0;
            int or1 = remap ? ((r1 & 31) * TT + (r1 >> 5)) : r1;
            float2 v0 = make_float2(acc[mt][nt][0] + b0v, acc[mt][nt][1] + b1v);
            float2 v1 = make_float2(acc[mt][nt][2] + b0v, acc[mt][nt][3] + b1v);
            *reinterpret_cast<float2*>(C + (size_t)or0 * N + col) = v0;
            *reinterpret_cast<float2*>(C + (size_t)or1 * N + col) = v1;
        }
    }
}

// ---------------- persistent tensor-core encoder ----------------
// 64 blocks: dir = bid>>5, chunk = bid&31 (16 h-dims x 4 gates). Wh slice resident in smem.
#define E_WHS_B (512 * 72 * 4)
#define E_HS_B  (32 * 516 * 4)
#define E_ZS_B  (32 * 68 * 4)
#define E_SMEM  (E_WHS_B + E_HS_B + E_ZS_B)

__global__ __launch_bounds__(256) void k_encoder(const float* __restrict__ Whf,
                                                 const float* __restrict__ Whb)
{
    extern __shared__ char esm[];
    uint32_t (*WhS)[72]  = (uint32_t(*)[72])esm;
    uint32_t (*hS)[516]  = (uint32_t(*)[516])(esm + E_WHS_B);
    float    (*zS)[68]   = (float(*)[68])(esm + E_WHS_B + E_HS_B);

    int dir = blockIdx.x >> 5, chunk = blockIdx.x & 31, d0 = chunk << 4;
    const float* Wh = dir ? Whb : Whf;
    const float* Z  = dir ? g_Zb : g_Zf;
    int tid = threadIdx.x, lane = tid & 31, warp = tid >> 5;
    int gid = lane >> 2, tig = lane & 3;
    int n0 = warp << 3;
    int* bar = &g_ebar[dir][0];

    // preload Wh slice: col j = gate*16 + dd
    for (int idx = tid; idx < 512 * 64; idx += 256) {
        int k = idx >> 6, j = idx & 63;
        WhS[k][j] = __float_as_uint(Wh[(size_t)k * G4U + (j >> 4) * UU + d0 + (j & 15)]);
    }

    int cells[2] = { tid, tid + 256 };
    float cst[2] = { 0.f, 0.f };

    for (int s = 0; s < TT; s++) {
        int t = dir ? (TT - 1 - s) : s;
        if (s) {
            bar_sync(&bar[s], 32);
            int tp = dir ? (t + 1) : (t - 1);
            for (int i = tid; i < 32 * 128; i += 256) {
                int b = i >> 7, k4 = (i & 127) << 2;
                float4 v = *reinterpret_cast<const float4*>(
                    &g_a[(size_t)(tp * BB + b) * G2U + dir * UU + k4]);
                hS[b][k4 + 0] = __float_as_uint(v.x);
                hS[b][k4 + 1] = __float_as_uint(v.y);
                hS[b][k4 + 2] = __float_as_uint(v.z);
                hS[b][k4 + 3] = __float_as_uint(v.w);
            }
            __syncthreads();
            float acc[2][4] = {};
#pragma unroll 8
            for (int kk = 0; kk < 512; kk += 8) {
                uint32_t b0 = WhS[kk + tig    ][n0 + gid];
                uint32_t b1 = WhS[kk + tig + 4][n0 + gid];
#pragma unroll
                for (int mt = 0; mt < 2; mt++) {
                    uint32_t a0 = hS[mt * 16 + gid    ][kk + tig];
                    uint32_t a1 = hS[mt * 16 + gid + 8][kk + tig];
                    uint32_t a2 = hS[mt * 16 + gid    ][kk + tig + 4];
                    uint32_t a3 = hS[mt * 16 + gid + 8][kk + tig + 4];
                    mma8(acc[mt], a0, a1, a2, a3, b0, b1);
                }
            }
#pragma unroll
            for (int mt = 0; mt < 2; mt++) {
                zS[mt * 16 + gid    ][n0 + 2 * tig    ] = acc[mt][0];
                zS[mt * 16 + gid    ][n0 + 2 * tig + 1] = acc[mt][1];
                zS[mt * 16 + gid + 8][n0 + 2 * tig    ] = acc[mt][2];
                zS[mt * 16 + gid + 8][n0 + 2 * tig + 1] = acc[mt][3];
            }
            __syncthreads();
        }
#pragma unroll
        for (int ci = 0; ci < 2; ci++) {
            int cell = cells[ci];
            int b = cell >> 4, dd = cell & 15;
            size_t zrow = (size_t)(t * BB + b) * G4U + d0 + dd;
            float zi = Z[zrow], zf = Z[zrow + UU], zg = Z[zrow + 2 * UU], zo = Z[zrow + 3 * UU];
            if (s) {
                zi += zS[b][dd]; zf += zS[b][16 + dd];
                zg += zS[b][32 + dd]; zo += zS[b][48 + dd];
            }
            float ct = sigf(zf) * cst[ci] + sigf(zi) * tanhf(zg);
            float h  = sigf(zo) * tanhf(ct);
            cst[ci] = ct;
            g_a[(size_t)(t * BB + b) * G2U + dir * UU + d0 + dd] = h;
        }
    }
    __syncthreads();
    if (tid == 0) {
        __threadfence();
        if (atomicAdd(&g_efin[dir], 1) == 31) {
            for (int i = 0; i < TT; i++) bar[i] = 0;
            g_efin[dir] = 0;
        }
    }
}

// ---------------- aW1 = a @ W1[:1024] + b1 ----------------
__global__ __launch_bounds__(128) void k_aw1(const float* __restrict__ W1,
                                             const float* __restrict__ b1)
{
    __shared__ float red[128][10];
    int r = blockIdx.x;
    int tid = threadIdx.x;
    float acc[10];
#pragma unroll
    for (int j = 0; j < 10; j++) acc[j] = 0.f;
    for (int k = tid; k < G2U; k += 128) {
        float av = g_a[(size_t)r * G2U + k];
#pragma unroll
        for (int j = 0; j < 10; j++) acc[j] += av * W1[(size_t)k * 10 + j];
    }
#pragma unroll
    for (int j = 0; j < 10; j++) red[tid][j] = acc[j];
    __syncthreads();
    for (int s = 64; s > 0; s >>= 1) {
        if (tid < s)
#pragma unroll
            for (int j = 0; j < 10; j++) red[tid][j] += red[tid + s][j];
        __syncthreads();
    }
    if (tid < 10) g_aW1[(size_t)r * 10 + tid] = red[0][tid] + b1[tid];
}

// ---------------- persistent tensor-core attention decoder ----------------
// 32 blocks, block owns 16 d x 4 gates. Whd slice in smem.
#define D_WHS_B (512 * 72 * 4)
#define D_HS_B  (32 * 516 * 4)
#define D_ZS_B  (32 * 68 * 4)
#define D_SC_B  (32 * 64 * 4)
#define D_HW_B  (32 * 10 * 4)
#define D_SMEM  (D_WHS_B + D_HS_B + D_ZS_B + D_SC_B + D_HW_B)

__global__ __launch_bounds__(256) void k_decoder(
    const float* __restrict__ W2, const float* __restrict__ b2,
    const float* __restrict__ Whd, const float* __restrict__ bd)
{
    extern __shared__ char dsm[];
    uint32_t (*WhS)[72]  = (uint32_t(*)[72])dsm;
    uint32_t (*hS)[516]  = (uint32_t(*)[516])(dsm + D_WHS_B);
    float    (*zS)[68]   = (float(*)[68])(dsm + D_WHS_B + D_HS_B);
    float    (*scS)[64]  = (float(*)[64])(dsm + D_WHS_B + D_HS_B + D_ZS_B);
    float    (*hW1s)[10] = (float(*)[10])(dsm + D_WHS_B + D_HS_B + D_ZS_B + D_SC_B);

    int chunk = blockIdx.x, d0 = chunk << 4;
    int tid = threadIdx.x, lane = tid & 31, warp = tid >> 5;
    int gid = lane >> 2, tig = lane & 3;
    int n0 = warp << 3;

    // preload Whd slice
    for (int idx = tid; idx < 512 * 64; idx += 256) {
        int k = idx >> 6, j = idx & 63;
        WhS[k][j] = __float_as_uint(Whd[(size_t)k * G4U + (j >> 4) * DD + d0 + (j & 15)]);
    }
    float w2r[10];
#pragma unroll
    for (int j = 0; j < 10; j++) w2r[j] = W2[j];
    float b2s = b2[0];

    int cells[2] = { tid, tid + 256 };
    float cst[2] = { 0.f, 0.f };

    for (int t = 0; t < TT; t++) {
        if (t) {
            bar_sync(&g_dbar[t], 32);
            // stage h(t-1)
            for (int i = tid; i < 32 * 128; i += 256) {
                int b = i >> 7, k4 = (i & 127) << 2;
                float4 v = *reinterpret_cast<const float4*>(
                    &g_Hd[(size_t)((t - 1) * BB + b) * DD + k4]);
                hS[b][k4 + 0] = __float_as_uint(v.x);
                hS[b][k4 + 1] = __float_as_uint(v.y);
                hS[b][k4 + 2] = __float_as_uint(v.z);
                hS[b][k4 + 3] = __float_as_uint(v.w);
            }
            __syncthreads();
            // hW1 = h @ W1[1024:1536]
            for (int p = tid; p < 320; p += 256) {
                int b = p / 10, j = p % 10;
                const float* wt = g_W1T + j * 512;
                const uint32_t* hb = hS[b];
                float a0 = 0.f, a1 = 0.f, a2 = 0.f, a3 = 0.f;
                for (int k = 0; k < 512; k += 4) {
                    a0 += __uint_as_float(hb[k    ]) * wt[k    ];
                    a1 += __uint_as_float(hb[k + 1]) * wt[k + 1];
                    a2 += __uint_as_float(hb[k + 2]) * wt[k + 2];
                    a3 += __uint_as_float(hb[k + 3]) * wt[k + 3];
                }
                hW1s[b][j] = a0 + a1 + a2 + a3;
            }
        } else {
            for (int p = tid; p < 320; p += 256) hW1s[p / 10][p % 10] = 0.f;
        }
        __syncthreads();
        // attention energies
        for (int p = tid; p < 2048; p += 256) {
            int b = p & 31, s5 = p >> 5;
            const float* aw = g_aW1 + (size_t)(s5 * BB + b) * 10;
            float v = b2s;
#pragma unroll
            for (int j = 0; j < 10; j++) v += tanh_fast(aw[j] + hW1s[b][j]) * w2r[j];
            scS[b][s5] = fmaxf(v, 0.f);
        }
        __syncthreads();
        // softmax over s per row (8 lanes per row)
        {
            int b = tid >> 3, g8 = tid & 7;
            float vv[8];
            float m = -1e30f;
#pragma unroll
            for (int q = 0; q < 8; q++) { vv[q] = scS[b][g8 * 8 + q]; m = fmaxf(m, vv[q]); }
#pragma unroll
            for (int o = 1; o < 8; o <<= 1) m = fmaxf(m, __shfl_xor_sync(0xffffffffu, m, o));
            float sm = 0.f;
#pragma unroll
            for (int q = 0; q < 8; q++) { vv[q] = __expf(vv[q] - m); sm += vv[q]; }
#pragma unroll
            for (int o = 1; o < 8; o <<= 1) sm += __shfl_xor_sync(0xffffffffu, sm, o);
            float inv = 1.f / sm;
#pragma unroll
            for (int q = 0; q < 8; q++) scS[b][g8 * 8 + q] = vv[q] * inv;
        }
        __syncthreads();
        // ctx gates = sum_s score * aWxd (registers)
        float ctx[2][4];
#pragma unroll
        for (int ci = 0; ci < 2; ci++) {
            int cell = cells[ci];
            int b = cell >> 4, dd = cell & 15;
            const float* bp = g_aWxd + (size_t)b * G4U + d0 + dd;
            float ai = 0.f, af_ = 0.f, ag = 0.f, ao = 0.f;
#pragma unroll 4
            for (int s5 = 0; s5 < 64; s5++) {
                float sc = scS[b][s5];
                const float* r = bp + (size_t)s5 * BB * G4U;
                ai  += sc * r[0];
                af_ += sc * r[DD];
                ag  += sc * r[2 * DD];
                ao  += sc * r[3 * DD];
            }
            ctx[ci][0] = ai; ctx[ci][1] = af_; ctx[ci][2] = ag; ctx[ci][3] = ao;
        }
        // mma: h @ Whd slice
        if (t) {
            float acc[2][4] = {};
#pragma unroll 8
            for (int kk = 0; kk < 512; kk += 8) {
                uint32_t b0 = WhS[kk + tig    ][n0 + gid];
                uint32_t b1 = WhS[kk + tig + 4][n0 + gid];
#pragma unroll
                for (int mt = 0; mt < 2; mt++) {
                    uint32_t a0 = hS[mt * 16 + gid    ][kk + tig];
                    uint32_t a1 = hS[mt * 16 + gid + 8][kk + tig];
                    uint32_t a2 = hS[mt * 16 + gid    ][kk + tig + 4];
                    uint32_t a3 = hS[mt * 16 + gid + 8][kk + tig + 4];
                    mma8(acc[mt], a0, a1, a2, a3, b0, b1);
                }
            }
#pragma unroll
            for (int mt = 0; mt < 2; mt++) {
                zS[mt * 16 + gid    ][n0 + 2 * tig    ] = acc[mt][0];
                zS[mt * 16 + gid    ][n0 + 2 * tig + 1] = acc[mt][1];
                zS[mt * 16 + gid + 8][n0 + 2 * tig    ] = acc[mt][2];
                zS[mt * 16 + gid + 8][n0 + 2 * tig + 1] = acc[mt][3];
            }
        }
        __syncthreads();
        // cell update
#pragma unroll
        for (int ci = 0; ci < 2; ci++) {
            int cell = cells[ci];
            int b = cell >> 4, dd = cell & 15;
            float zi = ctx[ci][0] + bd[d0 + dd];
            float zf = ctx[ci][1] + bd[DD + d0 + dd];
            float zg = ctx[ci][2] + bd[2 * DD + d0 + dd];
            float zo = ctx[ci][3] + bd[3 * DD + d0 + dd];
            if (t) {
                zi += zS[b][dd]; zf += zS[b][16 + dd];
                zg += zS[b][32 + dd]; zo += zS[b][48 + dd];
            }
            float ct = sigf(zf) * cst[ci] + sigf(zi) * tanhf(zg);
            float h  = sigf(zo) * tanhf(ct);
            cst[ci] = ct;
            g_Hd[(size_t)(t * BB + b) * DD + d0 + dd] = h;
        }
    }
    __syncthreads();
    if (tid == 0) {
        __threadfence();
        if (atomicAdd(&g_dfin, 1) == 31) {
            for (int i = 0; i < TT; i++) g_dbar[i] = 0;
            g_dfin = 0;
        }
    }
}

// ---------------- row softmax over V ----------------
__global__ void k_softmax_v(float* __restrict__ out) {
    extern __shared__ float row[];
    __shared__ float red[512];
    int r = blockIdx.x;
    float* p = out + (size_t)r * VV;
    int tid = threadIdx.x;
    float mx = -3.4e38f;
    for (int i = tid; i < VV; i += 512) { float v = p[i]; row[i] = v; mx = fmaxf(mx, v); }
    red[tid] = mx; __syncthreads();
    for (int s = 256; s > 0; s >>= 1) {
        if (tid < s) red[tid] = fmaxf(red[tid], red[tid + s]);
        __syncthreads();
    }
    mx = red[0]; __syncthreads();
    float sum = 0.f;
    for (int i = tid; i < VV; i += 512) { float e = __expf(row[i] - mx); row[i] = e; sum += e; }
    red[tid] = sum; __syncthreads();
    for (int s = 256; s > 0; s >>= 1) {
        if (tid < s) red[tid] += red[tid + s];
        __syncthreads();
    }
    float inv = 1.f / red[0];
    for (int i = tid; i < VV; i += 512) p[i] = row[i] * inv;
}

// ---------------- host driver ----------------
extern "C" void kernel_launch(void* const* d_in, const int* in_sizes, int n_in,
                              void* d_out, int out_size)
{
    (void)in_sizes; (void)n_in; (void)out_size;
    const int*   x   = (const int*)  d_in[0];
    const float* emb = (const float*)d_in[1];
    const float* Wxf = (const float*)d_in[2];
    const float* Whf = (const float*)d_in[3];
    const float* bf  = (const float*)d_in[4];
    const float* Wxb = (const float*)d_in[5];
    const float* Whb = (const float*)d_in[6];
    const float* bbv = (const float*)d_in[7];
    const float* W1  = (const float*)d_in[8];
    const float* b1  = (const float*)d_in[9];
    const float* W2  = (const float*)d_in[10];
    const float* b2  = (const float*)d_in[11];
    const float* Wxd = (const float*)d_in[12];
    const float* Whd = (const float*)d_in[13];
    const float* bd  = (const float*)d_in[14];
    const float* Wo  = (const float*)d_in[15];
    const float* bo  = (const float*)d_in[16];
    float* out = (float*)d_out;

    float *p_xe, *p_Zf, *p_Zb, *p_a, *p_aWxd, *p_Hd;
    cudaGetSymbolAddress((void**)&p_xe,   g_xe);
    cudaGetSymbolAddress((void**)&p_Zf,   g_Zf);
    cudaGetSymbolAddress((void**)&p_Zb,   g_Zb);
    cudaGetSymbolAddress((void**)&p_a,    g_a);
    cudaGetSymbolAddress((void**)&p_aWxd, g_aWxd);
    cudaGetSymbolAddress((void**)&p_Hd,   g_Hd);

    cudaFuncSetAttribute(k_gemm,      cudaFuncAttributeMaxDynamicSharedMemorySize, 75776);
    cudaFuncSetAttribute(k_encoder,   cudaFuncAttributeMaxDynamicSharedMemorySize, E_SMEM);
    cudaFuncSetAttribute(k_decoder,   cudaFuncAttributeMaxDynamicSharedMemorySize, D_SMEM);
    cudaFuncSetAttribute(k_softmax_v, cudaFuncAttributeMaxDynamicSharedMemorySize, VV * 4);

    k_embed<<<NTOK, 64>>>(x, emb);
    k_gemm<<<dim3(G4U / 128, NTOK / 128), 256, 75776>>>(p_xe, Wxf, bf,  p_Zf, NTOK, G4U, EE, 0);
    k_gemm<<<dim3(G4U / 128, NTOK / 128), 256, 75776>>>(p_xe, Wxb, bbv, p_Zb, NTOK, G4U, EE, 0);
    k_encoder<<<64, 256, E_SMEM>>>(Whf, Whb);
    k_gemm<<<dim3(G4U / 128, NTOK / 128), 256, 75776>>>(p_a, Wxd, nullptr, p_aWxd, NTOK, G4U, G2U, 0);
    k_aw1<<<NTOK, 128>>>(W1, b1);
    k_w1t<<<10, 512>>>(W1);
    k_decoder<<<32, 256, D_SMEM>>>(W2, b2, Whd, bd);
    k_gemm<<<dim3(VV / 128, NTOK / 128), 256, 75776>>>(p_Hd, Wo, bo, out, NTOK, VV, DD, 1);
    k_softmax_v<<<NTOK, 512, VV * 4>>>(out);
}

// round 4
// speedup vs baseline: 2.6506x; 2.2290x over previous
#include <cuda_runtime.h>
#include <cuda_fp16.h>
#include <cstdint>

#define BB   32
#define TT   64
#define EE   256
#define UU   512
#define DD   512
#define VV   32000
#define NTOK 2048
#define G4U  2048
#define G2U  1024

// ---------------- scratch ----------------
__device__ float  g_xe  [NTOK * EE];
__device__ float  g_Zf  [NTOK * G4U];
__device__ float  g_Zb  [NTOK * G4U];
__device__ float  g_a   [NTOK * G2U];
__device__ float  g_aW1 [NTOK * 12];       // padded pitch 12
__device__ float  g_aWxd[NTOK * G4U];
__device__ float  g_Hd  [NTOK * DD];
__device__ __half g_HdH [NTOK * DD];       // half copy for logits A
__device__ __half g_WoH [VV * DD];         // Wo transposed [N][K] half
__device__ float  g_W1T [10 * 512];
__device__ int    g_ebar[2][TT];
__device__ int    g_efin[2];
__device__ int    g_dbar[TT];
__device__ int    g_dfin;

__device__ __forceinline__ float sigf(float x) { return 1.f / (1.f + __expf(-x)); }
__device__ __forceinline__ float tanh_fast(float x) {
    float r; asm("tanh.approx.f32 %0, %1;" : "=f"(r) : "f"(x)); return r;
}

__device__ __forceinline__ void bar_sync(int* slot, int n) {
    __syncthreads();
    if (threadIdx.x == 0) {
        asm volatile("red.release.gpu.global.add.s32 [%0], 1;" :: "l"(slot) : "memory");
        int v;
        do {
            asm volatile("ld.acquire.gpu.global.b32 %0, [%1];" : "=r"(v) : "l"(slot) : "memory");
        } while (v < n);
    }
    __syncthreads();
}

__device__ __forceinline__ void mma8(float* c, uint32_t a0, uint32_t a1, uint32_t a2, uint32_t a3,
                                     uint32_t b0, uint32_t b1) {
    asm volatile(
        "mma.sync.aligned.m16n8k8.row.col.f32.tf32.tf32.f32 "
        "{%0,%1,%2,%3}, {%4,%5,%6,%7}, {%8,%9}, {%0,%1,%2,%3};\n"
        : "+f"(c[0]), "+f"(c[1]), "+f"(c[2]), "+f"(c[3])
        : "r"(a0), "r"(a1), "r"(a2), "r"(a3), "r"(b0), "r"(b1));
}

__device__ __forceinline__ void mma16h(float* c, uint32_t a0, uint32_t a1, uint32_t a2, uint32_t a3,
                                       uint32_t b0, uint32_t b1) {
    asm volatile(
        "mma.sync.aligned.m16n8k16.row.col.f32.f16.f16.f32 "
        "{%0,%1,%2,%3}, {%4,%5,%6,%7}, {%8,%9}, {%0,%1,%2,%3};\n"
        : "+f"(c[0]), "+f"(c[1]), "+f"(c[2]), "+f"(c[3])
        : "r"(a0), "r"(a1), "r"(a2), "r"(a3), "r"(b0), "r"(b1));
}

// ---------------- embedding gather ----------------
__global__ void k_embed(const int* __restrict__ x, const float* __restrict__ emb) {
    int row = blockIdx.x;
    int t = row >> 5, b = row & 31;
    int tok = x[b * TT + t];
    const float4* src = reinterpret_cast<const float4*>(emb + (size_t)tok * EE);
    float4* dst = reinterpret_cast<float4*>(g_xe + (size_t)row * EE);
    dst[threadIdx.x] = src[threadIdx.x];
}

// ---------------- Wo convert + transpose: [512][32000] f32 -> [32000][512] half ----------------
__global__ void k_cvt_wo(const float* __restrict__ Wo) {
    __shared__ float t[32][33];
    int n0 = blockIdx.x << 5, k0 = blockIdx.y << 5;
    for (int i = threadIdx.y; i < 32; i += 8)
        t[i][threadIdx.x] = Wo[(size_t)(k0 + i) * VV + n0 + threadIdx.x];
    __syncthreads();
    for (int i = threadIdx.y; i < 32; i += 8)
        g_WoH[(size_t)(n0 + i) * DD + k0 + threadIdx.x] = __float2half(t[threadIdx.x][i]);
}

// ---------------- W1 decoder-half transpose ----------------
__global__ void k_w1t(const float* __restrict__ W1) {
    int j = blockIdx.x;
    for (int k = threadIdx.x; k < 512; k += blockDim.x)
        g_W1T[j * 512 + k] = W1[(size_t)(G2U + k) * 10 + j];
}

// ---------------- tf32 GEMM (double-buffered) ----------------
__global__ __launch_bounds__(256) void k_gemm(
    const float* __restrict__ A, const float* __restrict__ B,
    const float* __restrict__ bias, float* __restrict__ C,
    int M, int N, int K)
{
    extern __shared__ char gsm[];
    uint32_t (*As)[128][40] = (uint32_t(*)[128][40])gsm;
    uint32_t (*Bs)[32][136] = (uint32_t(*)[32][136])(gsm + 2 * 128 * 40 * 4);
    int tid = threadIdx.x, lane = tid & 31, warp = tid >> 5;
    int gid = lane >> 2, tig = lane & 3;
    int wm = warp & 3, wn = warp >> 2;
    int m0 = blockIdx.y << 7, n0 = blockIdx.x << 7;
    int ntile = K >> 5;
    float acc[2][8][4] = {};

    auto issue = [&](int kt) {
        int st = kt & 1;
        int k0 = kt << 5;
#pragma unroll
        for (int i = 0; i < 4; i++) {
            int idx = tid + (i << 8);
            int r = idx >> 3, c4 = (idx & 7) << 2;
            uint32_t d = (uint32_t)__cvta_generic_to_shared(&As[st][r][c4]);
            const float* s = A + (size_t)(m0 + r) * K + k0 + c4;
            asm volatile("cp.async.cg.shared.global [%0], [%1], 16;\n" :: "r"(d), "l"(s));
        }
#pragma unroll
        for (int i = 0; i < 4; i++) {
            int idx = tid + (i << 8);
            int r = idx >> 5, c4 = (idx & 31) << 2;
            uint32_t d = (uint32_t)__cvta_generic_to_shared(&Bs[st][r][c4]);
            const float* s = B + (size_t)(k0 + r) * N + n0 + c4;
            asm volatile("cp.async.cg.shared.global [%0], [%1], 16;\n" :: "r"(d), "l"(s));
        }
        asm volatile("cp.async.commit_group;\n");
    };

    issue(0);
    for (int kt = 0; kt < ntile; kt++) {
        if (kt + 1 < ntile) { issue(kt + 1); asm volatile("cp.async.wait_group 1;\n"); }
        else                 { asm volatile("cp.async.wait_group 0;\n"); }
        __syncthreads();
        int st = kt & 1;
#pragma unroll
        for (int kk = 0; kk < 32; kk += 8) {
            uint32_t af[2][4];
#pragma unroll
            for (int mt = 0; mt < 2; mt++) {
                int rb = (wm << 5) + (mt << 4);
                af[mt][0] = As[st][rb + gid    ][kk + tig];
                af[mt][1] = As[st][rb + gid + 8][kk + tig];
                af[mt][2] = As[st][rb + gid    ][kk + tig + 4];
                af[mt][3] = As[st][rb + gid + 8][kk + tig + 4];
            }
#pragma unroll
            for (int nt = 0; nt < 8; nt++) {
                uint32_t b0 = Bs[st][kk + tig    ][(wn << 6) + (nt << 3) + gid];
                uint32_t b1 = Bs[st][kk + tig + 4][(wn << 6) + (nt << 3) + gid];
#pragma unroll
                for (int mt = 0; mt < 2; mt++)
                    mma8(acc[mt][nt], af[mt][0], af[mt][1], af[mt][2], af[mt][3], b0, b1);
            }
        }
        __syncthreads();
    }
#pragma unroll
    for (int mt = 0; mt < 2; mt++) {
#pragma unroll
        for (int nt = 0; nt < 8; nt++) {
            int col = n0 + (wn << 6) + (nt << 3) + (tig << 1);
            float b0v = bias ? bias[col]     : 0.f;
            float b1v = bias ? bias[col + 1] : 0.f;
            int r0 = m0 + (wm << 5) + (mt << 4) + gid;
            int r1 = r0 + 8;
            float2 v0 = make_float2(acc[mt][nt][0] + b0v, acc[mt][nt][1] + b1v);
            float2 v1 = make_float2(acc[mt][nt][2] + b0v, acc[mt][nt][3] + b1v);
            *reinterpret_cast<float2*>(C + (size_t)r0 * N + col) = v0;
            *reinterpret_cast<float2*>(C + (size_t)r1 * N + col) = v1;
        }
    }
}

// ---------------- fp16 GEMM, 3-stage pipeline, remap rows (t*B+b -> b*T+t) ----------------
#define F_SMEM (3 * 2 * 128 * 40 * 2)
__global__ __launch_bounds__(256) void k_gemm_f16(
    const __half* __restrict__ A, const __half* __restrict__ Bt,
    const float* __restrict__ bias, float* __restrict__ C,
    int M, int N, int K)
{
    extern __shared__ char fsm[];
    __half (*As)[128][40] = (__half(*)[128][40])fsm;
    __half (*Bs)[128][40] = (__half(*)[128][40])(fsm + 3 * 128 * 40 * 2);
    int tid = threadIdx.x, lane = tid & 31, warp = tid >> 5;
    int gid = lane >> 2, tig = lane & 3;
    int wm = warp & 3, wn = warp >> 2;
    int m0 = blockIdx.y << 7, n0 = blockIdx.x << 7;
    int ntile = K >> 5;
    float acc[2][8][4] = {};

    auto issue = [&](int kt) {
        int st = kt % 3;
        int k0 = kt << 5;
#pragma unroll
        for (int i = 0; i < 2; i++) {
            int idx = tid + (i << 8);
            int r = idx >> 2, c = (idx & 3) << 3;
            uint32_t d = (uint32_t)__cvta_generic_to_shared(&As[st][r][c]);
            const __half* s = A + (size_t)(m0 + r) * K + k0 + c;
            asm volatile("cp.async.cg.shared.global [%0], [%1], 16;\n" :: "r"(d), "l"(s));
        }
#pragma unroll
        for (int i = 0; i < 2; i++) {
            int idx = tid + (i << 8);
            int r = idx >> 2, c = (idx & 3) << 3;
            uint32_t d = (uint32_t)__cvta_generic_to_shared(&Bs[st][r][c]);
            const __half* s = Bt + (size_t)(n0 + r) * K + k0 + c;
            asm volatile("cp.async.cg.shared.global [%0], [%1], 16;\n" :: "r"(d), "l"(s));
        }
        asm volatile("cp.async.commit_group;\n");
    };

    issue(0); issue(1);
    for (int kt = 0; kt < ntile; kt++) {
        if (kt + 2 < ntile)      { issue(kt + 2); asm volatile("cp.async.wait_group 2;\n"); }
        else if (kt + 1 < ntile) { asm volatile("cp.async.wait_group 1;\n"); }
        else                     { asm volatile("cp.async.wait_group 0;\n"); }
        __syncthreads();
        int st = kt % 3;
#pragma unroll
        for (int ks = 0; ks < 32; ks += 16) {
            uint32_t af[2][4];
#pragma unroll
            for (int mt = 0; mt < 2; mt++) {
                int rb = (wm << 5) + (mt << 4);
                af[mt][0] = *(const uint32_t*)&As[st][rb + gid    ][ks + 2 * tig];
                af[mt][1] = *(const uint32_t*)&As[st][rb + gid + 8][ks + 2 * tig];
                af[mt][2] = *(const uint32_t*)&As[st][rb + gid    ][ks + 2 * tig + 8];
                af[mt][3] = *(const uint32_t*)&As[st][rb + gid + 8][ks + 2 * tig + 8];
            }
#pragma unroll
            for (int nt = 0; nt < 8; nt++) {
                int n = (wn << 6) + (nt << 3) + gid;
                uint32_t b0 = *(const uint32_t*)&Bs[st][n][ks + 2 * tig];
                uint32_t b1 = *(const uint32_t*)&Bs[st][n][ks + 2 * tig + 8];
#pragma unroll
                for (int mt = 0; mt < 2; mt++)
                    mma16h(acc[mt][nt], af[mt][0], af[mt][1], af[mt][2], af[mt][3], b0, b1);
            }
        }
        __syncthreads();
    }
#pragma unroll
    for (int mt = 0; mt < 2; mt++) {
#pragma unroll
        for (int nt = 0; nt < 8; nt++) {
            int col = n0 + (wn << 6) + (nt << 3) + (tig << 1);
            float b0v = bias[col], b1v = bias[col + 1];
            int r0 = m0 + (wm << 5) + (mt << 4) + gid;
            int r1 = r0 + 8;
            int or0 = (r0 & 31) * TT + (r0 >> 5);
            int or1 = (r1 & 31) * TT + (r1 >> 5);
            float2 v0 = make_float2(acc[mt][nt][0] + b0v, acc[mt][nt][1] + b1v);
            float2 v1 = make_float2(acc[mt][nt][2] + b0v, acc[mt][nt][3] + b1v);
            *reinterpret_cast<float2*>(C + (size_t)or0 * N + col) = v0;
            *reinterpret_cast<float2*>(C + (size_t)or1 * N + col) = v1;
        }
    }
}

// ---------------- persistent tensor-core encoder ----------------
#define E_WHS_B (512 * 72 * 4)
#define E_HS_B  (32 * 516 * 4)
#define E_ZS_B  (32 * 68 * 4)
#define E_SMEM  (E_WHS_B + E_HS_B + E_ZS_B)

__global__ __launch_bounds__(256) void k_encoder(const float* __restrict__ Whf,
                                                 const float* __restrict__ Whb)
{
    extern __shared__ char esm[];
    uint32_t (*WhS)[72] = (uint32_t(*)[72])esm;
    uint32_t (*hS)[516] = (uint32_t(*)[516])(esm + E_WHS_B);
    float    (*zS)[68]  = (float(*)[68])(esm + E_WHS_B + E_HS_B);

    int dir = blockIdx.x >> 5, chunk = blockIdx.x & 31, d0 = chunk << 4;
    const float* Wh = dir ? Whb : Whf;
    const float* Z  = dir ? g_Zb : g_Zf;
    int tid = threadIdx.x, lane = tid & 31, warp = tid >> 5;
    int gid = lane >> 2, tig = lane & 3;
    int n0 = warp << 3;
    int* bar = &g_ebar[dir][0];

    for (int idx = tid; idx < 512 * 64; idx += 256) {
        int k = idx >> 6, j = idx & 63;
        WhS[k][j] = __float_as_uint(Wh[(size_t)k * G4U + (j >> 4) * UU + d0 + (j & 15)]);
    }

    int cells[2] = { tid, tid + 256 };
    float cst[2] = { 0.f, 0.f };

    for (int s = 0; s < TT; s++) {
        int t = dir ? (TT - 1 - s) : s;
        // prefetch Z (independent of barrier)
        float zv[2][4];
#pragma unroll
        for (int ci = 0; ci < 2; ci++) {
            int cell = cells[ci];
            int b = cell >> 4, dd = cell & 15;
            size_t zrow = (size_t)(t * BB + b) * G4U + d0 + dd;
            zv[ci][0] = Z[zrow];
            zv[ci][1] = Z[zrow + UU];
            zv[ci][2] = Z[zrow + 2 * UU];
            zv[ci][3] = Z[zrow + 3 * UU];
        }
        if (s) {
            bar_sync(&bar[s], 32);
            int tp = dir ? (t + 1) : (t - 1);
            for (int i = tid; i < 32 * 128; i += 256) {
                int b = i >> 7, k4 = (i & 127) << 2;
                float4 v = *reinterpret_cast<const float4*>(
                    &g_a[(size_t)(tp * BB + b) * G2U + dir * UU + k4]);
                hS[b][k4 + 0] = __float_as_uint(v.x);
                hS[b][k4 + 1] = __float_as_uint(v.y);
                hS[b][k4 + 2] = __float_as_uint(v.z);
                hS[b][k4 + 3] = __float_as_uint(v.w);
            }
            __syncthreads();
            float acc[2][4] = {};
#pragma unroll 8
            for (int kk = 0; kk < 512; kk += 8) {
                uint32_t b0 = WhS[kk + tig    ][n0 + gid];
                uint32_t b1 = WhS[kk + tig + 4][n0 + gid];
#pragma unroll
                for (int mt = 0; mt < 2; mt++) {
                    uint32_t a0 = hS[mt * 16 + gid    ][kk + tig];
                    uint32_t a1 = hS[mt * 16 + gid + 8][kk + tig];
                    uint32_t a2 = hS[mt * 16 + gid    ][kk + tig + 4];
                    uint32_t a3 = hS[mt * 16 + gid + 8][kk + tig + 4];
                    mma8(acc[mt], a0, a1, a2, a3, b0, b1);
                }
            }
#pragma unroll
            for (int mt = 0; mt < 2; mt++) {
                zS[mt * 16 + gid    ][n0 + 2 * tig    ] = acc[mt][0];
                zS[mt * 16 + gid    ][n0 + 2 * tig + 1] = acc[mt][1];
                zS[mt * 16 + gid + 8][n0 + 2 * tig    ] = acc[mt][2];
                zS[mt * 16 + gid + 8][n0 + 2 * tig + 1] = acc[mt][3];
            }
            __syncthreads();
        }
#pragma unroll
        for (int ci = 0; ci < 2; ci++) {
            int cell = cells[ci];
            int b = cell >> 4, dd = cell & 15;
            float zi = zv[ci][0], zf = zv[ci][1], zg = zv[ci][2], zo = zv[ci][3];
            if (s) {
                zi += zS[b][dd]; zf += zS[b][16 + dd];
                zg += zS[b][32 + dd]; zo += zS[b][48 + dd];
            }
            float ct = sigf(zf) * cst[ci] + sigf(zi) * tanhf(zg);
            float h  = sigf(zo) * tanhf(ct);
            cst[ci] = ct;
            g_a[(size_t)(t * BB + b) * G2U + dir * UU + d0 + dd] = h;
        }
    }
    __syncthreads();
    if (tid == 0) {
        __threadfence();
        if (atomicAdd(&g_efin[dir], 1) == 31) {
            for (int i = 0; i < TT; i++) bar[i] = 0;
            g_efin[dir] = 0;
        }
    }
}

// ---------------- aW1 = a @ W1[:1024] + b1 (padded pitch 12) ----------------
__global__ __launch_bounds__(128) void k_aw1(const float* __restrict__ W1,
                                             const float* __restrict__ b1)
{
    __shared__ float red[128][10];
    int r = blockIdx.x;
    int tid = threadIdx.x;
    float acc[10];
#pragma unroll
    for (int j = 0; j < 10; j++) acc[j] = 0.f;
    for (int k = tid; k < G2U; k += 128) {
        float av = g_a[(size_t)r * G2U + k];
#pragma unroll
        for (int j = 0; j < 10; j++) acc[j] += av * W1[(size_t)k * 10 + j];
    }
#pragma unroll
    for (int j = 0; j < 10; j++) red[tid][j] = acc[j];
    __syncthreads();
    for (int s = 64; s > 0; s >>= 1) {
        if (tid < s)
#pragma unroll
            for (int j = 0; j < 10; j++) red[tid][j] += red[tid + s][j];
        __syncthreads();
    }
    if (tid < 12) g_aW1[(size_t)r * 12 + tid] = (tid < 10) ? (red[0][tid] + b1[tid]) : 0.f;
}

// ---------------- persistent attention decoder ----------------
#define D_WHS_B (512 * 72 * 4)
#define D_HS_B  (32 * 516 * 4)
#define D_ZS_B  (32 * 68 * 4)
#define D_SC_B  (32 * 64 * 4)
#define D_HW_B  (32 * 10 * 4)
#define D_SMEM  (D_WHS_B + D_HS_B + D_ZS_B + D_SC_B + D_HW_B)

__global__ __launch_bounds__(256) void k_decoder(
    const float* __restrict__ W2, const float* __restrict__ b2,
    const float* __restrict__ Whd, const float* __restrict__ bd)
{
    extern __shared__ char dsm[];
    uint32_t (*WhS)[72]  = (uint32_t(*)[72])dsm;
    uint32_t (*hS)[516]  = (uint32_t(*)[516])(dsm + D_WHS_B);
    float    (*zS)[68]   = (float(*)[68])(dsm + D_WHS_B + D_HS_B);
    float    (*scS)[64]  = (float(*)[64])(dsm + D_WHS_B + D_HS_B + D_ZS_B);
    float    (*hW1s)[10] = (float(*)[10])(dsm + D_WHS_B + D_HS_B + D_ZS_B + D_SC_B);

    int chunk = blockIdx.x, d0 = chunk << 4;
    int tid = threadIdx.x, lane = tid & 31, warp = tid >> 5;
    int gid = lane >> 2, tig = lane & 3;
    int n0 = warp << 3;

    for (int idx = tid; idx < 512 * 64; idx += 256) {
        int k = idx >> 6, j = idx & 63;
        WhS[k][j] = __float_as_uint(Whd[(size_t)k * G4U + (j >> 4) * DD + d0 + (j & 15)]);
    }
    float w2r[10];
#pragma unroll
    for (int j = 0; j < 10; j++) w2r[j] = W2[j];
    float b2s = b2[0];

    // unit decomposition: unit = tid>>1 (0..127): ub = unit>>2 (batch), uq = unit&3 (4-dim group)
    int unit = tid >> 1, shalf = tid & 1;
    int ub = unit >> 2, uq = unit & 3;
    float cst4[4] = { 0.f, 0.f, 0.f, 0.f };
    float bdv[4][4];
#pragma unroll
    for (int gg = 0; gg < 4; gg++)
#pragma unroll
        for (int j = 0; j < 4; j++) bdv[gg][j] = bd[gg * DD + d0 + uq * 4 + j];

    for (int t = 0; t < TT; t++) {
        if (t) {
            bar_sync(&g_dbar[t], 32);
            for (int i = tid; i < 32 * 128; i += 256) {
                int b = i >> 7, k4 = (i & 127) << 2;
                float4 v = *reinterpret_cast<const float4*>(
                    &g_Hd[(size_t)((t - 1) * BB + b) * DD + k4]);
                hS[b][k4 + 0] = __float_as_uint(v.x);
                hS[b][k4 + 1] = __float_as_uint(v.y);
                hS[b][k4 + 2] = __float_as_uint(v.z);
                hS[b][k4 + 3] = __float_as_uint(v.w);
            }
            __syncthreads();
            // hW1 = h @ W1[1024:1536] (vectorized)
            for (int p = tid; p < 320; p += 256) {
                int b = p / 10, j = p % 10;
                const float4* wt = reinterpret_cast<const float4*>(g_W1T + j * 512);
                const float4* hb = reinterpret_cast<const float4*>(hS[b]);
                float a0 = 0.f, a1 = 0.f, a2 = 0.f, a3 = 0.f;
#pragma unroll 4
                for (int k = 0; k < 128; k++) {
                    float4 w = wt[k], h = hb[k];
                    a0 += h.x * w.x; a1 += h.y * w.y; a2 += h.z * w.z; a3 += h.w * w.w;
                }
                hW1s[b][j] = a0 + a1 + a2 + a3;
            }
        } else {
            for (int p = tid; p < 320; p += 256) hW1s[p / 10][p % 10] = 0.f;
        }
        __syncthreads();
        // attention energies (vectorized aW1 loads, pitch 12)
        for (int p = tid; p < 2048; p += 256) {
            int b = p & 31, s5 = p >> 5;
            const float4* aw = reinterpret_cast<const float4*>(g_aW1 + (size_t)(s5 * BB + b) * 12);
            float4 A0 = aw[0], A1 = aw[1], A2 = aw[2];
            float awv[10] = { A0.x, A0.y, A0.z, A0.w, A1.x, A1.y, A1.z, A1.w, A2.x, A2.y };
            float v = b2s;
#pragma unroll
            for (int j = 0; j < 10; j++) v += tanh_fast(awv[j] + hW1s[b][j]) * w2r[j];
            scS[b][s5] = fmaxf(v, 0.f);
        }
        __syncthreads();
        // softmax over s per row (8 lanes per row)
        {
            int b = tid >> 3, g8 = tid & 7;
            float vv[8];
            float m = -1e30f;
#pragma unroll
            for (int q = 0; q < 8; q++) { vv[q] = scS[b][g8 * 8 + q]; m = fmaxf(m, vv[q]); }
#pragma unroll
            for (int o = 1; o < 8; o <<= 1) m = fmaxf(m, __shfl_xor_sync(0xffffffffu, m, o));
            float sm = 0.f;
#pragma unroll
            for (int q = 0; q < 8; q++) { vv[q] = __expf(vv[q] - m); sm += vv[q]; }
#pragma unroll
            for (int o = 1; o < 8; o <<= 1) sm += __shfl_xor_sync(0xffffffffu, sm, o);
            float inv = 1.f / sm;
#pragma unroll
            for (int q = 0; q < 8; q++) scS[b][g8 * 8 + q] = vv[q] * inv;
        }
        __syncthreads();
        // ctx gates: float4 per gate, pair-split over s, shfl-reduce
        float4 cg[4];
#pragma unroll
        for (int gg = 0; gg < 4; gg++) cg[gg] = make_float4(0.f, 0.f, 0.f, 0.f);
        {
            const float* bp = g_aWxd + (size_t)ub * G4U + d0 + uq * 4;
            int s0 = shalf << 5;
#pragma unroll 2
            for (int s5 = s0; s5 < s0 + 32; s5++) {
                float sc = scS[ub][s5];
                const float* r = bp + (size_t)(s5 * BB) * G4U;
#pragma unroll
                for (int gg = 0; gg < 4; gg++) {
                    float4 v = *reinterpret_cast<const float4*>(r + gg * DD);
                    cg[gg].x += sc * v.x; cg[gg].y += sc * v.y;
                    cg[gg].z += sc * v.z; cg[gg].w += sc * v.w;
                }
            }
        }
#pragma unroll
        for (int gg = 0; gg < 4; gg++) {
            cg[gg].x += __shfl_down_sync(0xffffffffu, cg[gg].x, 1);
            cg[gg].y += __shfl_down_sync(0xffffffffu, cg[gg].y, 1);
            cg[gg].z += __shfl_down_sync(0xffffffffu, cg[gg].z, 1);
            cg[gg].w += __shfl_down_sync(0xffffffffu, cg[gg].w, 1);
        }
        // mma: h @ Whd slice
        if (t) {
            float acc[2][4] = {};
#pragma unroll 8
            for (int kk = 0; kk < 512; kk += 8) {
                uint32_t b0 = WhS[kk + tig    ][n0 + gid];
                uint32_t b1 = WhS[kk + tig + 4][n0 + gid];
#pragma unroll
                for (int mt = 0; mt < 2; mt++) {
                    uint32_t a0 = hS[mt * 16 + gid    ][kk + tig];
                    uint32_t a1 = hS[mt * 16 + gid + 8][kk + tig];
                    uint32_t a2 = hS[mt * 16 + gid    ][kk + tig + 4];
                    uint32_t a3 = hS[mt * 16 + gid + 8][kk + tig + 4];
                    mma8(acc[mt], a0, a1, a2, a3, b0, b1);
                }
            }
#pragma unroll
            for (int mt = 0; mt < 2; mt++) {
                zS[mt * 16 + gid    ][n0 + 2 * tig    ] = acc[mt][0];
                zS[mt * 16 + gid    ][n0 + 2 * tig + 1] = acc[mt][1];
                zS[mt * 16 + gid + 8][n0 + 2 * tig    ] = acc[mt][2];
                zS[mt * 16 + gid + 8][n0 + 2 * tig + 1] = acc[mt][3];
            }
        }
        __syncthreads();
        // cell update (even threads, 4 dims each)
        if (shalf == 0) {
            float zg4[4][4];
            float* cgp = &cg[0].x;
#pragma unroll
            for (int gg = 0; gg < 4; gg++)
#pragma unroll
                for (int j = 0; j < 4; j++) {
                    float z = cgp[gg * 4 + j] + bdv[gg][j];
                    if (t) z += zS[ub][gg * 16 + uq * 4 + j];
                    zg4[gg][j] = z;
                }
            float hv[4];
#pragma unroll
            for (int j = 0; j < 4; j++) {
                float ct = sigf(zg4[1][j]) * cst4[j] + sigf(zg4[0][j]) * tanhf(zg4[2][j]);
                hv[j] = sigf(zg4[3][j]) * tanhf(ct);
                cst4[j] = ct;
            }
            size_t idx = (size_t)(t * BB + ub) * DD + d0 + uq * 4;
            *reinterpret_cast<float4*>(&g_Hd[idx]) = make_float4(hv[0], hv[1], hv[2], hv[3]);
            __half2* hp = reinterpret_cast<__half2*>(&g_HdH[idx]);
            hp[0] = __floats2half2_rn(hv[0], hv[1]);
            hp[1] = __floats2half2_rn(hv[2], hv[3]);
        }
    }
    __syncthreads();
    if (tid == 0) {
        __threadfence();
        if (atomicAdd(&g_dfin, 1) == 31) {
            for (int i = 0; i < TT; i++) g_dbar[i] = 0;
            g_dfin = 0;
        }
    }
}

// ---------------- row softmax over V ----------------
__global__ void k_softmax_v(float* __restrict__ out) {
    extern __shared__ float row[];
    __shared__ float red[512];
    int r = blockIdx.x;
    float* p = out + (size_t)r * VV;
    int tid = threadIdx.x;
    float mx = -3.4e38f;
    for (int i = tid; i < VV; i += 512) { float v = p[i]; row[i] = v; mx = fmaxf(mx, v); }
    red[tid] = mx; __syncthreads();
    for (int s = 256; s > 0; s >>= 1) {
        if (tid < s) red[tid] = fmaxf(red[tid], red[tid + s]);
        __syncthreads();
    }
    mx = red[0]; __syncthreads();
    float sum = 0.f;
    for (int i = tid; i < VV; i += 512) { float e = __expf(row[i] - mx); row[i] = e; sum += e; }
    red[tid] = sum; __syncthreads();
    for (int s = 256; s > 0; s >>= 1) {
        if (tid < s) red[tid] += red[tid + s];
        __syncthreads();
    }
    float inv = 1.f / red[0];
    for (int i = tid; i < VV; i += 512) p[i] = row[i] * inv;
}

// ---------------- host driver ----------------
extern "C" void kernel_launch(void* const* d_in, const int* in_sizes, int n_in,
                              void* d_out, int out_size)
{
    (void)in_sizes; (void)n_in; (void)out_size;
    const int*   x   = (const int*)  d_in[0];
    const float* emb = (const float*)d_in[1];
    const float* Wxf = (const float*)d_in[2];
    const float* Whf = (const float*)d_in[3];
    const float* bf  = (const float*)d_in[4];
    const float* Wxb = (const float*)d_in[5];
    const float* Whb = (const float*)d_in[6];
    const float* bbv = (const float*)d_in[7];
    const float* W1  = (const float*)d_in[8];
    const float* b1  = (const float*)d_in[9];
    const float* W2  = (const float*)d_in[10];
    const float* b2  = (const float*)d_in[11];
    const float* Wxd = (const float*)d_in[12];
    const float* Whd = (const float*)d_in[13];
    const float* bd  = (const float*)d_in[14];
    const float* Wo  = (const float*)d_in[15];
    const float* bo  = (const float*)d_in[16];
    float* out = (float*)d_out;

    float *p_xe, *p_Zf, *p_Zb, *p_a, *p_aWxd;
    __half *p_HdH, *p_WoH;
    cudaGetSymbolAddress((void**)&p_xe,   g_xe);
    cudaGetSymbolAddress((void**)&p_Zf,   g_Zf);
    cudaGetSymbolAddress((void**)&p_Zb,   g_Zb);
    cudaGetSymbolAddress((void**)&p_a,    g_a);
    cudaGetSymbolAddress((void**)&p_aWxd, g_aWxd);
    cudaGetSymbolAddress((void**)&p_HdH,  g_HdH);
    cudaGetSymbolAddress((void**)&p_WoH,  g_WoH);

    cudaFuncSetAttribute(k_gemm,      cudaFuncAttributeMaxDynamicSharedMemorySize, 75776);
    cudaFuncSetAttribute(k_gemm_f16,  cudaFuncAttributeMaxDynamicSharedMemorySize, F_SMEM);
    cudaFuncSetAttribute(k_encoder,   cudaFuncAttributeMaxDynamicSharedMemorySize, E_SMEM);
    cudaFuncSetAttribute(k_decoder,   cudaFuncAttributeMaxDynamicSharedMemorySize, D_SMEM);
    cudaFuncSetAttribute(k_softmax_v, cudaFuncAttributeMaxDynamicSharedMemorySize, VV * 4);

    k_embed<<<NTOK, 64>>>(x, emb);
    k_cvt_wo<<<dim3(VV / 32, DD / 32), dim3(32, 8)>>>(Wo);
    k_gemm<<<dim3(G4U / 128, NTOK / 128), 256, 75776>>>(p_xe, Wxf, bf,  p_Zf, NTOK, G4U, EE);
    k_gemm<<<dim3(G4U / 128, NTOK / 128), 256, 75776>>>(p_xe, Wxb, bbv, p_Zb, NTOK, G4U, EE);
    k_encoder<<<64, 256, E_SMEM>>>(Whf, Whb);
    k_gemm<<<dim3(G4U / 128, NTOK / 128), 256, 75776>>>(p_a, Wxd, nullptr, p_aWxd, NTOK, G4U, G2U);
    k_aw1<<<NTOK, 128>>>(W1, b1);
    k_w1t<<<10, 512>>>(W1);
    k_decoder<<<32, 256, D_SMEM>>>(W2, b2, Whd, bd);
    k_gemm_f16<<<dim3(VV / 128, NTOK / 128), 256, F_SMEM>>>(p_HdH, p_WoH, bo, out, NTOK, VV, DD);
    k_softmax_v<<<NTOK, 512, VV * 4>>>(out);
}

// round 5
// speedup vs baseline: 2.7845x; 1.0505x over previous
#include <cuda_runtime.h>
#include <cuda_fp16.h>
#include <cstdint>

#define BB   32
#define TT   64
#define EE   256
#define UU   512
#define DD   512
#define VV   32000
#define NTOK 2048
#define G4U  2048
#define G2U  1024

// ---------------- scratch ----------------
__device__ float  g_xe   [NTOK * EE];
__device__ float  g_Zf   [NTOK * G4U];
__device__ float  g_Zb   [NTOK * G4U];
__device__ float  g_a    [NTOK * G2U];     // encoder h fp32 (for GEMMs)
__device__ __half g_aH   [NTOK * G2U];     // encoder h half (for staging)
__device__ float  g_aW1  [NTOK * 12];      // padded pitch 12
__device__ __half g_aWxdH[NTOK * G4U];     // a@Wxd half, gate-interleaved cols
__device__ __half g_HdH  [NTOK * DD];      // decoder h half
__device__ __half g_WoH  [VV * DD];        // Wo transposed [N][K] half
__device__ float  g_W1T  [10 * 512];
__device__ int    g_ebar[2][TT];
__device__ int    g_efin[2];
__device__ int    g_dbar[TT];
__device__ int    g_dfin;

__device__ __forceinline__ float sigf(float x) { return 1.f / (1.f + __expf(-x)); }
__device__ __forceinline__ float tanh_fast(float x) {
    float r; asm("tanh.approx.f32 %0, %1;" : "=f"(r) : "f"(x)); return r;
}

__device__ __forceinline__ void bar_sync(int* slot, int n) {
    __syncthreads();
    if (threadIdx.x == 0) {
        asm volatile("red.release.gpu.global.add.s32 [%0], 1;" :: "l"(slot) : "memory");
        int v;
        do {
            asm volatile("ld.acquire.gpu.global.b32 %0, [%1];" : "=r"(v) : "l"(slot) : "memory");
        } while (v < n);
    }
    __syncthreads();
}

__device__ __forceinline__ void mma8(float* c, uint32_t a0, uint32_t a1, uint32_t a2, uint32_t a3,
                                     uint32_t b0, uint32_t b1) {
    asm volatile(
        "mma.sync.aligned.m16n8k8.row.col.f32.tf32.tf32.f32 "
        "{%0,%1,%2,%3}, {%4,%5,%6,%7}, {%8,%9}, {%0,%1,%2,%3};\n"
        : "+f"(c[0]), "+f"(c[1]), "+f"(c[2]), "+f"(c[3])
        : "r"(a0), "r"(a1), "r"(a2), "r"(a3), "r"(b0), "r"(b1));
}

__device__ __forceinline__ void mma16h(float* c, uint32_t a0, uint32_t a1, uint32_t a2, uint32_t a3,
                                       uint32_t b0, uint32_t b1) {
    asm volatile(
        "mma.sync.aligned.m16n8k16.row.col.f32.f16.f16.f32 "
        "{%0,%1,%2,%3}, {%4,%5,%6,%7}, {%8,%9}, {%0,%1,%2,%3};\n"
        : "+f"(c[0]), "+f"(c[1]), "+f"(c[2]), "+f"(c[3])
        : "r"(a0), "r"(a1), "r"(a2), "r"(a3), "r"(b0), "r"(b1));
}

__device__ __forceinline__ uint32_t lds32(const __half* p) { return *(const uint32_t*)p; }

// ---------------- embedding gather ----------------
__global__ void k_embed(const int* __restrict__ x, const float* __restrict__ emb) {
    int row = blockIdx.x;
    int t = row >> 5, b = row & 31;
    int tok = x[b * TT + t];
    const float4* src = reinterpret_cast<const float4*>(emb + (size_t)tok * EE);
    float4* dst = reinterpret_cast<float4*>(g_xe + (size_t)row * EE);
    dst[threadIdx.x] = src[threadIdx.x];
}

// ---------------- Wo convert + transpose ----------------
__global__ void k_cvt_wo(const float* __restrict__ Wo) {
    __shared__ float t[32][33];
    int n0 = blockIdx.x << 5, k0 = blockIdx.y << 5;
    for (int i = threadIdx.y; i < 32; i += 8)
        t[i][threadIdx.x] = Wo[(size_t)(k0 + i) * VV + n0 + threadIdx.x];
    __syncthreads();
    for (int i = threadIdx.y; i < 32; i += 8)
        g_WoH[(size_t)(n0 + i) * DD + k0 + threadIdx.x] = __float2half(t[threadIdx.x][i]);
}

// ---------------- W1 decoder-half transpose ----------------
__global__ void k_w1t(const float* __restrict__ W1) {
    int j = blockIdx.x;
    for (int k = threadIdx.x; k < 512; k += blockDim.x)
        g_W1T[j * 512 + k] = W1[(size_t)(G2U + k) * 10 + j];
}

// ---------------- tf32 GEMM (double-buffered); Ch!=null -> permuted half output ----------------
__global__ __launch_bounds__(256) void k_gemm(
    const float* __restrict__ A, const float* __restrict__ B,
    const float* __restrict__ bias, float* __restrict__ C, __half* __restrict__ Ch,
    int M, int N, int K)
{
    extern __shared__ char gsm[];
    uint32_t (*As)[128][40] = (uint32_t(*)[128][40])gsm;
    uint32_t (*Bs)[32][136] = (uint32_t(*)[32][136])(gsm + 2 * 128 * 40 * 4);
    int tid = threadIdx.x, lane = tid & 31, warp = tid >> 5;
    int gid = lane >> 2, tig = lane & 3;
    int wm = warp & 3, wn = warp >> 2;
    int m0 = blockIdx.y << 7, n0 = blockIdx.x << 7;
    int ntile = K >> 5;
    float acc[2][8][4] = {};

    auto issue = [&](int kt) {
        int st = kt & 1;
        int k0 = kt << 5;
#pragma unroll
        for (int i = 0; i < 4; i++) {
            int idx = tid + (i << 8);
            int r = idx >> 3, c4 = (idx & 7) << 2;
            uint32_t d = (uint32_t)__cvta_generic_to_shared(&As[st][r][c4]);
            const float* s = A + (size_t)(m0 + r) * K + k0 + c4;
            asm volatile("cp.async.cg.shared.global [%0], [%1], 16;\n" :: "r"(d), "l"(s));
        }
#pragma unroll
        for (int i = 0; i < 4; i++) {
            int idx = tid + (i << 8);
            int r = idx >> 5, c4 = (idx & 31) << 2;
            uint32_t d = (uint32_t)__cvta_generic_to_shared(&Bs[st][r][c4]);
            const float* s = B + (size_t)(k0 + r) * N + n0 + c4;
            asm volatile("cp.async.cg.shared.global [%0], [%1], 16;\n" :: "r"(d), "l"(s));
        }
        asm volatile("cp.async.commit_group;\n");
    };

    issue(0);
    for (int kt = 0; kt < ntile; kt++) {
        if (kt + 1 < ntile) { issue(kt + 1); asm volatile("cp.async.wait_group 1;\n"); }
        else                 { asm volatile("cp.async.wait_group 0;\n"); }
        __syncthreads();
        int st = kt & 1;
#pragma unroll
        for (int kk = 0; kk < 32; kk += 8) {
            uint32_t af[2][4];
#pragma unroll
            for (int mt = 0; mt < 2; mt++) {
                int rb = (wm << 5) + (mt << 4);
                af[mt][0] = As[st][rb + gid    ][kk + tig];
                af[mt][1] = As[st][rb + gid + 8][kk + tig];
                af[mt][2] = As[st][rb + gid    ][kk + tig + 4];
                af[mt][3] = As[st][rb + gid + 8][kk + tig + 4];
            }
#pragma unroll
            for (int nt = 0; nt < 8; nt++) {
                uint32_t b0 = Bs[st][kk + tig    ][(wn << 6) + (nt << 3) + gid];
                uint32_t b1 = Bs[st][kk + tig + 4][(wn << 6) + (nt << 3) + gid];
#pragma unroll
                for (int mt = 0; mt < 2; mt++)
                    mma8(acc[mt][nt], af[mt][0], af[mt][1], af[mt][2], af[mt][3], b0, b1);
            }
        }
        __syncthreads();
    }
#pragma unroll
    for (int mt = 0; mt < 2; mt++) {
#pragma unroll
        for (int nt = 0; nt < 8; nt++) {
            int col = n0 + (wn << 6) + (nt << 3) + (tig << 1);
            int r0 = m0 + (wm << 5) + (mt << 4) + gid;
            int r1 = r0 + 8;
            if (Ch) {
                // gate-interleaved permute: col = gate*512 + d -> (d>>4)*64 + gate*16 + (d&15)
                int d = col & 511, gate = col >> 9;
                int nc = ((d >> 4) << 6) + (gate << 4) + (d & 15);
                *reinterpret_cast<__half2*>(Ch + (size_t)r0 * N + nc) =
                    __floats2half2_rn(acc[mt][nt][0], acc[mt][nt][1]);
                *reinterpret_cast<__half2*>(Ch + (size_t)r1 * N + nc) =
                    __floats2half2_rn(acc[mt][nt][2], acc[mt][nt][3]);
            } else {
                float b0v = bias ? bias[col]     : 0.f;
                float b1v = bias ? bias[col + 1] : 0.f;
                float2 v0 = make_float2(acc[mt][nt][0] + b0v, acc[mt][nt][1] + b1v);
                float2 v1 = make_float2(acc[mt][nt][2] + b0v, acc[mt][nt][3] + b1v);
                *reinterpret_cast<float2*>(C + (size_t)r0 * N + col) = v0;
                *reinterpret_cast<float2*>(C + (size_t)r1 * N + col) = v1;
            }
        }
    }
}

// ---------------- fp16 GEMM, 3-stage pipeline, remap rows ----------------
#define F_SMEM (3 * 2 * 128 * 40 * 2)
__global__ __launch_bounds__(256) void k_gemm_f16(
    const __half* __restrict__ A, const __half* __restrict__ Bt,
    const float* __restrict__ bias, float* __restrict__ C,
    int M, int N, int K)
{
    extern __shared__ char fsm[];
    __half (*As)[128][40] = (__half(*)[128][40])fsm;
    __half (*Bs)[128][40] = (__half(*)[128][40])(fsm + 3 * 128 * 40 * 2);
    int tid = threadIdx.x, lane = tid & 31, warp = tid >> 5;
    int gid = lane >> 2, tig = lane & 3;
    int wm = warp & 3, wn = warp >> 2;
    int m0 = blockIdx.y << 7, n0 = blockIdx.x << 7;
    int ntile = K >> 5;
    float acc[2][8][4] = {};

    auto issue = [&](int kt) {
        int st = kt % 3;
        int k0 = kt << 5;
#pragma unroll
        for (int i = 0; i < 2; i++) {
            int idx = tid + (i << 8);
            int r = idx >> 2, c = (idx & 3) << 3;
            uint32_t d = (uint32_t)__cvta_generic_to_shared(&As[st][r][c]);
            const __half* s = A + (size_t)(m0 + r) * K + k0 + c;
            asm volatile("cp.async.cg.shared.global [%0], [%1], 16;\n" :: "r"(d), "l"(s));
        }
#pragma unroll
        for (int i = 0; i < 2; i++) {
            int idx = tid + (i << 8);
            int r = idx >> 2, c = (idx & 3) << 3;
            uint32_t d = (uint32_t)__cvta_generic_to_shared(&Bs[st][r][c]);
            const __half* s = Bt + (size_t)(n0 + r) * K + k0 + c;
            asm volatile("cp.async.cg.shared.global [%0], [%1], 16;\n" :: "r"(d), "l"(s));
        }
        asm volatile("cp.async.commit_group;\n");
    };

    issue(0); issue(1);
    for (int kt = 0; kt < ntile; kt++) {
        if (kt + 2 < ntile)      { issue(kt + 2); asm volatile("cp.async.wait_group 2;\n"); }
        else if (kt + 1 < ntile) { asm volatile("cp.async.wait_group 1;\n"); }
        else                     { asm volatile("cp.async.wait_group 0;\n"); }
        __syncthreads();
        int st = kt % 3;
#pragma unroll
        for (int ks = 0; ks < 32; ks += 16) {
            uint32_t af[2][4];
#pragma unroll
            for (int mt = 0; mt < 2; mt++) {
                int rb = (wm << 5) + (mt << 4);
                af[mt][0] = *(const uint32_t*)&As[st][rb + gid    ][ks + 2 * tig];
                af[mt][1] = *(const uint32_t*)&As[st][rb + gid + 8][ks + 2 * tig];
                af[mt][2] = *(const uint32_t*)&As[st][rb + gid    ][ks + 2 * tig + 8];
                af[mt][3] = *(const uint32_t*)&As[st][rb + gid + 8][ks + 2 * tig + 8];
            }
#pragma unroll
            for (int nt = 0; nt < 8; nt++) {
                int n = (wn << 6) + (nt << 3) + gid;
                uint32_t b0 = *(const uint32_t*)&Bs[st][n][ks + 2 * tig];
                uint32_t b1 = *(const uint32_t*)&Bs[st][n][ks + 2 * tig + 8];
#pragma unroll
                for (int mt = 0; mt < 2; mt++)
                    mma16h(acc[mt][nt], af[mt][0], af[mt][1], af[mt][2], af[mt][3], b0, b1);
            }
        }
        __syncthreads();
    }
#pragma unroll
    for (int mt = 0; mt < 2; mt++) {
#pragma unroll
        for (int nt = 0; nt < 8; nt++) {
            int col = n0 + (wn << 6) + (nt << 3) + (tig << 1);
            float b0v = bias[col], b1v = bias[col + 1];
            int r0 = m0 + (wm << 5) + (mt << 4) + gid;
            int r1 = r0 + 8;
            int or0 = (r0 & 31) * TT + (r0 >> 5);
            int or1 = (r1 & 31) * TT + (r1 >> 5);
            float2 v0 = make_float2(acc[mt][nt][0] + b0v, acc[mt][nt][1] + b1v);
            float2 v1 = make_float2(acc[mt][nt][2] + b0v, acc[mt][nt][3] + b1v);
            *reinterpret_cast<float2*>(C + (size_t)or0 * N + col) = v0;
            *reinterpret_cast<float2*>(C + (size_t)or1 * N + col) = v1;
        }
    }
}

// ---------------- persistent fp16 tensor-core encoder ----------------
// 64 blocks: dir = bid>>5, chunk = bid&31 (16 h-dims x 4 gates). Half Wh slice in smem.
#define E_WH_B (64 * 520 * 2)
#define E_HS_B (32 * 520 * 2)
#define E_ZS_B (32 * 68 * 4)
#define E_SMEM (E_WH_B + E_HS_B + E_ZS_B)

__global__ __launch_bounds__(256) void k_encoder(const float* __restrict__ Whf,
                                                 const float* __restrict__ Whb)
{
    extern __shared__ char esm[];
    __half (*WhS)[520] = (__half(*)[520])esm;                 // [j=gate*16+dd][k]
    __half (*hS)[520]  = (__half(*)[520])(esm + E_WH_B);      // [b][k]
    float  (*zS)[68]   = (float(*)[68])(esm + E_WH_B + E_HS_B);

    int dir = blockIdx.x >> 5, chunk = blockIdx.x & 31, d0 = chunk << 4;
    const float* Wh = dir ? Whb : Whf;
    const float* Z  = dir ? g_Zb : g_Zf;
    int tid = threadIdx.x, lane = tid & 31, warp = tid >> 5;
    int gid = lane >> 2, tig = lane & 3;
    int n0 = warp << 3;
    int* bar = &g_ebar[dir][0];

    for (int idx = tid; idx < 64 * 512; idx += 256) {
        int j = idx >> 9, k = idx & 511;
        WhS[j][k] = __float2half(Wh[(size_t)k * G4U + (j >> 4) * UU + d0 + (j & 15)]);
    }

    int cells[2] = { tid, tid + 256 };
    float cst[2] = { 0.f, 0.f };

    for (int s = 0; s < TT; s++) {
        int t = dir ? (TT - 1 - s) : s;
        float zv[2][4];
#pragma unroll
        for (int ci = 0; ci < 2; ci++) {
            int cell = cells[ci];
            int b = cell >> 4, dd = cell & 15;
            size_t zrow = (size_t)(t * BB + b) * G4U + d0 + dd;
            zv[ci][0] = Z[zrow];
            zv[ci][1] = Z[zrow + UU];
            zv[ci][2] = Z[zrow + 2 * UU];
            zv[ci][3] = Z[zrow + 3 * UU];
        }
        if (s) {
            bar_sync(&bar[s], 32);
            int tp = dir ? (t + 1) : (t - 1);
            for (int i = tid; i < 32 * 64; i += 256) {
                int b = i >> 6, k8 = (i & 63) << 3;
                uint4 v = *reinterpret_cast<const uint4*>(
                    &g_aH[(size_t)(tp * BB + b) * G2U + dir * UU + k8]);
                *reinterpret_cast<uint4*>(&hS[b][k8]) = v;
            }
            __syncthreads();
            float acc[2][4] = {};
#pragma unroll 8
            for (int ks = 0; ks < 512; ks += 16) {
                uint32_t b0 = lds32(&WhS[n0 + gid][ks + 2 * tig]);
                uint32_t b1 = lds32(&WhS[n0 + gid][ks + 2 * tig + 8]);
#pragma unroll
                for (int mt = 0; mt < 2; mt++) {
                    uint32_t a0 = lds32(&hS[mt * 16 + gid    ][ks + 2 * tig]);
                    uint32_t a1 = lds32(&hS[mt * 16 + gid + 8][ks + 2 * tig]);
                    uint32_t a2 = lds32(&hS[mt * 16 + gid    ][ks + 2 * tig + 8]);
                    uint32_t a3 = lds32(&hS[mt * 16 + gid + 8][ks + 2 * tig + 8]);
                    mma16h(acc[mt], a0, a1, a2, a3, b0, b1);
                }
            }
#pragma unroll
            for (int mt = 0; mt < 2; mt++) {
                zS[mt * 16 + gid    ][n0 + 2 * tig    ] = acc[mt][0];
                zS[mt * 16 + gid    ][n0 + 2 * tig + 1] = acc[mt][1];
                zS[mt * 16 + gid + 8][n0 + 2 * tig    ] = acc[mt][2];
                zS[mt * 16 + gid + 8][n0 + 2 * tig + 1] = acc[mt][3];
            }
            __syncthreads();
        }
#pragma unroll
        for (int ci = 0; ci < 2; ci++) {
            int cell = cells[ci];
            int b = cell >> 4, dd = cell & 15;
            float zi = zv[ci][0], zf = zv[ci][1], zg = zv[ci][2], zo = zv[ci][3];
            if (s) {
                zi += zS[b][dd]; zf += zS[b][16 + dd];
                zg += zS[b][32 + dd]; zo += zS[b][48 + dd];
            }
            float ct = sigf(zf) * cst[ci] + sigf(zi) * tanhf(zg);
            float h  = sigf(zo) * tanhf(ct);
            cst[ci] = ct;
            size_t oi = (size_t)(t * BB + b) * G2U + dir * UU + d0 + dd;
            g_a[oi]  = h;
            g_aH[oi] = __float2half(h);
        }
    }
    __syncthreads();
    if (tid == 0) {
        __threadfence();
        if (atomicAdd(&g_efin[dir], 1) == 31) {
            for (int i = 0; i < TT; i++) bar[i] = 0;
            g_efin[dir] = 0;
        }
    }
}

// ---------------- aW1 = a @ W1[:1024] + b1 ----------------
__global__ __launch_bounds__(128) void k_aw1(const float* __restrict__ W1,
                                             const float* __restrict__ b1)
{
    __shared__ float red[128][10];
    int r = blockIdx.x;
    int tid = threadIdx.x;
    float acc[10];
#pragma unroll
    for (int j = 0; j < 10; j++) acc[j] = 0.f;
    for (int k = tid; k < G2U; k += 128) {
        float av = g_a[(size_t)r * G2U + k];
#pragma unroll
        for (int j = 0; j < 10; j++) acc[j] += av * W1[(size_t)k * 10 + j];
    }
#pragma unroll
    for (int j = 0; j < 10; j++) red[tid][j] = acc[j];
    __syncthreads();
    for (int s = 64; s > 0; s >>= 1) {
        if (tid < s)
#pragma unroll
            for (int j = 0; j < 10; j++) red[tid][j] += red[tid + s][j];
        __syncthreads();
    }
    if (tid < 12) g_aW1[(size_t)r * 12 + tid] = (tid < 10) ? (red[0][tid] + b1[tid]) : 0.f;
}

// ---------------- persistent fp16 attention decoder ----------------
#define D_WH_B (64 * 520 * 2)
#define D_HS_B (32 * 520 * 2)
#define D_ZS_B (32 * 68 * 4)
#define D_SC_B (32 * 64 * 4)
#define D_HW_B (32 * 10 * 4)
#define D_CX_B (32 * 64 * 4)
#define D_SMEM (D_WH_B + D_HS_B + D_ZS_B + D_SC_B + D_HW_B + D_CX_B)

__global__ __launch_bounds__(256) void k_decoder(
    const float* __restrict__ W2, const float* __restrict__ b2,
    const float* __restrict__ Whd, const float* __restrict__ bd)
{
    extern __shared__ char dsm[];
    __half (*WhS)[520]  = (__half(*)[520])dsm;
    __half (*hS)[520]   = (__half(*)[520])(dsm + D_WH_B);
    float  (*zS)[68]    = (float(*)[68])(dsm + D_WH_B + D_HS_B);
    float  (*scS)[64]   = (float(*)[64])(dsm + D_WH_B + D_HS_B + D_ZS_B);
    float  (*hW1s)[10]  = (float(*)[10])(dsm + D_WH_B + D_HS_B + D_ZS_B + D_SC_B);
    float  (*ctxS)[64]  = (float(*)[64])(dsm + D_WH_B + D_HS_B + D_ZS_B + D_SC_B + D_HW_B);

    int chunk = blockIdx.x, d0 = chunk << 4;
    int tid = threadIdx.x, lane = tid & 31, warp = tid >> 5;
    int gid = lane >> 2, tig = lane & 3;
    int n0 = warp << 3;

    for (int idx = tid; idx < 64 * 512; idx += 256) {
        int j = idx >> 9, k = idx & 511;
        WhS[j][k] = __float2half(Whd[(size_t)k * G4U + (j >> 4) * DD + d0 + (j & 15)]);
    }
    float w2r[10];
#pragma unroll
    for (int j = 0; j < 10; j++) w2r[j] = W2[j];
    float b2s = b2[0];

    // ctx decomposition: b = tid>>3, j8 = tid&7 -> 8 contiguous permuted cols
    int cb = tid >> 3, cj = tid & 7;
    const __half* ctx_base = g_aWxdH + (size_t)cb * G4U + chunk * 64 + cj * 8;

    // cell decomposition: unit = tid (<128): ub = unit>>2, uq = unit&3 (4 dims)
    int unit = tid, ub = unit >> 2, uq = unit & 3;
    float cst4[4] = { 0.f, 0.f, 0.f, 0.f };
    float bdv[4][4];
    if (tid < 128) {
#pragma unroll
        for (int gg = 0; gg < 4; gg++)
#pragma unroll
            for (int j = 0; j < 4; j++) bdv[gg][j] = bd[gg * DD + d0 + uq * 4 + j];
    }

    for (int t = 0; t < TT; t++) {
        if (t) {
            bar_sync(&g_dbar[t], 32);
            for (int i = tid; i < 32 * 64; i += 256) {
                int b = i >> 6, k8 = (i & 63) << 3;
                uint4 v = *reinterpret_cast<const uint4*>(
                    &g_HdH[(size_t)((t - 1) * BB + b) * DD + k8]);
                *reinterpret_cast<uint4*>(&hS[b][k8]) = v;
            }
            __syncthreads();
            // hW1 = h @ W1[1024:1536]
            for (int p = tid; p < 320; p += 256) {
                int b = p / 10, j = p % 10;
                const float4* wt = reinterpret_cast<const float4*>(g_W1T + j * 512);
                const uint32_t* hb = reinterpret_cast<const uint32_t*>(&hS[b][0]);
                float a0 = 0.f, a1 = 0.f;
#pragma unroll 4
                for (int k2 = 0; k2 < 128; k2++) {
                    float4 w = wt[k2];
                    float2 h0 = __half22float2(*(const __half2*)&hb[2 * k2]);
                    float2 h1 = __half22float2(*(const __half2*)&hb[2 * k2 + 1]);
                    a0 += h0.x * w.x + h0.y * w.y;
                    a1 += h1.x * w.z + h1.y * w.w;
                }
                hW1s[b][j] = a0 + a1;
            }
        } else {
            for (int p = tid; p < 320; p += 256) hW1s[p / 10][p % 10] = 0.f;
        }
        __syncthreads();
        // attention energies
        for (int p = tid; p < 2048; p += 256) {
            int b = p & 31, s5 = p >> 5;
            const float4* aw = reinterpret_cast<const float4*>(g_aW1 + (size_t)(s5 * BB + b) * 12);
            float4 A0 = aw[0], A1 = aw[1], A2 = aw[2];
            float awv[10] = { A0.x, A0.y, A0.z, A0.w, A1.x, A1.y, A1.z, A1.w, A2.x, A2.y };
            float v = b2s;
#pragma unroll
            for (int j = 0; j < 10; j++) v += tanh_fast(awv[j] + hW1s[b][j]) * w2r[j];
            scS[b][s5] = fmaxf(v, 0.f);
        }
        __syncthreads();
        // softmax over s per row
        {
            int b = tid >> 3, g8 = tid & 7;
            float vv[8];
            float m = -1e30f;
#pragma unroll
            for (int q = 0; q < 8; q++) { vv[q] = scS[b][g8 * 8 + q]; m = fmaxf(m, vv[q]); }
#pragma unroll
            for (int o = 1; o < 8; o <<= 1) m = fmaxf(m, __shfl_xor_sync(0xffffffffu, m, o));
            float sm = 0.f;
#pragma unroll
            for (int q = 0; q < 8; q++) { vv[q] = __expf(vv[q] - m); sm += vv[q]; }
#pragma unroll
            for (int o = 1; o < 8; o <<= 1) sm += __shfl_xor_sync(0xffffffffu, sm, o);
            float inv = 1.f / sm;
#pragma unroll
            for (int q = 0; q < 8; q++) scS[b][g8 * 8 + q] = vv[q] * inv;
        }
        __syncthreads();
        // ctx: each thread accumulates 8 contiguous permuted cols over all 64 s
        float ca[8] = {};
#pragma unroll 4
        for (int s5 = 0; s5 < 64; s5++) {
            float sc = scS[cb][s5];
            uint4 v = *reinterpret_cast<const uint4*>(ctx_base + (size_t)s5 * BB * G4U);
            float2 f0 = __half22float2(*(const __half2*)&v.x);
            float2 f1 = __half22float2(*(const __half2*)&v.y);
            float2 f2 = __half22float2(*(const __half2*)&v.z);
            float2 f3 = __half22float2(*(const __half2*)&v.w);
            ca[0] += sc * f0.x; ca[1] += sc * f0.y;
            ca[2] += sc * f1.x; ca[3] += sc * f1.y;
            ca[4] += sc * f2.x; ca[5] += sc * f2.y;
            ca[6] += sc * f3.x; ca[7] += sc * f3.y;
        }
#pragma unroll
        for (int q = 0; q < 8; q++) ctxS[cb][cj * 8 + q] = ca[q];
        // mma: h @ Whd slice
        if (t) {
            float acc[2][4] = {};
#pragma unroll 8
            for (int ks = 0; ks < 512; ks += 16) {
                uint32_t b0 = lds32(&WhS[n0 + gid][ks + 2 * tig]);
                uint32_t b1 = lds32(&WhS[n0 + gid][ks + 2 * tig + 8]);
#pragma unroll
                for (int mt = 0; mt < 2; mt++) {
                    uint32_t a0 = lds32(&hS[mt * 16 + gid    ][ks + 2 * tig]);
                    uint32_t a1 = lds32(&hS[mt * 16 + gid + 8][ks + 2 * tig]);
                    uint32_t a2 = lds32(&hS[mt * 16 + gid    ][ks + 2 * tig + 8]);
                    uint32_t a3 = lds32(&hS[mt * 16 + gid + 8][ks + 2 * tig + 8]);
                    mma16h(acc[mt], a0, a1, a2, a3, b0, b1);
                }
            }
#pragma unroll
            for (int mt = 0; mt < 2; mt++) {
                zS[mt * 16 + gid    ][n0 + 2 * tig    ] = acc[mt][0];
                zS[mt * 16 + gid    ][n0 + 2 * tig + 1] = acc[mt][1];
                zS[mt * 16 + gid + 8][n0 + 2 * tig    ] = acc[mt][2];
                zS[mt * 16 + gid + 8][n0 + 2 * tig + 1] = acc[mt][3];
            }
        }
        __syncthreads();
        // cell update (threads < 128, 4 dims each)
        if (tid < 128) {
            float zg4[4][4];
#pragma unroll
            for (int gg = 0; gg < 4; gg++)
#pragma unroll
                for (int j = 0; j < 4; j++) {
                    float z = ctxS[ub][gg * 16 + uq * 4 + j] + bdv[gg][j];
                    if (t) z += zS[ub][gg * 16 + uq * 4 + j];
                    zg4[gg][j] = z;
                }
            float hv[4];
#pragma unroll
            for (int j = 0; j < 4; j++) {
                float ct = sigf(zg4[1][j]) * cst4[j] + sigf(zg4[0][j]) * tanhf(zg4[2][j]);
                hv[j] = sigf(zg4[3][j]) * tanhf(ct);
                cst4[j] = ct;
            }
            size_t idx = (size_t)(t * BB + ub) * DD + d0 + uq * 4;
            __half2* hp = reinterpret_cast<__half2*>(&g_HdH[idx]);
            hp[0] = __floats2half2_rn(hv[0], hv[1]);
            hp[1] = __floats2half2_rn(hv[2], hv[3]);
        }
    }
    __syncthreads();
    if (tid == 0) {
        __threadfence();
        if (atomicAdd(&g_dfin, 1) == 31) {
            for (int i = 0; i < TT; i++) g_dbar[i] = 0;
            g_dfin = 0;
        }
    }
}

// ---------------- row softmax over V ----------------
__global__ void k_softmax_v(float* __restrict__ out) {
    extern __shared__ float row[];
    __shared__ float red[512];
    int r = blockIdx.x;
    float* p = out + (size_t)r * VV;
    int tid = threadIdx.x;
    float mx = -3.4e38f;
    for (int i = tid; i < VV; i += 512) { float v = p[i]; row[i] = v; mx = fmaxf(mx, v); }
    red[tid] = mx; __syncthreads();
    for (int s = 256; s > 0; s >>= 1) {
        if (tid < s) red[tid] = fmaxf(red[tid], red[tid + s]);
        __syncthreads();
    }
    mx = red[0]; __syncthreads();
    float sum = 0.f;
    for (int i = tid; i < VV; i += 512) { float e = __expf(row[i] - mx); row[i] = e; sum += e; }
    red[tid] = sum; __syncthreads();
    for (int s = 256; s > 0; s >>= 1) {
        if (tid < s) red[tid] += red[tid + s];
        __syncthreads();
    }
    float inv = 1.f / red[0];
    for (int i = tid; i < VV; i += 512) p[i] = row[i] * inv;
}

// ---------------- host driver ----------------
extern "C" void kernel_launch(void* const* d_in, const int* in_sizes, int n_in,
                              void* d_out, int out_size)
{
    (void)in_sizes; (void)n_in; (void)out_size;
    const int*   x   = (const int*)  d_in[0];
    const float* emb = (const float*)d_in[1];
    const float* Wxf = (const float*)d_in[2];
    const float* Whf = (const float*)d_in[3];
    const float* bf  = (const float*)d_in[4];
    const float* Wxb = (const float*)d_in[5];
    const float* Whb = (const float*)d_in[6];
    const float* bbv = (const float*)d_in[7];
    const float* W1  = (const float*)d_in[8];
    const float* b1  = (const float*)d_in[9];
    const float* W2  = (const float*)d_in[10];
    const float* b2  = (const float*)d_in[11];
    const float* Wxd = (const float*)d_in[12];
    const float* Whd = (const float*)d_in[13];
    const float* bd  = (const float*)d_in[14];
    const float* Wo  = (const float*)d_in[15];
    const float* bo  = (const float*)d_in[16];
    float* out = (float*)d_out;

    float *p_xe, *p_Zf, *p_Zb, *p_a;
    __half *p_HdH, *p_WoH, *p_aWxdH;
    cudaGetSymbolAddress((void**)&p_xe,    g_xe);
    cudaGetSymbolAddress((void**)&p_Zf,    g_Zf);
    cudaGetSymbolAddress((void**)&p_Zb,    g_Zb);
    cudaGetSymbolAddress((void**)&p_a,     g_a);
    cudaGetSymbolAddress((void**)&p_HdH,   g_HdH);
    cudaGetSymbolAddress((void**)&p_WoH,   g_WoH);
    cudaGetSymbolAddress((void**)&p_aWxdH, g_aWxdH);

    cudaFuncSetAttribute(k_gemm,      cudaFuncAttributeMaxDynamicSharedMemorySize, 75776);
    cudaFuncSetAttribute(k_gemm_f16,  cudaFuncAttributeMaxDynamicSharedMemorySize, F_SMEM);
    cudaFuncSetAttribute(k_encoder,   cudaFuncAttributeMaxDynamicSharedMemorySize, E_SMEM);
    cudaFuncSetAttribute(k_decoder,   cudaFuncAttributeMaxDynamicSharedMemorySize, D_SMEM);
    cudaFuncSetAttribute(k_softmax_v, cudaFuncAttributeMaxDynamicSharedMemorySize, VV * 4);

    k_embed<<<NTOK, 64>>>(x, emb);
    k_cvt_wo<<<dim3(VV / 32, DD / 32), dim3(32, 8)>>>(Wo);
    k_gemm<<<dim3(G4U / 128, NTOK / 128), 256, 75776>>>(p_xe, Wxf, bf,  p_Zf, nullptr, NTOK, G4U, EE);
    k_gemm<<<dim3(G4U / 128, NTOK / 128), 256, 75776>>>(p_xe, Wxb, bbv, p_Zb, nullptr, NTOK, G4U, EE);
    k_encoder<<<64, 256, E_SMEM>>>(Whf, Whb);
    k_gemm<<<dim3(G4U / 128, NTOK / 128), 256, 75776>>>(p_a, Wxd, nullptr, nullptr, p_aWxdH, NTOK, G4U, G2U);
    k_aw1<<<NTOK, 128>>>(W1, b1);
    k_w1t<<<10, 512>>>(W1);
    k_decoder<<<32, 256, D_SMEM>>>(W2, b2, Whd, bd);
    k_gemm_f16<<<dim3(VV / 128, NTOK / 128), 256, F_SMEM>>>(p_HdH, p_WoH, bo, out, NTOK, VV, DD);
    k_softmax_v<<<NTOK, 512, VV * 4>>>(out);
}

// round 6
// speedup vs baseline: 4.9885x; 1.7915x over previous
#include <cuda_runtime.h>
#include <cuda_fp16.h>
#include <cstdint>

#define BB   32
#define TT   64
#define EE   256
#define UU   512
#define DD   512
#define VV   32000
#define NTOK 2048
#define G4U  2048
#define G2U  1024

// ---------------- scratch ----------------
__device__ float  g_xe   [NTOK * EE];
__device__ float  g_Zf   [NTOK * G4U];
__device__ float  g_Zb   [NTOK * G4U];
__device__ float  g_a    [NTOK * G2U];     // encoder h fp32 (for GEMMs)
__device__ __half g_aH   [NTOK * G2U];     // encoder h half (staging)
__device__ __half g_aW1H [NTOK * 12];      // a@W1[:1024]+b1, half, pitch 12
__device__ __half g_aWxdH[NTOK * G4U];     // a@Wxd half, 32-col block-interleaved
__device__ __half g_HdH  [NTOK * DD];      // decoder h half
__device__ __half g_WoH  [VV * DD];        // Wo transposed [N][K] half
__device__ __half g_W1TH [10 * 512];       // W1[1024:1536].T half
__device__ int    g_ebar[2][TT];
__device__ int    g_efin[2];
__device__ int    g_dbar[TT];
__device__ int    g_dfin;

__device__ __forceinline__ float sigf(float x) { return 1.f / (1.f + __expf(-x)); }
__device__ __forceinline__ float tanh_fast(float x) {
    float r; asm("tanh.approx.f32 %0, %1;" : "=f"(r) : "f"(x)); return r;
}

__device__ __forceinline__ void bar_sync(int* slot, int n) {
    __syncthreads();
    if (threadIdx.x == 0) {
        asm volatile("red.release.gpu.global.add.s32 [%0], 1;" :: "l"(slot) : "memory");
        int v;
        do {
            asm volatile("ld.acquire.gpu.global.b32 %0, [%1];" : "=r"(v) : "l"(slot) : "memory");
        } while (v < n);
    }
    __syncthreads();
}

__device__ __forceinline__ void mma8(float* c, uint32_t a0, uint32_t a1, uint32_t a2, uint32_t a3,
                                     uint32_t b0, uint32_t b1) {
    asm volatile(
        "mma.sync.aligned.m16n8k8.row.col.f32.tf32.tf32.f32 "
        "{%0,%1,%2,%3}, {%4,%5,%6,%7}, {%8,%9}, {%0,%1,%2,%3};\n"
        : "+f"(c[0]), "+f"(c[1]), "+f"(c[2]), "+f"(c[3])
        : "r"(a0), "r"(a1), "r"(a2), "r"(a3), "r"(b0), "r"(b1));
}

__device__ __forceinline__ void mma16h(float* c, uint32_t a0, uint32_t a1, uint32_t a2, uint32_t a3,
                                       uint32_t b0, uint32_t b1) {
    asm volatile(
        "mma.sync.aligned.m16n8k16.row.col.f32.f16.f16.f32 "
        "{%0,%1,%2,%3}, {%4,%5,%6,%7}, {%8,%9}, {%0,%1,%2,%3};\n"
        : "+f"(c[0]), "+f"(c[1]), "+f"(c[2]), "+f"(c[3])
        : "r"(a0), "r"(a1), "r"(a2), "r"(a3), "r"(b0), "r"(b1));
}

__device__ __forceinline__ uint32_t lds32(const __half* p) { return *(const uint32_t*)p; }

// ---------------- embedding gather ----------------
__global__ void k_embed(const int* __restrict__ x, const float* __restrict__ emb) {
    int row = blockIdx.x;
    int t = row >> 5, b = row & 31;
    int tok = x[b * TT + t];
    const float4* src = reinterpret_cast<const float4*>(emb + (size_t)tok * EE);
    float4* dst = reinterpret_cast<float4*>(g_xe + (size_t)row * EE);
    dst[threadIdx.x] = src[threadIdx.x];
}

// ---------------- Wo convert + transpose ----------------
__global__ void k_cvt_wo(const float* __restrict__ Wo) {
    __shared__ float t[32][33];
    int n0 = blockIdx.x << 5, k0 = blockIdx.y << 5;
    for (int i = threadIdx.y; i < 32; i += 8)
        t[i][threadIdx.x] = Wo[(size_t)(k0 + i) * VV + n0 + threadIdx.x];
    __syncthreads();
    for (int i = threadIdx.y; i < 32; i += 8)
        g_WoH[(size_t)(n0 + i) * DD + k0 + threadIdx.x] = __float2half(t[threadIdx.x][i]);
}

// ---------------- W1 decoder-half transpose (half) ----------------
__global__ void k_w1t(const float* __restrict__ W1) {
    int j = blockIdx.x;
    for (int k = threadIdx.x; k < 512; k += blockDim.x)
        g_W1TH[j * 512 + k] = __float2half(W1[(size_t)(G2U + k) * 10 + j]);
}

// ---------------- tf32 GEMM (double-buffered); Ch!=null -> permuted half output ----------------
__global__ __launch_bounds__(256) void k_gemm(
    const float* __restrict__ A, const float* __restrict__ B,
    const float* __restrict__ bias, float* __restrict__ C, __half* __restrict__ Ch,
    int M, int N, int K)
{
    extern __shared__ char gsm[];
    uint32_t (*As)[128][40] = (uint32_t(*)[128][40])gsm;
    uint32_t (*Bs)[32][136] = (uint32_t(*)[32][136])(gsm + 2 * 128 * 40 * 4);
    int tid = threadIdx.x, lane = tid & 31, warp = tid >> 5;
    int gid = lane >> 2, tig = lane & 3;
    int wm = warp & 3, wn = warp >> 2;
    int m0 = blockIdx.y << 7, n0 = blockIdx.x << 7;
    int ntile = K >> 5;
    float acc[2][8][4] = {};

    auto issue = [&](int kt) {
        int st = kt & 1;
        int k0 = kt << 5;
#pragma unroll
        for (int i = 0; i < 4; i++) {
            int idx = tid + (i << 8);
            int r = idx >> 3, c4 = (idx & 7) << 2;
            uint32_t d = (uint32_t)__cvta_generic_to_shared(&As[st][r][c4]);
            const float* s = A + (size_t)(m0 + r) * K + k0 + c4;
            asm volatile("cp.async.cg.shared.global [%0], [%1], 16;\n" :: "r"(d), "l"(s));
        }
#pragma unroll
        for (int i = 0; i < 4; i++) {
            int idx = tid + (i << 8);
            int r = idx >> 5, c4 = (idx & 31) << 2;
            uint32_t d = (uint32_t)__cvta_generic_to_shared(&Bs[st][r][c4]);
            const float* s = B + (size_t)(k0 + r) * N + n0 + c4;
            asm volatile("cp.async.cg.shared.global [%0], [%1], 16;\n" :: "r"(d), "l"(s));
        }
        asm volatile("cp.async.commit_group;\n");
    };

    issue(0);
    for (int kt = 0; kt < ntile; kt++) {
        if (kt + 1 < ntile) { issue(kt + 1); asm volatile("cp.async.wait_group 1;\n"); }
        else                 { asm volatile("cp.async.wait_group 0;\n"); }
        __syncthreads();
        int st = kt & 1;
#pragma unroll
        for (int kk = 0; kk < 32; kk += 8) {
            uint32_t af[2][4];
#pragma unroll
            for (int mt = 0; mt < 2; mt++) {
                int rb = (wm << 5) + (mt << 4);
                af[mt][0] = As[st][rb + gid    ][kk + tig];
                af[mt][1] = As[st][rb + gid + 8][kk + tig];
                af[mt][2] = As[st][rb + gid    ][kk + tig + 4];
                af[mt][3] = As[st][rb + gid + 8][kk + tig + 4];
            }
#pragma unroll
            for (int nt = 0; nt < 8; nt++) {
                uint32_t b0 = Bs[st][kk + tig    ][(wn << 6) + (nt << 3) + gid];
                uint32_t b1 = Bs[st][kk + tig + 4][(wn << 6) + (nt << 3) + gid];
#pragma unroll
                for (int mt = 0; mt < 2; mt++)
                    mma8(acc[mt][nt], af[mt][0], af[mt][1], af[mt][2], af[mt][3], b0, b1);
            }
        }
        __syncthreads();
    }
#pragma unroll
    for (int mt = 0; mt < 2; mt++) {
#pragma unroll
        for (int nt = 0; nt < 8; nt++) {
            int col = n0 + (wn << 6) + (nt << 3) + (tig << 1);
            int r0 = m0 + (wm << 5) + (mt << 4) + gid;
            int r1 = r0 + 8;
            if (Ch) {
                // permute: col = gate*512 + d -> (d>>3)*32 + gate*8 + (d&7)
                int d = col & 511, gate = col >> 9;
                int nc = ((d >> 3) << 5) + (gate << 3) + (d & 7);
                *reinterpret_cast<__half2*>(Ch + (size_t)r0 * N + nc) =
                    __floats2half2_rn(acc[mt][nt][0], acc[mt][nt][1]);
                *reinterpret_cast<__half2*>(Ch + (size_t)r1 * N + nc) =
                    __floats2half2_rn(acc[mt][nt][2], acc[mt][nt][3]);
            } else {
                float b0v = bias ? bias[col]     : 0.f;
                float b1v = bias ? bias[col + 1] : 0.f;
                float2 v0 = make_float2(acc[mt][nt][0] + b0v, acc[mt][nt][1] + b1v);
                float2 v1 = make_float2(acc[mt][nt][2] + b0v, acc[mt][nt][3] + b1v);
                *reinterpret_cast<float2*>(C + (size_t)r0 * N + col) = v0;
                *reinterpret_cast<float2*>(C + (size_t)r1 * N + col) = v1;
            }
        }
    }
}

// ---------------- fp16 GEMM, 3-stage pipeline, remap rows ----------------
#define F_SMEM (3 * 2 * 128 * 40 * 2)
__global__ __launch_bounds__(256) void k_gemm_f16(
    const __half* __restrict__ A, const __half* __restrict__ Bt,
    const float* __restrict__ bias, float* __restrict__ C,
    int M, int N, int K)
{
    extern __shared__ char fsm[];
    __half (*As)[128][40] = (__half(*)[128][40])fsm;
    __half (*Bs)[128][40] = (__half(*)[128][40])(fsm + 3 * 128 * 40 * 2);
    int tid = threadIdx.x, lane = tid & 31, warp = tid >> 5;
    int gid = lane >> 2, tig = lane & 3;
    int wm = warp & 3, wn = warp >> 2;
    int m0 = blockIdx.y << 7, n0 = blockIdx.x << 7;
    int ntile = K >> 5;
    float acc[2][8][4] = {};

    auto issue = [&](int kt) {
        int st = kt % 3;
        int k0 = kt << 5;
#pragma unroll
        for (int i = 0; i < 2; i++) {
            int idx = tid + (i << 8);
            int r = idx >> 2, c = (idx & 3) << 3;
            uint32_t d = (uint32_t)__cvta_generic_to_shared(&As[st][r][c]);
            const __half* s = A + (size_t)(m0 + r) * K + k0 + c;
            asm volatile("cp.async.cg.shared.global [%0], [%1], 16;\n" :: "r"(d), "l"(s));
        }
#pragma unroll
        for (int i = 0; i < 2; i++) {
            int idx = tid + (i << 8);
            int r = idx >> 2, c = (idx & 3) << 3;
            uint32_t d = (uint32_t)__cvta_generic_to_shared(&Bs[st][r][c]);
            const __half* s = Bt + (size_t)(n0 + r) * K + k0 + c;
            asm volatile("cp.async.cg.shared.global [%0], [%1], 16;\n" :: "r"(d), "l"(s));
        }
        asm volatile("cp.async.commit_group;\n");
    };

    issue(0); issue(1);
    for (int kt = 0; kt < ntile; kt++) {
        if (kt + 2 < ntile)      { issue(kt + 2); asm volatile("cp.async.wait_group 2;\n"); }
        else if (kt + 1 < ntile) { asm volatile("cp.async.wait_group 1;\n"); }
        else                     { asm volatile("cp.async.wait_group 0;\n"); }
        __syncthreads();
        int st = kt % 3;
#pragma unroll
        for (int ks = 0; ks < 32; ks += 16) {
            uint32_t af[2][4];
#pragma unroll
            for (int mt = 0; mt < 2; mt++) {
                int rb = (wm << 5) + (mt << 4);
                af[mt][0] = *(const uint32_t*)&As[st][rb + gid    ][ks + 2 * tig];
                af[mt][1] = *(const uint32_t*)&As[st][rb + gid + 8][ks + 2 * tig];
                af[mt][2] = *(const uint32_t*)&As[st][rb + gid    ][ks + 2 * tig + 8];
                af[mt][3] = *(const uint32_t*)&As[st][rb + gid + 8][ks + 2 * tig + 8];
            }
#pragma unroll
            for (int nt = 0; nt < 8; nt++) {
                int n = (wn << 6) + (nt << 3) + gid;
                uint32_t b0 = *(const uint32_t*)&Bs[st][n][ks + 2 * tig];
                uint32_t b1 = *(const uint32_t*)&Bs[st][n][ks + 2 * tig + 8];
#pragma unroll
                for (int mt = 0; mt < 2; mt++)
                    mma16h(acc[mt][nt], af[mt][0], af[mt][1], af[mt][2], af[mt][3], b0, b1);
            }
        }
        __syncthreads();
    }
#pragma unroll
    for (int mt = 0; mt < 2; mt++) {
#pragma unroll
        for (int nt = 0; nt < 8; nt++) {
            int col = n0 + (wn << 6) + (nt << 3) + (tig << 1);
            float b0v = bias[col], b1v = bias[col + 1];
            int r0 = m0 + (wm << 5) + (mt << 4) + gid;
            int r1 = r0 + 8;
            int or0 = (r0 & 31) * TT + (r0 >> 5);
            int or1 = (r1 & 31) * TT + (r1 >> 5);
            float2 v0 = make_float2(acc[mt][nt][0] + b0v, acc[mt][nt][1] + b1v);
            float2 v1 = make_float2(acc[mt][nt][2] + b0v, acc[mt][nt][3] + b1v);
            *reinterpret_cast<float2*>(C + (size_t)or0 * N + col) = v0;
            *reinterpret_cast<float2*>(C + (size_t)or1 * N + col) = v1;
        }
    }
}

// ---------------- persistent fp16 tensor-core encoder ----------------
#define E_WH_B (64 * 520 * 2)
#define E_HS_B (32 * 520 * 2)
#define E_ZS_B (32 * 68 * 4)
#define E_SMEM (E_WH_B + E_HS_B + E_ZS_B)

__global__ __launch_bounds__(256) void k_encoder(const float* __restrict__ Whf,
                                                 const float* __restrict__ Whb)
{
    extern __shared__ char esm[];
    __half (*WhS)[520] = (__half(*)[520])esm;
    __half (*hS)[520]  = (__half(*)[520])(esm + E_WH_B);
    float  (*zS)[68]   = (float(*)[68])(esm + E_WH_B + E_HS_B);

    int dir = blockIdx.x >> 5, chunk = blockIdx.x & 31, d0 = chunk << 4;
    const float* Wh = dir ? Whb : Whf;
    const float* Z  = dir ? g_Zb : g_Zf;
    int tid = threadIdx.x, lane = tid & 31, warp = tid >> 5;
    int gid = lane >> 2, tig = lane & 3;
    int n0 = warp << 3;
    int* bar = &g_ebar[dir][0];

    for (int idx = tid; idx < 64 * 512; idx += 256) {
        int j = idx >> 9, k = idx & 511;
        WhS[j][k] = __float2half(Wh[(size_t)k * G4U + (j >> 4) * UU + d0 + (j & 15)]);
    }

    int cells[2] = { tid, tid + 256 };
    float cst[2] = { 0.f, 0.f };

    for (int s = 0; s < TT; s++) {
        int t = dir ? (TT - 1 - s) : s;
        float zv[2][4];
#pragma unroll
        for (int ci = 0; ci < 2; ci++) {
            int cell = cells[ci];
            int b = cell >> 4, dd = cell & 15;
            size_t zrow = (size_t)(t * BB + b) * G4U + d0 + dd;
            zv[ci][0] = Z[zrow];
            zv[ci][1] = Z[zrow + UU];
            zv[ci][2] = Z[zrow + 2 * UU];
            zv[ci][3] = Z[zrow + 3 * UU];
        }
        if (s) {
            bar_sync(&bar[s], 32);
            int tp = dir ? (t + 1) : (t - 1);
#pragma unroll
            for (int i = tid; i < 32 * 64; i += 256) {
                int b = i >> 6, k8 = (i & 63) << 3;
                uint4 v = *reinterpret_cast<const uint4*>(
                    &g_aH[(size_t)(tp * BB + b) * G2U + dir * UU + k8]);
                *reinterpret_cast<uint4*>(&hS[b][k8]) = v;
            }
            __syncthreads();
            float acc[2][4] = {};
#pragma unroll 8
            for (int ks = 0; ks < 512; ks += 16) {
                uint32_t b0 = lds32(&WhS[n0 + gid][ks + 2 * tig]);
                uint32_t b1 = lds32(&WhS[n0 + gid][ks + 2 * tig + 8]);
#pragma unroll
                for (int mt = 0; mt < 2; mt++) {
                    uint32_t a0 = lds32(&hS[mt * 16 + gid    ][ks + 2 * tig]);
                    uint32_t a1 = lds32(&hS[mt * 16 + gid + 8][ks + 2 * tig]);
                    uint32_t a2 = lds32(&hS[mt * 16 + gid    ][ks + 2 * tig + 8]);
                    uint32_t a3 = lds32(&hS[mt * 16 + gid + 8][ks + 2 * tig + 8]);
                    mma16h(acc[mt], a0, a1, a2, a3, b0, b1);
                }
            }
#pragma unroll
            for (int mt = 0; mt < 2; mt++) {
                zS[mt * 16 + gid    ][n0 + 2 * tig    ] = acc[mt][0];
                zS[mt * 16 + gid    ][n0 + 2 * tig + 1] = acc[mt][1];
                zS[mt * 16 + gid + 8][n0 + 2 * tig    ] = acc[mt][2];
                zS[mt * 16 + gid + 8][n0 + 2 * tig + 1] = acc[mt][3];
            }
            __syncthreads();
        }
#pragma unroll
        for (int ci = 0; ci < 2; ci++) {
            int cell = cells[ci];
            int b = cell >> 4, dd = cell & 15;
            float zi = zv[ci][0], zf = zv[ci][1], zg = zv[ci][2], zo = zv[ci][3];
            if (s) {
                zi += zS[b][dd]; zf += zS[b][16 + dd];
                zg += zS[b][32 + dd]; zo += zS[b][48 + dd];
            }
            float ct = sigf(zf) * cst[ci] + sigf(zi) * tanhf(zg);
            float h  = sigf(zo) * tanhf(ct);
            cst[ci] = ct;
            size_t oi = (size_t)(t * BB + b) * G2U + dir * UU + d0 + dd;
            g_a[oi]  = h;
            g_aH[oi] = __float2half(h);
        }
    }
    __syncthreads();
    if (tid == 0) {
        __threadfence();
        if (atomicAdd(&g_efin[dir], 1) == 31) {
            for (int i = 0; i < TT; i++) bar[i] = 0;
            g_efin[dir] = 0;
        }
    }
}

// ---------------- aW1 = a @ W1[:1024] + b1 -> half, pitch 12 ----------------
__global__ __launch_bounds__(128) void k_aw1(const float* __restrict__ W1,
                                             const float* __restrict__ b1)
{
    __shared__ float red[128][10];
    int r = blockIdx.x;
    int tid = threadIdx.x;
    float acc[10];
#pragma unroll
    for (int j = 0; j < 10; j++) acc[j] = 0.f;
    for (int k = tid; k < G2U; k += 128) {
        float av = g_a[(size_t)r * G2U + k];
#pragma unroll
        for (int j = 0; j < 10; j++) acc[j] += av * W1[(size_t)k * 10 + j];
    }
#pragma unroll
    for (int j = 0; j < 10; j++) red[tid][j] = acc[j];
    __syncthreads();
    for (int s = 64; s > 0; s >>= 1) {
        if (tid < s)
#pragma unroll
            for (int j = 0; j < 10; j++) red[tid][j] += red[tid + s][j];
        __syncthreads();
    }
    if (tid < 12)
        g_aW1H[(size_t)r * 12 + tid] = __float2half((tid < 10) ? (red[0][tid] + b1[tid]) : 0.f);
}

// ---------------- persistent fp16 attention decoder: 64 blocks, 8 dims each ----------------
// smem layout offsets
#define D_WH_OFF  0
#define D_WH_B    (32 * 520 * 2)
#define D_HS_OFF  (D_WH_OFF + D_WH_B)
#define D_HS_B    (32 * 520 * 2)
#define D_AW_OFF  (D_HS_OFF + D_HS_B)
#define D_AW_B    (2048 * 12 * 2)
#define D_W1_OFF  (D_AW_OFF + D_AW_B)
#define D_W1_B    (10 * 520 * 2)
#define D_ZS_OFF  (D_W1_OFF + D_W1_B)
#define D_ZS_B    (32 * 36 * 4)
#define D_SC_OFF  (D_ZS_OFF + D_ZS_B)
#define D_SC_B    (32 * 64 * 4)
#define D_HW_OFF  (D_SC_OFF + D_SC_B)
#define D_HW_B    (32 * 10 * 4)
#define D_CX_OFF  (D_HW_OFF + D_HW_B)
#define D_CX_B    (32 * 32 * 4)
#define D_SMEM    (D_CX_OFF + D_CX_B)

__global__ __launch_bounds__(256) void k_decoder(
    const float* __restrict__ W2, const float* __restrict__ b2,
    const float* __restrict__ Whd, const float* __restrict__ bd)
{
    extern __shared__ char dsm[];
    __half (*WhS)[520]  = (__half(*)[520])(dsm + D_WH_OFF);   // [local col 0..31][k]
    __half (*hS)[520]   = (__half(*)[520])(dsm + D_HS_OFF);   // [b][k]
    __half* aW1s        = (__half*)(dsm + D_AW_OFF);          // [2048][12]
    __half* W1TS        = (__half*)(dsm + D_W1_OFF);          // [10][520]
    float  (*zS)[36]    = (float(*)[36])(dsm + D_ZS_OFF);
    float  (*scS)[64]   = (float(*)[64])(dsm + D_SC_OFF);
    float  (*hW1s)[10]  = (float(*)[10])(dsm + D_HW_OFF);
    float  (*ctxS)[32]  = (float(*)[32])(dsm + D_CX_OFF);

    int chunk = blockIdx.x, d0 = chunk << 3;   // 8 dims per block
    int tid = threadIdx.x, lane = tid & 31, warp = tid >> 5;
    int gid = lane >> 2, tig = lane & 3;
    int wm = warp >> 2, wn = warp & 3;         // M-half, 8-col group
    int mrow = wm << 4, ncol = wn << 3;

    // one-time loads: Whd slice (local col j = gate*8+dd), aW1, W1T
    for (int idx = tid; idx < 32 * 512; idx += 256) {
        int j = idx >> 9, k = idx & 511;
        WhS[j][k] = __float2half(Whd[(size_t)k * G4U + (j >> 3) * DD + d0 + (j & 7)]);
    }
    for (int i = tid; i < D_AW_B / 16; i += 256)
        reinterpret_cast<uint4*>(aW1s)[i] = reinterpret_cast<const uint4*>(g_aW1H)[i];
    for (int j = 0; j < 10; j++)
        for (int k = tid; k < 512; k += 256)
            W1TS[j * 520 + k] = g_W1TH[j * 512 + k];

    float w2r[10];
#pragma unroll
    for (int j = 0; j < 10; j++) w2r[j] = W2[j];
    float b2s = b2[0];

    // ctx decomposition: b = tid>>3; q = tid&7: j4 = q>>1 (8-col group), sh = q&1 (s-half)
    int cb = tid >> 3, cq = tid & 7, cj4 = cq >> 1, csh = cq & 1;
    const __half* ctx_base = g_aWxdH + (size_t)cb * G4U + chunk * 32 + cj4 * 8;

    // cell decomposition: 1 cell per thread: b = tid>>3, dd = tid&7
    int ub = tid >> 3, ud = tid & 7;
    float cst = 0.f;
    float bdv[4];
#pragma unroll
    for (int gg = 0; gg < 4; gg++) bdv[gg] = bd[gg * DD + d0 + ud];

    __syncthreads();

    for (int t = 0; t < TT; t++) {
        if (t) {
            bar_sync(&g_dbar[t], 64);
#pragma unroll
            for (int i = tid; i < 32 * 64; i += 256) {
                int b = i >> 6, k8 = (i & 63) << 3;
                uint4 v = *reinterpret_cast<const uint4*>(
                    &g_HdH[(size_t)((t - 1) * BB + b) * DD + k8]);
                *reinterpret_cast<uint4*>(&hS[b][k8]) = v;
            }
            __syncthreads();
            // hW1 = h @ W1[1024:1536] (all smem)
            for (int p = tid; p < 320; p += 256) {
                int b = p / 10, j = p % 10;
                const __half2* wt = reinterpret_cast<const __half2*>(&W1TS[j * 520]);
                const __half2* hb = reinterpret_cast<const __half2*>(&hS[b][0]);
                float a0 = 0.f, a1 = 0.f;
#pragma unroll 8
                for (int k2 = 0; k2 < 256; k2 += 2) {
                    float2 w0 = __half22float2(wt[k2]),     h0 = __half22float2(hb[k2]);
                    float2 w1 = __half22float2(wt[k2 + 1]), h1 = __half22float2(hb[k2 + 1]);
                    a0 += h0.x * w0.x + h0.y * w0.y;
                    a1 += h1.x * w1.x + h1.y * w1.y;
                }
                hW1s[b][j] = a0 + a1;
            }
        } else {
            for (int p = tid; p < 320; p += 256) hW1s[p / 10][p % 10] = 0.f;
        }
        __syncthreads();
        // attention energies (aW1 from smem; row index == p)
        for (int p = tid; p < 2048; p += 256) {
            int b = p & 31;
            const __half* aw = &aW1s[p * 12];
            float v = b2s;
#pragma unroll
            for (int j = 0; j < 10; j++)
                v += tanh_fast(__half2float(aw[j]) + hW1s[b][j]) * w2r[j];
            scS[b][p >> 5] = fmaxf(v, 0.f);
        }
        __syncthreads();
        // softmax over s per row (8 lanes per row)
        {
            int b = tid >> 3, g8 = tid & 7;
            float vv[8];
            float m = -1e30f;
#pragma unroll
            for (int q = 0; q < 8; q++) { vv[q] = scS[b][g8 * 8 + q]; m = fmaxf(m, vv[q]); }
#pragma unroll
            for (int o = 1; o < 8; o <<= 1) m = fmaxf(m, __shfl_xor_sync(0xffffffffu, m, o));
            float sm = 0.f;
#pragma unroll
            for (int q = 0; q < 8; q++) { vv[q] = __expf(vv[q] - m); sm += vv[q]; }
#pragma unroll
            for (int o = 1; o < 8; o <<= 1) sm += __shfl_xor_sync(0xffffffffu, sm, o);
            float inv = 1.f / sm;
#pragma unroll
            for (int q = 0; q < 8; q++) scS[b][g8 * 8 + q] = vv[q] * inv;
        }
        __syncthreads();
        // ctx: 8 cols per thread, 32 s-values (split over pairs), MLP-8
        float ca[8] = {};
        {
            int s0 = csh << 5;
#pragma unroll 8
            for (int s5 = s0; s5 < s0 + 32; s5++) {
                float sc = scS[cb][s5];
                uint4 v = *reinterpret_cast<const uint4*>(ctx_base + (size_t)s5 * BB * G4U);
                float2 f0 = __half22float2(*(const __half2*)&v.x);
                float2 f1 = __half22float2(*(const __half2*)&v.y);
                float2 f2 = __half22float2(*(const __half2*)&v.z);
                float2 f3 = __half22float2(*(const __half2*)&v.w);
                ca[0] += sc * f0.x; ca[1] += sc * f0.y;
                ca[2] += sc * f1.x; ca[3] += sc * f1.y;
                ca[4] += sc * f2.x; ca[5] += sc * f2.y;
                ca[6] += sc * f3.x; ca[7] += sc * f3.y;
            }
        }
#pragma unroll
        for (int q = 0; q < 8; q++) ca[q] += __shfl_xor_sync(0xffffffffu, ca[q], 1);
        if (csh == 0) {
#pragma unroll
            for (int q = 0; q < 8; q++) ctxS[cb][cj4 * 8 + q] = ca[q];
        }
        // mma: h @ Whd slice (32 local cols)
        if (t) {
            float acc[4] = {};
#pragma unroll 8
            for (int ks = 0; ks < 512; ks += 16) {
                uint32_t b0 = lds32(&WhS[ncol + gid][ks + 2 * tig]);
                uint32_t b1 = lds32(&WhS[ncol + gid][ks + 2 * tig + 8]);
                uint32_t a0 = lds32(&hS[mrow + gid    ][ks + 2 * tig]);
                uint32_t a1 = lds32(&hS[mrow + gid + 8][ks + 2 * tig]);
                uint32_t a2 = lds32(&hS[mrow + gid    ][ks + 2 * tig + 8]);
                uint32_t a3 = lds32(&hS[mrow + gid + 8][ks + 2 * tig + 8]);
                mma16h(acc, a0, a1, a2, a3, b0, b1);
            }
            zS[mrow + gid    ][ncol + 2 * tig    ] = acc[0];
            zS[mrow + gid    ][ncol + 2 * tig + 1] = acc[1];
            zS[mrow + gid + 8][ncol + 2 * tig    ] = acc[2];
            zS[mrow + gid + 8][ncol + 2 * tig + 1] = acc[3];
        }
        __syncthreads();
        // cell update: 1 cell per thread
        {
            float z[4];
#pragma unroll
            for (int gg = 0; gg < 4; gg++) {
                float zz = ctxS[ub][gg * 8 + ud] + bdv[gg];
                if (t) zz += zS[ub][gg * 8 + ud];
                z[gg] = zz;
            }
            float ct = sigf(z[1]) * cst + sigf(z[0]) * tanhf(z[2]);
            float h  = sigf(z[3]) * tanhf(ct);
            cst = ct;
            g_HdH[(size_t)(t * BB + ub) * DD + d0 + ud] = __float2half(h);
        }
    }
    __syncthreads();
    if (tid == 0) {
        __threadfence();
        if (atomicAdd(&g_dfin, 1) == 63) {
            for (int i = 0; i < TT; i++) g_dbar[i] = 0;
            g_dfin = 0;
        }
    }
}

// ---------------- row softmax over V ----------------
__global__ void k_softmax_v(float* __restrict__ out) {
    extern __shared__ float row[];
    __shared__ float red[512];
    int r = blockIdx.x;
    float* p = out + (size_t)r * VV;
    int tid = threadIdx.x;
    float mx = -3.4e38f;
    for (int i = tid; i < VV; i += 512) { float v = p[i]; row[i] = v; mx = fmaxf(mx, v); }
    red[tid] = mx; __syncthreads();
    for (int s = 256; s > 0; s >>= 1) {
        if (tid < s) red[tid] = fmaxf(red[tid], red[tid + s]);
        __syncthreads();
    }
    mx = red[0]; __syncthreads();
    float sum = 0.f;
    for (int i = tid; i < VV; i += 512) { float e = __expf(row[i] - mx); row[i] = e; sum += e; }
    red[tid] = sum; __syncthreads();
    for (int s = 256; s > 0; s >>= 1) {
        if (tid < s) red[tid] += red[tid + s];
        __syncthreads();
    }
    float inv = 1.f / red[0];
    for (int i = tid; i < VV; i += 512) p[i] = row[i] * inv;
}

// ---------------- host driver ----------------
extern "C" void kernel_launch(void* const* d_in, const int* in_sizes, int n_in,
                              void* d_out, int out_size)
{
    (void)in_sizes; (void)n_in; (void)out_size;
    const int*   x   = (const int*)  d_in[0];
    const float* emb = (const float*)d_in[1];
    const float* Wxf = (const float*)d_in[2];
    const float* Whf = (const float*)d_in[3];
    const float* bf  = (const float*)d_in[4];
    const float* Wxb = (const float*)d_in[5];
    const float* Whb = (const float*)d_in[6];
    const float* bbv = (const float*)d_in[7];
    const float* W1  = (const float*)d_in[8];
    const float* b1  = (const float*)d_in[9];
    const float* W2  = (const float*)d_in[10];
    const float* b2  = (const float*)d_in[11];
    const float* Wxd = (const float*)d_in[12];
    const float* Whd = (const float*)d_in[13];
    const float* bd  = (const float*)d_in[14];
    const float* Wo  = (const float*)d_in[15];
    const float* bo  = (const float*)d_in[16];
    float* out = (float*)d_out;

    float *p_xe, *p_Zf, *p_Zb, *p_a;
    __half *p_HdH, *p_WoH, *p_aWxdH;
    cudaGetSymbolAddress((void**)&p_xe,    g_xe);
    cudaGetSymbolAddress((void**)&p_Zf,    g_Zf);
    cudaGetSymbolAddress((void**)&p_Zb,    g_Zb);
    cudaGetSymbolAddress((void**)&p_a,     g_a);
    cudaGetSymbolAddress((void**)&p_HdH,   g_HdH);
    cudaGetSymbolAddress((void**)&p_WoH,   g_WoH);
    cudaGetSymbolAddress((void**)&p_aWxdH, g_aWxdH);

    cudaFuncSetAttribute(k_gemm,      cudaFuncAttributeMaxDynamicSharedMemorySize, 75776);
    cudaFuncSetAttribute(k_gemm_f16,  cudaFuncAttributeMaxDynamicSharedMemorySize, F_SMEM);
    cudaFuncSetAttribute(k_encoder,   cudaFuncAttributeMaxDynamicSharedMemorySize, E_SMEM);
    cudaFuncSetAttribute(k_decoder,   cudaFuncAttributeMaxDynamicSharedMemorySize, D_SMEM);
    cudaFuncSetAttribute(k_softmax_v, cudaFuncAttributeMaxDynamicSharedMemorySize, VV * 4);

    k_embed<<<NTOK, 64>>>(x, emb);
    k_cvt_wo<<<dim3(VV / 32, DD / 32), dim3(32, 8)>>>(Wo);
    k_gemm<<<dim3(G4U / 128, NTOK / 128), 256, 75776>>>(p_xe, Wxf, bf,  p_Zf, nullptr, NTOK, G4U, EE);
    k_gemm<<<dim3(G4U / 128, NTOK / 128), 256, 75776>>>(p_xe, Wxb, bbv, p_Zb, nullptr, NTOK, G4U, EE);
    k_encoder<<<64, 256, E_SMEM>>>(Whf, Whb);
    k_gemm<<<dim3(G4U / 128, NTOK / 128), 256, 75776>>>(p_a, Wxd, nullptr, nullptr, p_aWxdH, NTOK, G4U, G2U);
    k_aw1<<<NTOK, 128>>>(W1, b1);
    k_w1t<<<10, 512>>>(W1);
    k_decoder<<<64, 256, D_SMEM>>>(W2, b2, Whd, bd);
    k_gemm_f16<<<dim3(VV / 128, NTOK / 128), 256, F_SMEM>>>(p_HdH, p_WoH, bo, out, NTOK, VV, DD);
    k_softmax_v<<<NTOK, 512, VV * 4>>>(out);
}

// round 7
// speedup vs baseline: 5.1619x; 1.0348x over previous
#include <cuda_runtime.h>
#include <cuda_fp16.h>
#include <cstdint>

#define BB   32
#define TT   64
#define EE   256
#define UU   512
#define DD   512
#define VV   32000
#define NTOK 2048
#define G4U  2048
#define G2U  1024

// ---------------- scratch ----------------
__device__ float  g_xe   [NTOK * EE];
__device__ float  g_Zf   [NTOK * G4U];
__device__ float  g_Zb   [NTOK * G4U];
__device__ float  g_a    [NTOK * G2U];     // encoder h fp32 (for GEMMs)
__device__ __half g_aH   [NTOK * G2U];     // encoder h half (staging)
__device__ __half g_aW1H [NTOK * 12];      // a@W1[:1024]+b1, half, pitch 12
__device__ __half g_aWxdH[NTOK * G4U];     // a@Wxd half, 32-col block-interleaved
__device__ __half g_HdH  [NTOK * DD];      // decoder h half
__device__ __half g_WoH  [VV * DD];        // Wo transposed [N][K] half
__device__ __half g_W1TH [10 * 512];       // W1[1024:1536].T half
__device__ int    g_ebar[2][TT];
__device__ int    g_efin[2];
__device__ int    g_dbar[TT];
__device__ int    g_dfin;

__device__ __forceinline__ float sigf(float x) { return 1.f / (1.f + __expf(-x)); }
__device__ __forceinline__ float tanh_fast(float x) {
    float r; asm("tanh.approx.f32 %0, %1;" : "=f"(r) : "f"(x)); return r;
}

__device__ __forceinline__ void bar_sync(int* slot, int n) {
    __syncthreads();
    if (threadIdx.x == 0) {
        asm volatile("red.release.gpu.global.add.s32 [%0], 1;" :: "l"(slot) : "memory");
        int v;
        do {
            asm volatile("ld.acquire.gpu.global.b32 %0, [%1];" : "=r"(v) : "l"(slot) : "memory");
        } while (v < n);
    }
    __syncthreads();
}

__device__ __forceinline__ void mma8(float* c, uint32_t a0, uint32_t a1, uint32_t a2, uint32_t a3,
                                     uint32_t b0, uint32_t b1) {
    asm volatile(
        "mma.sync.aligned.m16n8k8.row.col.f32.tf32.tf32.f32 "
        "{%0,%1,%2,%3}, {%4,%5,%6,%7}, {%8,%9}, {%0,%1,%2,%3};\n"
        : "+f"(c[0]), "+f"(c[1]), "+f"(c[2]), "+f"(c[3])
        : "r"(a0), "r"(a1), "r"(a2), "r"(a3), "r"(b0), "r"(b1));
}

__device__ __forceinline__ void mma16h(float* c, uint32_t a0, uint32_t a1, uint32_t a2, uint32_t a3,
                                       uint32_t b0, uint32_t b1) {
    asm volatile(
        "mma.sync.aligned.m16n8k16.row.col.f32.f16.f16.f32 "
        "{%0,%1,%2,%3}, {%4,%5,%6,%7}, {%8,%9}, {%0,%1,%2,%3};\n"
        : "+f"(c[0]), "+f"(c[1]), "+f"(c[2]), "+f"(c[3])
        : "r"(a0), "r"(a1), "r"(a2), "r"(a3), "r"(b0), "r"(b1));
}

__device__ __forceinline__ uint32_t lds32(const __half* p) { return *(const uint32_t*)p; }

// ---------------- embedding gather ----------------
__global__ void k_embed(const int* __restrict__ x, const float* __restrict__ emb) {
    int row = blockIdx.x;
    int t = row >> 5, b = row & 31;
    int tok = x[b * TT + t];
    const float4* src = reinterpret_cast<const float4*>(emb + (size_t)tok * EE);
    float4* dst = reinterpret_cast<float4*>(g_xe + (size_t)row * EE);
    dst[threadIdx.x] = src[threadIdx.x];
}

// ---------------- Wo convert + transpose ----------------
__global__ void k_cvt_wo(const float* __restrict__ Wo) {
    __shared__ float t[32][33];
    int n0 = blockIdx.x << 5, k0 = blockIdx.y << 5;
    for (int i = threadIdx.y; i < 32; i += 8)
        t[i][threadIdx.x] = Wo[(size_t)(k0 + i) * VV + n0 + threadIdx.x];
    __syncthreads();
    for (int i = threadIdx.y; i < 32; i += 8)
        g_WoH[(size_t)(n0 + i) * DD + k0 + threadIdx.x] = __float2half(t[threadIdx.x][i]);
}

// ---------------- W1 decoder-half transpose ----------------
__global__ void k_w1t(const float* __restrict__ W1) {
    int j = blockIdx.x;
    for (int k = threadIdx.x; k < 512; k += blockDim.x)
        g_W1TH[j * 512 + k] = __float2half(W1[(size_t)(G2U + k) * 10 + j]);
}

// ---------------- tf32 GEMM (double-buffered); Ch!=null -> permuted half output ----------------
__global__ __launch_bounds__(256) void k_gemm(
    const float* __restrict__ A, const float* __restrict__ B,
    const float* __restrict__ bias, float* __restrict__ C, __half* __restrict__ Ch,
    int M, int N, int K)
{
    extern __shared__ char gsm[];
    uint32_t (*As)[128][40] = (uint32_t(*)[128][40])gsm;
    uint32_t (*Bs)[32][136] = (uint32_t(*)[32][136])(gsm + 2 * 128 * 40 * 4);
    int tid = threadIdx.x, lane = tid & 31, warp = tid >> 5;
    int gid = lane >> 2, tig = lane & 3;
    int wm = warp & 3, wn = warp >> 2;
    int m0 = blockIdx.y << 7, n0 = blockIdx.x << 7;
    int ntile = K >> 5;
    float acc[2][8][4] = {};

    auto issue = [&](int kt) {
        int st = kt & 1;
        int k0 = kt << 5;
#pragma unroll
        for (int i = 0; i < 4; i++) {
            int idx = tid + (i << 8);
            int r = idx >> 3, c4 = (idx & 7) << 2;
            uint32_t d = (uint32_t)__cvta_generic_to_shared(&As[st][r][c4]);
            const float* s = A + (size_t)(m0 + r) * K + k0 + c4;
            asm volatile("cp.async.cg.shared.global [%0], [%1], 16;\n" :: "r"(d), "l"(s));
        }
#pragma unroll
        for (int i = 0; i < 4; i++) {
            int idx = tid + (i << 8);
            int r = idx >> 5, c4 = (idx & 31) << 2;
            uint32_t d = (uint32_t)__cvta_generic_to_shared(&Bs[st][r][c4]);
            const float* s = B + (size_t)(k0 + r) * N + n0 + c4;
            asm volatile("cp.async.cg.shared.global [%0], [%1], 16;\n" :: "r"(d), "l"(s));
        }
        asm volatile("cp.async.commit_group;\n");
    };

    issue(0);
    for (int kt = 0; kt < ntile; kt++) {
        if (kt + 1 < ntile) { issue(kt + 1); asm volatile("cp.async.wait_group 1;\n"); }
        else                 { asm volatile("cp.async.wait_group 0;\n"); }
        __syncthreads();
        int st = kt & 1;
#pragma unroll
        for (int kk = 0; kk < 32; kk += 8) {
            uint32_t af[2][4];
#pragma unroll
            for (int mt = 0; mt < 2; mt++) {
                int rb = (wm << 5) + (mt << 4);
                af[mt][0] = As[st][rb + gid    ][kk + tig];
                af[mt][1] = As[st][rb + gid + 8][kk + tig];
                af[mt][2] = As[st][rb + gid    ][kk + tig + 4];
                af[mt][3] = As[st][rb + gid + 8][kk + tig + 4];
            }
#pragma unroll
            for (int nt = 0; nt < 8; nt++) {
                uint32_t b0 = Bs[st][kk + tig    ][(wn << 6) + (nt << 3) + gid];
                uint32_t b1 = Bs[st][kk + tig + 4][(wn << 6) + (nt << 3) + gid];
#pragma unroll
                for (int mt = 0; mt < 2; mt++)
                    mma8(acc[mt][nt], af[mt][0], af[mt][1], af[mt][2], af[mt][3], b0, b1);
            }
        }
        __syncthreads();
    }
#pragma unroll
    for (int mt = 0; mt < 2; mt++) {
#pragma unroll
        for (int nt = 0; nt < 8; nt++) {
            int col = n0 + (wn << 6) + (nt << 3) + (tig << 1);
            int r0 = m0 + (wm << 5) + (mt << 4) + gid;
            int r1 = r0 + 8;
            if (Ch) {
                // permute: col = gate*512 + d -> (d>>3)*32 + gate*8 + (d&7)
                int d = col & 511, gate = col >> 9;
                int nc = ((d >> 3) << 5) + (gate << 3) + (d & 7);
                *reinterpret_cast<__half2*>(Ch + (size_t)r0 * N + nc) =
                    __floats2half2_rn(acc[mt][nt][0], acc[mt][nt][1]);
                *reinterpret_cast<__half2*>(Ch + (size_t)r1 * N + nc) =
                    __floats2half2_rn(acc[mt][nt][2], acc[mt][nt][3]);
            } else {
                float b0v = bias ? bias[col]     : 0.f;
                float b1v = bias ? bias[col + 1] : 0.f;
                float2 v0 = make_float2(acc[mt][nt][0] + b0v, acc[mt][nt][1] + b1v);
                float2 v1 = make_float2(acc[mt][nt][2] + b0v, acc[mt][nt][3] + b1v);
                *reinterpret_cast<float2*>(C + (size_t)r0 * N + col) = v0;
                *reinterpret_cast<float2*>(C + (size_t)r1 * N + col) = v1;
            }
        }
    }
}

// ---------------- fp16 GEMM, 3-stage pipeline, remap rows ----------------
#define F_SMEM (3 * 2 * 128 * 40 * 2)
__global__ __launch_bounds__(256) void k_gemm_f16(
    const __half* __restrict__ A, const __half* __restrict__ Bt,
    const float* __restrict__ bias, float* __restrict__ C,
    int M, int N, int K)
{
    extern __shared__ char fsm[];
    __half (*As)[128][40] = (__half(*)[128][40])fsm;
    __half (*Bs)[128][40] = (__half(*)[128][40])(fsm + 3 * 128 * 40 * 2);
    int tid = threadIdx.x, lane = tid & 31, warp = tid >> 5;
    int gid = lane >> 2, tig = lane & 3;
    int wm = warp & 3, wn = warp >> 2;
    int m0 = blockIdx.y << 7, n0 = blockIdx.x << 7;
    int ntile = K >> 5;
    float acc[2][8][4] = {};

    auto issue = [&](int kt) {
        int st = kt % 3;
        int k0 = kt << 5;
#pragma unroll
        for (int i = 0; i < 2; i++) {
            int idx = tid + (i << 8);
            int r = idx >> 2, c = (idx & 3) << 3;
            uint32_t d = (uint32_t)__cvta_generic_to_shared(&As[st][r][c]);
            const __half* s = A + (size_t)(m0 + r) * K + k0 + c;
            asm volatile("cp.async.cg.shared.global [%0], [%1], 16;\n" :: "r"(d), "l"(s));
        }
#pragma unroll
        for (int i = 0; i < 2; i++) {
            int idx = tid + (i << 8);
            int r = idx >> 2, c = (idx & 3) << 3;
            uint32_t d = (uint32_t)__cvta_generic_to_shared(&Bs[st][r][c]);
            const __half* s = Bt + (size_t)(n0 + r) * K + k0 + c;
            asm volatile("cp.async.cg.shared.global [%0], [%1], 16;\n" :: "r"(d), "l"(s));
        }
        asm volatile("cp.async.commit_group;\n");
    };

    issue(0); issue(1);
    for (int kt = 0; kt < ntile; kt++) {
        if (kt + 2 < ntile)      { issue(kt + 2); asm volatile("cp.async.wait_group 2;\n"); }
        else if (kt + 1 < ntile) { asm volatile("cp.async.wait_group 1;\n"); }
        else                     { asm volatile("cp.async.wait_group 0;\n"); }
        __syncthreads();
        int st = kt % 3;
#pragma unroll
        for (int ks = 0; ks < 32; ks += 16) {
            uint32_t af[2][4];
#pragma unroll
            for (int mt = 0; mt < 2; mt++) {
                int rb = (wm << 5) + (mt << 4);
                af[mt][0] = *(const uint32_t*)&As[st][rb + gid    ][ks + 2 * tig];
                af[mt][1] = *(const uint32_t*)&As[st][rb + gid + 8][ks + 2 * tig];
                af[mt][2] = *(const uint32_t*)&As[st][rb + gid    ][ks + 2 * tig + 8];
                af[mt][3] = *(const uint32_t*)&As[st][rb + gid + 8][ks + 2 * tig + 8];
            }
#pragma unroll
            for (int nt = 0; nt < 8; nt++) {
                int n = (wn << 6) + (nt << 3) + gid;
                uint32_t b0 = *(const uint32_t*)&Bs[st][n][ks + 2 * tig];
                uint32_t b1 = *(const uint32_t*)&Bs[st][n][ks + 2 * tig + 8];
#pragma unroll
                for (int mt = 0; mt < 2; mt++)
                    mma16h(acc[mt][nt], af[mt][0], af[mt][1], af[mt][2], af[mt][3], b0, b1);
            }
        }
        __syncthreads();
    }
#pragma unroll
    for (int mt = 0; mt < 2; mt++) {
#pragma unroll
        for (int nt = 0; nt < 8; nt++) {
            int col = n0 + (wn << 6) + (nt << 3) + (tig << 1);
            float b0v = bias[col], b1v = bias[col + 1];
            int r0 = m0 + (wm << 5) + (mt << 4) + gid;
            int r1 = r0 + 8;
            int or0 = (r0 & 31) * TT + (r0 >> 5);
            int or1 = (r1 & 31) * TT + (r1 >> 5);
            float2 v0 = make_float2(acc[mt][nt][0] + b0v, acc[mt][nt][1] + b1v);
            float2 v1 = make_float2(acc[mt][nt][2] + b0v, acc[mt][nt][3] + b1v);
            *reinterpret_cast<float2*>(C + (size_t)or0 * N + col) = v0;
            *reinterpret_cast<float2*>(C + (size_t)or1 * N + col) = v1;
        }
    }
}

// ---------------- persistent fp16 encoder: 128 blocks (64/dir), 8 dims each ----------------
#define E_WH_B (32 * 520 * 2)
#define E_HS_B (32 * 520 * 2)
#define E_ZS_B (32 * 36 * 4)
#define E_SMEM (E_WH_B + E_HS_B + E_ZS_B)

__global__ __launch_bounds__(256) void k_encoder(const float* __restrict__ Whf,
                                                 const float* __restrict__ Whb)
{
    extern __shared__ char esm[];
    __half (*WhS)[520] = (__half(*)[520])esm;                  // [j=gate*8+dd][k]
    __half (*hS)[520]  = (__half(*)[520])(esm + E_WH_B);       // [b][k]
    float  (*zS)[36]   = (float(*)[36])(esm + E_WH_B + E_HS_B);

    int dir = blockIdx.x >> 6, chunk = blockIdx.x & 63, d0 = chunk << 3;
    const float* Wh = dir ? Whb : Whf;
    const float* Z  = dir ? g_Zb : g_Zf;
    int tid = threadIdx.x, lane = tid & 31, warp = tid >> 5;
    int gid = lane >> 2, tig = lane & 3;
    int mrow = (warp >> 2) << 4, ncol = (warp & 3) << 3;
    int* bar = &g_ebar[dir][0];

    for (int idx = tid; idx < 32 * 512; idx += 256) {
        int j = idx >> 9, k = idx & 511;
        WhS[j][k] = __float2half(Wh[(size_t)k * G4U + (j >> 3) * UU + d0 + (j & 7)]);
    }

    int ub = tid >> 3, ud = tid & 7;       // 1 cell per thread
    float cst = 0.f;

    for (int s = 0; s < TT; s++) {
        int t = dir ? (TT - 1 - s) : s;
        // prefetch Z (independent of barrier)
        size_t zrow = (size_t)(t * BB + ub) * G4U + d0 + ud;
        float zv0 = Z[zrow];
        float zv1 = Z[zrow + UU];
        float zv2 = Z[zrow + 2 * UU];
        float zv3 = Z[zrow + 3 * UU];
        if (s) {
            bar_sync(&bar[s], 64);
            int tp = dir ? (t + 1) : (t - 1);
#pragma unroll
            for (int i = tid; i < 32 * 64; i += 256) {
                int b = i >> 6, k8 = (i & 63) << 3;
                uint4 v = *reinterpret_cast<const uint4*>(
                    &g_aH[(size_t)(tp * BB + b) * G2U + dir * UU + k8]);
                *reinterpret_cast<uint4*>(&hS[b][k8]) = v;
            }
            __syncthreads();
            float ac0[4] = {}, ac1[4] = {};
#pragma unroll 8
            for (int ks = 0; ks < 256; ks += 16) {
                int ks2 = ks + 256;
                uint32_t b0 = lds32(&WhS[ncol + gid][ks + 2 * tig]);
                uint32_t b1 = lds32(&WhS[ncol + gid][ks + 2 * tig + 8]);
                uint32_t a0 = lds32(&hS[mrow + gid    ][ks + 2 * tig]);
                uint32_t a1 = lds32(&hS[mrow + gid + 8][ks + 2 * tig]);
                uint32_t a2 = lds32(&hS[mrow + gid    ][ks + 2 * tig + 8]);
                uint32_t a3 = lds32(&hS[mrow + gid + 8][ks + 2 * tig + 8]);
                mma16h(ac0, a0, a1, a2, a3, b0, b1);
                uint32_t c0 = lds32(&WhS[ncol + gid][ks2 + 2 * tig]);
                uint32_t c1 = lds32(&WhS[ncol + gid][ks2 + 2 * tig + 8]);
                uint32_t d0r = lds32(&hS[mrow + gid    ][ks2 + 2 * tig]);
                uint32_t d1r = lds32(&hS[mrow + gid + 8][ks2 + 2 * tig]);
                uint32_t d2r = lds32(&hS[mrow + gid    ][ks2 + 2 * tig + 8]);
                uint32_t d3r = lds32(&hS[mrow + gid + 8][ks2 + 2 * tig + 8]);
                mma16h(ac1, d0r, d1r, d2r, d3r, c0, c1);
            }
            zS[mrow + gid    ][ncol + 2 * tig    ] = ac0[0] + ac1[0];
            zS[mrow + gid    ][ncol + 2 * tig + 1] = ac0[1] + ac1[1];
            zS[mrow + gid + 8][ncol + 2 * tig    ] = ac0[2] + ac1[2];
            zS[mrow + gid + 8][ncol + 2 * tig + 1] = ac0[3] + ac1[3];
            __syncthreads();
        }
        {
            float zi = zv0, zf = zv1, zg = zv2, zo = zv3;
            if (s) {
                zi += zS[ub][ud]; zf += zS[ub][8 + ud];
                zg += zS[ub][16 + ud]; zo += zS[ub][24 + ud];
            }
            float ct = sigf(zf) * cst + sigf(zi) * tanhf(zg);
            float h  = sigf(zo) * tanhf(ct);
            cst = ct;
            size_t oi = (size_t)(t * BB + ub) * G2U + dir * UU + d0 + ud;
            g_a[oi]  = h;
            g_aH[oi] = __float2half(h);
        }
    }
    __syncthreads();
    if (tid == 0) {
        __threadfence();
        if (atomicAdd(&g_efin[dir], 1) == 63) {
            for (int i = 0; i < TT; i++) bar[i] = 0;
            g_efin[dir] = 0;
        }
    }
}

// ---------------- aW1 = a @ W1[:1024] + b1 -> half, pitch 12 ----------------
__global__ __launch_bounds__(128) void k_aw1(const float* __restrict__ W1,
                                             const float* __restrict__ b1)
{
    __shared__ float red[128][10];
    int r = blockIdx.x;
    int tid = threadIdx.x;
    float acc[10];
#pragma unroll
    for (int j = 0; j < 10; j++) acc[j] = 0.f;
    for (int k = tid; k < G2U; k += 128) {
        float av = g_a[(size_t)r * G2U + k];
#pragma unroll
        for (int j = 0; j < 10; j++) acc[j] += av * W1[(size_t)k * 10 + j];
    }
#pragma unroll
    for (int j = 0; j < 10; j++) red[tid][j] = acc[j];
    __syncthreads();
    for (int s = 64; s > 0; s >>= 1) {
        if (tid < s)
#pragma unroll
            for (int j = 0; j < 10; j++) red[tid][j] += red[tid + s][j];
        __syncthreads();
    }
    if (tid < 12)
        g_aW1H[(size_t)r * 12 + tid] = __float2half((tid < 10) ? (red[0][tid] + b1[tid]) : 0.f);
}

// ---------------- persistent fp16 attention decoder: 64 blocks, 8 dims each ----------------
#define D_WH_OFF  0
#define D_WH_B    (32 * 520 * 2)
#define D_HS_OFF  (D_WH_OFF + D_WH_B)
#define D_HS_B    (32 * 520 * 2)
#define D_AW_OFF  (D_HS_OFF + D_HS_B)
#define D_AW_B    (2048 * 12 * 2)
#define D_W1_OFF  (D_AW_OFF + D_AW_B)
#define D_W1_B    (10 * 520 * 2)
#define D_ZS_OFF  (D_W1_OFF + D_W1_B)
#define D_ZS_B    (32 * 36 * 4)
#define D_SC_OFF  (D_ZS_OFF + D_ZS_B)
#define D_SC_B    (32 * 64 * 4)
#define D_HW_OFF  (D_SC_OFF + D_SC_B)
#define D_HW_B    (32 * 10 * 4)
#define D_CX_OFF  (D_HW_OFF + D_HW_B)
#define D_CX_B    (32 * 32 * 4)
#define D_SMEM    (D_CX_OFF + D_CX_B)

__global__ __launch_bounds__(256) void k_decoder(
    const float* __restrict__ W2, const float* __restrict__ b2,
    const float* __restrict__ Whd, const float* __restrict__ bd)
{
    extern __shared__ char dsm[];
    __half (*WhS)[520]  = (__half(*)[520])(dsm + D_WH_OFF);
    __half (*hS)[520]   = (__half(*)[520])(dsm + D_HS_OFF);
    __half* aW1s        = (__half*)(dsm + D_AW_OFF);
    __half* W1TS        = (__half*)(dsm + D_W1_OFF);
    float  (*zS)[36]    = (float(*)[36])(dsm + D_ZS_OFF);
    float  (*scS)[64]   = (float(*)[64])(dsm + D_SC_OFF);
    float  (*hW1s)[10]  = (float(*)[10])(dsm + D_HW_OFF);
    float  (*ctxS)[32]  = (float(*)[32])(dsm + D_CX_OFF);

    int chunk = blockIdx.x, d0 = chunk << 3;
    int tid = threadIdx.x, lane = tid & 31, warp = tid >> 5;
    int gid = lane >> 2, tig = lane & 3;
    int mrow = (warp >> 2) << 4, ncol = (warp & 3) << 3;

    for (int idx = tid; idx < 32 * 512; idx += 256) {
        int j = idx >> 9, k = idx & 511;
        WhS[j][k] = __float2half(Whd[(size_t)k * G4U + (j >> 3) * DD + d0 + (j & 7)]);
    }
    for (int i = tid; i < D_AW_B / 16; i += 256)
        reinterpret_cast<uint4*>(aW1s)[i] = reinterpret_cast<const uint4*>(g_aW1H)[i];
    for (int j = 0; j < 10; j++)
        for (int k = tid; k < 512; k += 256)
            W1TS[j * 520 + k] = g_W1TH[j * 512 + k];

    float w2r[10];
#pragma unroll
    for (int j = 0; j < 10; j++) w2r[j] = W2[j];
    float b2s = b2[0];

    int cb = tid >> 3, cq = tid & 7, cj4 = cq >> 1, csh = cq & 1;
    const __half* ctx_base = g_aWxdH + (size_t)cb * G4U + chunk * 32 + cj4 * 8;

    int ub = tid >> 3, ud = tid & 7;
    float cst = 0.f;
    float bdv[4];
#pragma unroll
    for (int gg = 0; gg < 4; gg++) bdv[gg] = bd[gg * DD + d0 + ud];

    __syncthreads();

    for (int t = 0; t < TT; t++) {
        if (t) {
            bar_sync(&g_dbar[t], 64);
#pragma unroll
            for (int i = tid; i < 32 * 64; i += 256) {
                int b = i >> 6, k8 = (i & 63) << 3;
                uint4 v = *reinterpret_cast<const uint4*>(
                    &g_HdH[(size_t)((t - 1) * BB + b) * DD + k8]);
                *reinterpret_cast<uint4*>(&hS[b][k8]) = v;
            }
            __syncthreads();
            // hW1 = h @ W1[1024:1536] (all smem)
            for (int p = tid; p < 320; p += 256) {
                int b = p / 10, j = p % 10;
                const __half2* wt = reinterpret_cast<const __half2*>(&W1TS[j * 520]);
                const __half2* hb = reinterpret_cast<const __half2*>(&hS[b][0]);
                float a0 = 0.f, a1 = 0.f;
#pragma unroll 8
                for (int k2 = 0; k2 < 256; k2 += 2) {
                    float2 w0 = __half22float2(wt[k2]),     h0 = __half22float2(hb[k2]);
                    float2 w1 = __half22float2(wt[k2 + 1]), h1 = __half22float2(hb[k2 + 1]);
                    a0 += h0.x * w0.x + h0.y * w0.y;
                    a1 += h1.x * w1.x + h1.y * w1.y;
                }
                hW1s[b][j] = a0 + a1;
            }
        } else {
            for (int p = tid; p < 320; p += 256) hW1s[p / 10][p % 10] = 0.f;
        }
        __syncthreads();
        // attention energies
        for (int p = tid; p < 2048; p += 256) {
            int b = p & 31;
            const __half* aw = &aW1s[p * 12];
            float v = b2s;
#pragma unroll
            for (int j = 0; j < 10; j++)
                v += tanh_fast(__half2float(aw[j]) + hW1s[b][j]) * w2r[j];
            scS[b][p >> 5] = fmaxf(v, 0.f);
        }
        __syncthreads();
        // softmax over s per row (8 lanes per row)
        {
            int b = tid >> 3, g8 = tid & 7;
            float vv[8];
            float m = -1e30f;
#pragma unroll
            for (int q = 0; q < 8; q++) { vv[q] = scS[b][g8 * 8 + q]; m = fmaxf(m, vv[q]); }
#pragma unroll
            for (int o = 1; o < 8; o <<= 1) m = fmaxf(m, __shfl_xor_sync(0xffffffffu, m, o));
            float sm = 0.f;
#pragma unroll
            for (int q = 0; q < 8; q++) { vv[q] = __expf(vv[q] - m); sm += vv[q]; }
#pragma unroll
            for (int o = 1; o < 8; o <<= 1) sm += __shfl_xor_sync(0xffffffffu, sm, o);
            float inv = 1.f / sm;
#pragma unroll
            for (int q = 0; q < 8; q++) scS[b][g8 * 8 + q] = vv[q] * inv;
        }
        __syncthreads();
        // ctx: 8 cols per thread, 32 s-values (split over pairs)
        float ca[8] = {};
        {
            int s0 = csh << 5;
#pragma unroll 8
            for (int s5 = s0; s5 < s0 + 32; s5++) {
                float sc = scS[cb][s5];
                uint4 v = *reinterpret_cast<const uint4*>(ctx_base + (size_t)s5 * BB * G4U);
                float2 f0 = __half22float2(*(const __half2*)&v.x);
                float2 f1 = __half22float2(*(const __half2*)&v.y);
                float2 f2 = __half22float2(*(const __half2*)&v.z);
                float2 f3 = __half22float2(*(const __half2*)&v.w);
                ca[0] += sc * f0.x; ca[1] += sc * f0.y;
                ca[2] += sc * f1.x; ca[3] += sc * f1.y;
                ca[4] += sc * f2.x; ca[5] += sc * f2.y;
                ca[6] += sc * f3.x; ca[7] += sc * f3.y;
            }
        }
#pragma unroll
        for (int q = 0; q < 8; q++) ca[q] += __shfl_xor_sync(0xffffffffu, ca[q], 1);
        if (csh == 0) {
#pragma unroll
            for (int q = 0; q < 8; q++) ctxS[cb][cj4 * 8 + q] = ca[q];
        }
        // mma: h @ Whd slice, dual accumulator chains
        if (t) {
            float ac0[4] = {}, ac1[4] = {};
#pragma unroll 8
            for (int ks = 0; ks < 256; ks += 16) {
                int ks2 = ks + 256;
                uint32_t b0 = lds32(&WhS[ncol + gid][ks + 2 * tig]);
                uint32_t b1 = lds32(&WhS[ncol + gid][ks + 2 * tig + 8]);
                uint32_t a0 = lds32(&hS[mrow + gid    ][ks + 2 * tig]);
                uint32_t a1 = lds32(&hS[mrow + gid + 8][ks + 2 * tig]);
                uint32_t a2 = lds32(&hS[mrow + gid    ][ks + 2 * tig + 8]);
                uint32_t a3 = lds32(&hS[mrow + gid + 8][ks + 2 * tig + 8]);
                mma16h(ac0, a0, a1, a2, a3, b0, b1);
                uint32_t c0 = lds32(&WhS[ncol + gid][ks2 + 2 * tig]);
                uint32_t c1 = lds32(&WhS[ncol + gid][ks2 + 2 * tig + 8]);
                uint32_t e0 = lds32(&hS[mrow + gid    ][ks2 + 2 * tig]);
                uint32_t e1 = lds32(&hS[mrow + gid + 8][ks2 + 2 * tig]);
                uint32_t e2 = lds32(&hS[mrow + gid    ][ks2 + 2 * tig + 8]);
                uint32_t e3 = lds32(&hS[mrow + gid + 8][ks2 + 2 * tig + 8]);
                mma16h(ac1, e0, e1, e2, e3, c0, c1);
            }
            zS[mrow + gid    ][ncol + 2 * tig    ] = ac0[0] + ac1[0];
            zS[mrow + gid    ][ncol + 2 * tig + 1] = ac0[1] + ac1[1];
            zS[mrow + gid + 8][ncol + 2 * tig    ] = ac0[2] + ac1[2];
            zS[mrow + gid + 8][ncol + 2 * tig + 1] = ac0[3] + ac1[3];
        }
        __syncthreads();
        // cell update: 1 cell per thread
        {
            float z[4];
#pragma unroll
            for (int gg = 0; gg < 4; gg++) {
                float zz = ctxS[ub][gg * 8 + ud] + bdv[gg];
                if (t) zz += zS[ub][gg * 8 + ud];
                z[gg] = zz;
            }
            float ct = sigf(z[1]) * cst + sigf(z[0]) * tanhf(z[2]);
            float h  = sigf(z[3]) * tanhf(ct);
            cst = ct;
            g_HdH[(size_t)(t * BB + ub) * DD + d0 + ud] = __float2half(h);
        }
    }
    __syncthreads();
    if (tid == 0) {
        __threadfence();
        if (atomicAdd(&g_dfin, 1) == 63) {
            for (int i = 0; i < TT; i++) g_dbar[i] = 0;
            g_dfin = 0;
        }
    }
}

// ---------------- row softmax over V ----------------
__global__ void k_softmax_v(float* __restrict__ out) {
    extern __shared__ float row[];
    __shared__ float red[512];
    int r = blockIdx.x;
    float* p = out + (size_t)r * VV;
    int tid = threadIdx.x;
    float mx = -3.4e38f;
    for (int i = tid; i < VV; i += 512) { float v = p[i]; row[i] = v; mx = fmaxf(mx, v); }
    red[tid] = mx; __syncthreads();
    for (int s = 256; s > 0; s >>= 1) {
        if (tid < s) red[tid] = fmaxf(red[tid], red[tid + s]);
        __syncthreads();
    }
    mx = red[0]; __syncthreads();
    float sum = 0.f;
    for (int i = tid; i < VV; i += 512) { float e = __expf(row[i] - mx); row[i] = e; sum += e; }
    red[tid] = sum; __syncthreads();
    for (int s = 256; s > 0; s >>= 1) {
        if (tid < s) red[tid] += red[tid + s];
        __syncthreads();
    }
    float inv = 1.f / red[0];
    for (int i = tid; i < VV; i += 512) p[i] = row[i] * inv;
}

// ---------------- host driver ----------------
extern "C" void kernel_launch(void* const* d_in, const int* in_sizes, int n_in,
                              void* d_out, int out_size)
{
    (void)in_sizes; (void)n_in; (void)out_size;
    const int*   x   = (const int*)  d_in[0];
    const float* emb = (const float*)d_in[1];
    const float* Wxf = (const float*)d_in[2];
    const float* Whf = (const float*)d_in[3];
    const float* bf  = (const float*)d_in[4];
    const float* Wxb = (const float*)d_in[5];
    const float* Whb = (const float*)d_in[6];
    const float* bbv = (const float*)d_in[7];
    const float* W1  = (const float*)d_in[8];
    const float* b1  = (const float*)d_in[9];
    const float* W2  = (const float*)d_in[10];
    const float* b2  = (const float*)d_in[11];
    const float* Wxd = (const float*)d_in[12];
    const float* Whd = (const float*)d_in[13];
    const float* bd  = (const float*)d_in[14];
    const float* Wo  = (const float*)d_in[15];
    const float* bo  = (const float*)d_in[16];
    float* out = (float*)d_out;

    float *p_xe, *p_Zf, *p_Zb, *p_a;
    __half *p_HdH, *p_WoH, *p_aWxdH;
    cudaGetSymbolAddress((void**)&p_xe,    g_xe);
    cudaGetSymbolAddress((void**)&p_Zf,    g_Zf);
    cudaGetSymbolAddress((void**)&p_Zb,    g_Zb);
    cudaGetSymbolAddress((void**)&p_a,     g_a);
    cudaGetSymbolAddress((void**)&p_HdH,   g_HdH);
    cudaGetSymbolAddress((void**)&p_WoH,   g_WoH);
    cudaGetSymbolAddress((void**)&p_aWxdH, g_aWxdH);

    cudaFuncSetAttribute(k_gemm,      cudaFuncAttributeMaxDynamicSharedMemorySize, 75776);
    cudaFuncSetAttribute(k_gemm_f16,  cudaFuncAttributeMaxDynamicSharedMemorySize, F_SMEM);
    cudaFuncSetAttribute(k_encoder,   cudaFuncAttributeMaxDynamicSharedMemorySize, E_SMEM);
    cudaFuncSetAttribute(k_decoder,   cudaFuncAttributeMaxDynamicSharedMemorySize, D_SMEM);
    cudaFuncSetAttribute(k_softmax_v, cudaFuncAttributeMaxDynamicSharedMemorySize, VV * 4);

    k_embed<<<NTOK, 64>>>(x, emb);
    k_cvt_wo<<<dim3(VV / 32, DD / 32), dim3(32, 8)>>>(Wo);
    k_gemm<<<dim3(G4U / 128, NTOK / 128), 256, 75776>>>(p_xe, Wxf, bf,  p_Zf, nullptr, NTOK, G4U, EE);
    k_gemm<<<dim3(G4U / 128, NTOK / 128), 256, 75776>>>(p_xe, Wxb, bbv, p_Zb, nullptr, NTOK, G4U, EE);
    k_encoder<<<128, 256, E_SMEM>>>(Whf, Whb);
    k_gemm<<<dim3(G4U / 128, NTOK / 128), 256, 75776>>>(p_a, Wxd, nullptr, nullptr, p_aWxdH, NTOK, G4U, G2U);
    k_aw1<<<NTOK, 128>>>(W1, b1);
    k_w1t<<<10, 512>>>(W1);
    k_decoder<<<64, 256, D_SMEM>>>(W2, b2, Whd, bd);
    k_gemm_f16<<<dim3(VV / 128, NTOK / 128), 256, F_SMEM>>>(p_HdH, p_WoH, bo, out, NTOK, VV, DD);
    k_softmax_v<<<NTOK, 512, VV * 4>>>(out);
}

// round 8
// speedup vs baseline: 6.7906x; 1.3155x over previous
#include <cuda_runtime.h>
#include <cuda_fp16.h>
#include <cstdint>

#define BB   32
#define TT   64
#define EE   256
#define UU   512
#define DD   512
#define VV   32000
#define NTOK 2048
#define G4U  2048
#define G2U  1024
#define NTILES 4000          // (2048/128) * (32000/128)

// ---------------- scratch ----------------
__device__ float  g_xe   [NTOK * EE];
__device__ float  g_Zf   [NTOK * G4U];
__device__ float  g_Zb   [NTOK * G4U];
__device__ float  g_a    [NTOK * G2U];
__device__ __half g_aH   [NTOK * G2U];
__device__ __half g_aW1H [NTOK * 12];
__device__ __half g_aWxdH[NTOK * G4U];
__device__ __half g_HdH  [NTOK * DD];
__device__ __half g_WoH  [VV * DD];
__device__ __half g_W1TH [10 * 512];
__device__ int    g_ebar[2][TT];
__device__ int    g_efin[2];
__device__ int    g_dbar[TT];
__device__ int    g_dfin;
__device__ int    g_dprog;   // decoder step completion counter (64 per step)
__device__ int    g_tile;    // gemm tile dispenser
__device__ int    g_gfin;    // gemm role finish counter

__device__ __forceinline__ float sigf(float x) { return 1.f / (1.f + __expf(-x)); }
__device__ __forceinline__ float tanh_fast(float x) {
    float r; asm("tanh.approx.f32 %0, %1;" : "=f"(r) : "f"(x)); return r;
}

__device__ __forceinline__ void bar_sync(int* slot, int n) {
    __syncthreads();
    if (threadIdx.x == 0) {
        asm volatile("red.release.gpu.global.add.s32 [%0], 1;" :: "l"(slot) : "memory");
        int v;
        do {
            asm volatile("ld.acquire.gpu.global.b32 %0, [%1];" : "=r"(v) : "l"(slot) : "memory");
        } while (v < n);
    }
    __syncthreads();
}

__device__ __forceinline__ void mma8(float* c, uint32_t a0, uint32_t a1, uint32_t a2, uint32_t a3,
                                     uint32_t b0, uint32_t b1) {
    asm volatile(
        "mma.sync.aligned.m16n8k8.row.col.f32.tf32.tf32.f32 "
        "{%0,%1,%2,%3}, {%4,%5,%6,%7}, {%8,%9}, {%0,%1,%2,%3};\n"
        : "+f"(c[0]), "+f"(c[1]), "+f"(c[2]), "+f"(c[3])
        : "r"(a0), "r"(a1), "r"(a2), "r"(a3), "r"(b0), "r"(b1));
}

__device__ __forceinline__ void mma16h(float* c, uint32_t a0, uint32_t a1, uint32_t a2, uint32_t a3,
                                       uint32_t b0, uint32_t b1) {
    asm volatile(
        "mma.sync.aligned.m16n8k16.row.col.f32.f16.f16.f32 "
        "{%0,%1,%2,%3}, {%4,%5,%6,%7}, {%8,%9}, {%0,%1,%2,%3};\n"
        : "+f"(c[0]), "+f"(c[1]), "+f"(c[2]), "+f"(c[3])
        : "r"(a0), "r"(a1), "r"(a2), "r"(a3), "r"(b0), "r"(b1));
}

__device__ __forceinline__ uint32_t lds32(const __half* p) { return *(const uint32_t*)p; }

// ---------------- embedding gather ----------------
__global__ void k_embed(const int* __restrict__ x, const float* __restrict__ emb) {
    int row = blockIdx.x;
    int t = row >> 5, b = row & 31;
    int tok = x[b * TT + t];
    const float4* src = reinterpret_cast<const float4*>(emb + (size_t)tok * EE);
    float4* dst = reinterpret_cast<float4*>(g_xe + (size_t)row * EE);
    dst[threadIdx.x] = src[threadIdx.x];
}

// ---------------- Wo convert + transpose ----------------
__global__ void k_cvt_wo(const float* __restrict__ Wo) {
    __shared__ float t[32][33];
    int n0 = blockIdx.x << 5, k0 = blockIdx.y << 5;
    for (int i = threadIdx.y; i < 32; i += 8)
        t[i][threadIdx.x] = Wo[(size_t)(k0 + i) * VV + n0 + threadIdx.x];
    __syncthreads();
    for (int i = threadIdx.y; i < 32; i += 8)
        g_WoH[(size_t)(n0 + i) * DD + k0 + threadIdx.x] = __float2half(t[threadIdx.x][i]);
}

// ---------------- W1 decoder-half transpose ----------------
__global__ void k_w1t(const float* __restrict__ W1) {
    int j = blockIdx.x;
    for (int k = threadIdx.x; k < 512; k += blockDim.x)
        g_W1TH[j * 512 + k] = __float2half(W1[(size_t)(G2U + k) * 10 + j]);
}

// ---------------- tf32 GEMM (double-buffered); Ch!=null -> permuted half output ----------------
__global__ __launch_bounds__(256) void k_gemm(
    const float* __restrict__ A, const float* __restrict__ B,
    const float* __restrict__ bias, float* __restrict__ C, __half* __restrict__ Ch,
    int M, int N, int K)
{
    extern __shared__ char gsm[];
    uint32_t (*As)[128][40] = (uint32_t(*)[128][40])gsm;
    uint32_t (*Bs)[32][136] = (uint32_t(*)[32][136])(gsm + 2 * 128 * 40 * 4);
    int tid = threadIdx.x, lane = tid & 31, warp = tid >> 5;
    int gid = lane >> 2, tig = lane & 3;
    int wm = warp & 3, wn = warp >> 2;
    int m0 = blockIdx.y << 7, n0 = blockIdx.x << 7;
    int ntile = K >> 5;
    float acc[2][8][4] = {};

    auto issue = [&](int kt) {
        int st = kt & 1;
        int k0 = kt << 5;
#pragma unroll
        for (int i = 0; i < 4; i++) {
            int idx = tid + (i << 8);
            int r = idx >> 3, c4 = (idx & 7) << 2;
            uint32_t d = (uint32_t)__cvta_generic_to_shared(&As[st][r][c4]);
            const float* s = A + (size_t)(m0 + r) * K + k0 + c4;
            asm volatile("cp.async.cg.shared.global [%0], [%1], 16;\n" :: "r"(d), "l"(s));
        }
#pragma unroll
        for (int i = 0; i < 4; i++) {
            int idx = tid + (i << 8);
            int r = idx >> 5, c4 = (idx & 31) << 2;
            uint32_t d = (uint32_t)__cvta_generic_to_shared(&Bs[st][r][c4]);
            const float* s = B + (size_t)(k0 + r) * N + n0 + c4;
            asm volatile("cp.async.cg.shared.global [%0], [%1], 16;\n" :: "r"(d), "l"(s));
        }
        asm volatile("cp.async.commit_group;\n");
    };

    issue(0);
    for (int kt = 0; kt < ntile; kt++) {
        if (kt + 1 < ntile) { issue(kt + 1); asm volatile("cp.async.wait_group 1;\n"); }
        else                 { asm volatile("cp.async.wait_group 0;\n"); }
        __syncthreads();
        int st = kt & 1;
#pragma unroll
        for (int kk = 0; kk < 32; kk += 8) {
            uint32_t af[2][4];
#pragma unroll
            for (int mt = 0; mt < 2; mt++) {
                int rb = (wm << 5) + (mt << 4);
                af[mt][0] = As[st][rb + gid    ][kk + tig];
                af[mt][1] = As[st][rb + gid + 8][kk + tig];
                af[mt][2] = As[st][rb + gid    ][kk + tig + 4];
                af[mt][3] = As[st][rb + gid + 8][kk + tig + 4];
            }
#pragma unroll
            for (int nt = 0; nt < 8; nt++) {
                uint32_t b0 = Bs[st][kk + tig    ][(wn << 6) + (nt << 3) + gid];
                uint32_t b1 = Bs[st][kk + tig + 4][(wn << 6) + (nt << 3) + gid];
#pragma unroll
                for (int mt = 0; mt < 2; mt++)
                    mma8(acc[mt][nt], af[mt][0], af[mt][1], af[mt][2], af[mt][3], b0, b1);
            }
        }
        __syncthreads();
    }
#pragma unroll
    for (int mt = 0; mt < 2; mt++) {
#pragma unroll
        for (int nt = 0; nt < 8; nt++) {
            int col = n0 + (wn << 6) + (nt << 3) + (tig << 1);
            int r0 = m0 + (wm << 5) + (mt << 4) + gid;
            int r1 = r0 + 8;
            if (Ch) {
                int d = col & 511, gate = col >> 9;
                int nc = ((d >> 3) << 5) + (gate << 3) + (d & 7);
                *reinterpret_cast<__half2*>(Ch + (size_t)r0 * N + nc) =
                    __floats2half2_rn(acc[mt][nt][0], acc[mt][nt][1]);
                *reinterpret_cast<__half2*>(Ch + (size_t)r1 * N + nc) =
                    __floats2half2_rn(acc[mt][nt][2], acc[mt][nt][3]);
            } else {
                float b0v = bias ? bias[col]     : 0.f;
                float b1v = bias ? bias[col + 1] : 0.f;
                float2 v0 = make_float2(acc[mt][nt][0] + b0v, acc[mt][nt][1] + b1v);
                float2 v1 = make_float2(acc[mt][nt][2] + b0v, acc[mt][nt][3] + b1v);
                *reinterpret_cast<float2*>(C + (size_t)r0 * N + col) = v0;
                *reinterpret_cast<float2*>(C + (size_t)r1 * N + col) = v1;
            }
        }
    }
}

// ---------------- persistent fp16 encoder: 128 blocks (64/dir), 8 dims each ----------------
#define E_WH_B (32 * 520 * 2)
#define E_HS_B (32 * 520 * 2)
#define E_ZS_B (32 * 36 * 4)
#define E_SMEM (E_WH_B + E_HS_B + E_ZS_B)

__global__ __launch_bounds__(256) void k_encoder(const float* __restrict__ Whf,
                                                 const float* __restrict__ Whb)
{
    extern __shared__ char esm[];
    __half (*WhS)[520] = (__half(*)[520])esm;
    __half (*hS)[520]  = (__half(*)[520])(esm + E_WH_B);
    float  (*zS)[36]   = (float(*)[36])(esm + E_WH_B + E_HS_B);

    int dir = blockIdx.x >> 6, chunk = blockIdx.x & 63, d0 = chunk << 3;
    const float* Wh = dir ? Whb : Whf;
    const float* Z  = dir ? g_Zb : g_Zf;
    int tid = threadIdx.x, lane = tid & 31, warp = tid >> 5;
    int gid = lane >> 2, tig = lane & 3;
    int mrow = (warp >> 2) << 4, ncol = (warp & 3) << 3;
    int* bar = &g_ebar[dir][0];

    for (int idx = tid; idx < 32 * 512; idx += 256) {
        int j = idx >> 9, k = idx & 511;
        WhS[j][k] = __float2half(Wh[(size_t)k * G4U + (j >> 3) * UU + d0 + (j & 7)]);
    }

    int ub = tid >> 3, ud = tid & 7;
    float cst = 0.f;

    for (int s = 0; s < TT; s++) {
        int t = dir ? (TT - 1 - s) : s;
        size_t zrow = (size_t)(t * BB + ub) * G4U + d0 + ud;
        float zv0 = Z[zrow];
        float zv1 = Z[zrow + UU];
        float zv2 = Z[zrow + 2 * UU];
        float zv3 = Z[zrow + 3 * UU];
        if (s) {
            bar_sync(&bar[s], 64);
            int tp = dir ? (t + 1) : (t - 1);
#pragma unroll
            for (int i = tid; i < 32 * 64; i += 256) {
                int b = i >> 6, k8 = (i & 63) << 3;
                uint4 v = *reinterpret_cast<const uint4*>(
                    &g_aH[(size_t)(tp * BB + b) * G2U + dir * UU + k8]);
                *reinterpret_cast<uint4*>(&hS[b][k8]) = v;
            }
            __syncthreads();
            float ac0[4] = {}, ac1[4] = {};
#pragma unroll 8
            for (int ks = 0; ks < 256; ks += 16) {
                int ks2 = ks + 256;
                uint32_t b0 = lds32(&WhS[ncol + gid][ks + 2 * tig]);
                uint32_t b1 = lds32(&WhS[ncol + gid][ks + 2 * tig + 8]);
                uint32_t a0 = lds32(&hS[mrow + gid    ][ks + 2 * tig]);
                uint32_t a1 = lds32(&hS[mrow + gid + 8][ks + 2 * tig]);
                uint32_t a2 = lds32(&hS[mrow + gid    ][ks + 2 * tig + 8]);
                uint32_t a3 = lds32(&hS[mrow + gid + 8][ks + 2 * tig + 8]);
                mma16h(ac0, a0, a1, a2, a3, b0, b1);
                uint32_t c0 = lds32(&WhS[ncol + gid][ks2 + 2 * tig]);
                uint32_t c1 = lds32(&WhS[ncol + gid][ks2 + 2 * tig + 8]);
                uint32_t d0r = lds32(&hS[mrow + gid    ][ks2 + 2 * tig]);
                uint32_t d1r = lds32(&hS[mrow + gid + 8][ks2 + 2 * tig]);
                uint32_t d2r = lds32(&hS[mrow + gid    ][ks2 + 2 * tig + 8]);
                uint32_t d3r = lds32(&hS[mrow + gid + 8][ks2 + 2 * tig + 8]);
                mma16h(ac1, d0r, d1r, d2r, d3r, c0, c1);
            }
            zS[mrow + gid    ][ncol + 2 * tig    ] = ac0[0] + ac1[0];
            zS[mrow + gid    ][ncol + 2 * tig + 1] = ac0[1] + ac1[1];
            zS[mrow + gid + 8][ncol + 2 * tig    ] = ac0[2] + ac1[2];
            zS[mrow + gid + 8][ncol + 2 * tig + 1] = ac0[3] + ac1[3];
            __syncthreads();
        }
        {
            float zi = zv0, zf = zv1, zg = zv2, zo = zv3;
            if (s) {
                zi += zS[ub][ud]; zf += zS[ub][8 + ud];
                zg += zS[ub][16 + ud]; zo += zS[ub][24 + ud];
            }
            float ct = sigf(zf) * cst + sigf(zi) * tanhf(zg);
            float h  = sigf(zo) * tanhf(ct);
            cst = ct;
            size_t oi = (size_t)(t * BB + ub) * G2U + dir * UU + d0 + ud;
            g_a[oi]  = h;
            g_aH[oi] = __float2half(h);
        }
    }
    __syncthreads();
    if (tid == 0) {
        __threadfence();
        if (atomicAdd(&g_efin[dir], 1) == 63) {
            for (int i = 0; i < TT; i++) bar[i] = 0;
            g_efin[dir] = 0;
        }
    }
}

// ---------------- aW1 = a @ W1[:1024] + b1 -> half, pitch 12 ----------------
__global__ __launch_bounds__(128) void k_aw1(const float* __restrict__ W1,
                                             const float* __restrict__ b1)
{
    __shared__ float red[128][10];
    int r = blockIdx.x;
    int tid = threadIdx.x;
    float acc[10];
#pragma unroll
    for (int j = 0; j < 10; j++) acc[j] = 0.f;
    for (int k = tid; k < G2U; k += 128) {
        float av = g_a[(size_t)r * G2U + k];
#pragma unroll
        for (int j = 0; j < 10; j++) acc[j] += av * W1[(size_t)k * 10 + j];
    }
#pragma unroll
    for (int j = 0; j < 10; j++) red[tid][j] = acc[j];
    __syncthreads();
    for (int s = 64; s > 0; s >>= 1) {
        if (tid < s)
#pragma unroll
            for (int j = 0; j < 10; j++) red[tid][j] += red[tid + s][j];
        __syncthreads();
    }
    if (tid < 12)
        g_aW1H[(size_t)r * 12 + tid] = __float2half((tid < 10) ? (red[0][tid] + b1[tid]) : 0.f);
}

// ---------------- fused decoder + logits GEMM ----------------
#define D_WH_OFF  0
#define D_WH_B    (32 * 520 * 2)
#define D_HS_OFF  (D_WH_OFF + D_WH_B)
#define D_HS_B    (32 * 520 * 2)
#define D_AW_OFF  (D_HS_OFF + D_HS_B)
#define D_AW_B    (2048 * 12 * 2)
#define D_W1_OFF  (D_AW_OFF + D_AW_B)
#define D_W1_B    (10 * 520 * 2)
#define D_ZS_OFF  (D_W1_OFF + D_W1_B)
#define D_ZS_B    (32 * 36 * 4)
#define D_SC_OFF  (D_ZS_OFF + D_ZS_B)
#define D_SC_B    (32 * 64 * 4)
#define D_HW_OFF  (D_SC_OFF + D_SC_B)
#define D_HW_B    (32 * 10 * 4)
#define D_CX_OFF  (D_HW_OFF + D_HW_B)
#define D_CX_B    (32 * 32 * 4)
#define D_SMEM    (D_CX_OFF + D_CX_B)

// gemm-role tile: C[m0:m0+128, n0:n0+128] = HdH @ WoH^T + bo, remapped rows
__device__ void gemm_tile(char* fsm, const float* __restrict__ bias,
                          float* __restrict__ C, int m0, int n0)
{
    __half (*As)[128][40] = (__half(*)[128][40])fsm;
    __half (*Bs)[128][40] = (__half(*)[128][40])(fsm + 3 * 128 * 40 * 2);
    const __half* A  = g_HdH;
    const __half* Bt = g_WoH;
    const int N = VV, K = DD;
    int tid = threadIdx.x, lane = tid & 31, warp = tid >> 5;
    int gid = lane >> 2, tig = lane & 3;
    int wm = warp & 3, wn = warp >> 2;
    float acc[2][8][4] = {};

    auto issue = [&](int kt) {
        int st = kt % 3;
        int k0 = kt << 5;
#pragma unroll
        for (int i = 0; i < 2; i++) {
            int idx = tid + (i << 8);
            int r = idx >> 2, c = (idx & 3) << 3;
            uint32_t d = (uint32_t)__cvta_generic_to_shared(&As[st][r][c]);
            const __half* s = A + (size_t)(m0 + r) * K + k0 + c;
            asm volatile("cp.async.cg.shared.global [%0], [%1], 16;\n" :: "r"(d), "l"(s));
        }
#pragma unroll
        for (int i = 0; i < 2; i++) {
            int idx = tid + (i << 8);
            int r = idx >> 2, c = (idx & 3) << 3;
            uint32_t d = (uint32_t)__cvta_generic_to_shared(&Bs[st][r][c]);
            const __half* s = Bt + (size_t)(n0 + r) * K + k0 + c;
            asm volatile("cp.async.cg.shared.global [%0], [%1], 16;\n" :: "r"(d), "l"(s));
        }
        asm volatile("cp.async.commit_group;\n");
    };

    issue(0); issue(1);
#pragma unroll 1
    for (int kt = 0; kt < 16; kt++) {
        if (kt + 2 < 16)      { issue(kt + 2); asm volatile("cp.async.wait_group 2;\n"); }
        else if (kt + 1 < 16) { asm volatile("cp.async.wait_group 1;\n"); }
        else                  { asm volatile("cp.async.wait_group 0;\n"); }
        __syncthreads();
        int st = kt % 3;
#pragma unroll
        for (int ks = 0; ks < 32; ks += 16) {
            uint32_t af[2][4];
#pragma unroll
            for (int mt = 0; mt < 2; mt++) {
                int rb = (wm << 5) + (mt << 4);
                af[mt][0] = *(const uint32_t*)&As[st][rb + gid    ][ks + 2 * tig];
                af[mt][1] = *(const uint32_t*)&As[st][rb + gid + 8][ks + 2 * tig];
                af[mt][2] = *(const uint32_t*)&As[st][rb + gid    ][ks + 2 * tig + 8];
                af[mt][3] = *(const uint32_t*)&As[st][rb + gid + 8][ks + 2 * tig + 8];
            }
#pragma unroll
            for (int nt = 0; nt < 8; nt++) {
                int n = (wn << 6) + (nt << 3) + gid;
                uint32_t b0 = *(const uint32_t*)&Bs[st][n][ks + 2 * tig];
                uint32_t b1 = *(const uint32_t*)&Bs[st][n][ks + 2 * tig + 8];
#pragma unroll
                for (int mt = 0; mt < 2; mt++)
                    mma16h(acc[mt][nt], af[mt][0], af[mt][1], af[mt][2], af[mt][3], b0, b1);
            }
        }
        __syncthreads();
    }
#pragma unroll
    for (int mt = 0; mt < 2; mt++) {
#pragma unroll
        for (int nt = 0; nt < 8; nt++) {
            int col = n0 + (wn << 6) + (nt << 3) + (tig << 1);
            float b0v = bias[col], b1v = bias[col + 1];
            int r0 = m0 + (wm << 5) + (mt << 4) + gid;
            int r1 = r0 + 8;
            int or0 = (r0 & 31) * TT + (r0 >> 5);
            int or1 = (r1 & 31) * TT + (r1 >> 5);
            float2 v0 = make_float2(acc[mt][nt][0] + b0v, acc[mt][nt][1] + b1v);
            float2 v1 = make_float2(acc[mt][nt][2] + b0v, acc[mt][nt][3] + b1v);
            *reinterpret_cast<float2*>(C + (size_t)or0 * VV + col) = v0;
            *reinterpret_cast<float2*>(C + (size_t)or1 * VV + col) = v1;
        }
    }
}

__global__ __launch_bounds__(256) void k_dec_gemm(
    const float* __restrict__ W2, const float* __restrict__ b2,
    const float* __restrict__ Whd, const float* __restrict__ bd,
    const float* __restrict__ bo, float* __restrict__ out)
{
    extern __shared__ char dsm[];
    __shared__ int s_tile;
    int tid = threadIdx.x;

    if (blockIdx.x < 64) {
        // ---------------- decoder role ----------------
        __half (*WhS)[520]  = (__half(*)[520])(dsm + D_WH_OFF);
        __half (*hS)[520]   = (__half(*)[520])(dsm + D_HS_OFF);
        __half* aW1s        = (__half*)(dsm + D_AW_OFF);
        __half* W1TS        = (__half*)(dsm + D_W1_OFF);
        float  (*zS)[36]    = (float(*)[36])(dsm + D_ZS_OFF);
        float  (*scS)[64]   = (float(*)[64])(dsm + D_SC_OFF);
        float  (*hW1s)[10]  = (float(*)[10])(dsm + D_HW_OFF);
        float  (*ctxS)[32]  = (float(*)[32])(dsm + D_CX_OFF);

        int chunk = blockIdx.x, d0 = chunk << 3;
        int lane = tid & 31, warp = tid >> 5;
        int gid = lane >> 2, tig = lane & 3;
        int mrow = (warp >> 2) << 4, ncol = (warp & 3) << 3;

        for (int idx = tid; idx < 32 * 512; idx += 256) {
            int j = idx >> 9, k = idx & 511;
            WhS[j][k] = __float2half(Whd[(size_t)k * G4U + (j >> 3) * DD + d0 + (j & 7)]);
        }
        for (int i = tid; i < D_AW_B / 16; i += 256)
            reinterpret_cast<uint4*>(aW1s)[i] = reinterpret_cast<const uint4*>(g_aW1H)[i];
        for (int j = 0; j < 10; j++)
            for (int k = tid; k < 512; k += 256)
                W1TS[j * 520 + k] = g_W1TH[j * 512 + k];

        float w2r[10];
#pragma unroll
        for (int j = 0; j < 10; j++) w2r[j] = W2[j];
        float b2s = b2[0];

        int cb = tid >> 3, cq = tid & 7, cj4 = cq >> 1, csh = cq & 1;
        const __half* ctx_base = g_aWxdH + (size_t)cb * G4U + chunk * 32 + cj4 * 8;

        int ub = tid >> 3, ud = tid & 7;
        float cst = 0.f;
        float bdv[4];
#pragma unroll
        for (int gg = 0; gg < 4; gg++) bdv[gg] = bd[gg * DD + d0 + ud];

        __syncthreads();

        for (int t = 0; t < TT; t++) {
            if (t) {
                bar_sync(&g_dbar[t], 64);
#pragma unroll
                for (int i = tid; i < 32 * 64; i += 256) {
                    int b = i >> 6, k8 = (i & 63) << 3;
                    uint4 v = *reinterpret_cast<const uint4*>(
                        &g_HdH[(size_t)((t - 1) * BB + b) * DD + k8]);
                    *reinterpret_cast<uint4*>(&hS[b][k8]) = v;
                }
                __syncthreads();
                for (int p = tid; p < 320; p += 256) {
                    int b = p / 10, j = p % 10;
                    const __half2* wt = reinterpret_cast<const __half2*>(&W1TS[j * 520]);
                    const __half2* hb = reinterpret_cast<const __half2*>(&hS[b][0]);
                    float a0 = 0.f, a1 = 0.f;
#pragma unroll 8
                    for (int k2 = 0; k2 < 256; k2 += 2) {
                        float2 w0 = __half22float2(wt[k2]),     h0 = __half22float2(hb[k2]);
                        float2 w1 = __half22float2(wt[k2 + 1]), h1 = __half22float2(hb[k2 + 1]);
                        a0 += h0.x * w0.x + h0.y * w0.y;
                        a1 += h1.x * w1.x + h1.y * w1.y;
                    }
                    hW1s[b][j] = a0 + a1;
                }
            } else {
                for (int p = tid; p < 320; p += 256) hW1s[p / 10][p % 10] = 0.f;
            }
            __syncthreads();
            for (int p = tid; p < 2048; p += 256) {
                int b = p & 31;
                const __half* aw = &aW1s[p * 12];
                float v = b2s;
#pragma unroll
                for (int j = 0; j < 10; j++)
                    v += tanh_fast(__half2float(aw[j]) + hW1s[b][j]) * w2r[j];
                scS[b][p >> 5] = fmaxf(v, 0.f);
            }
            __syncthreads();
            {
                int b = tid >> 3, g8 = tid & 7;
                float vv[8];
                float m = -1e30f;
#pragma unroll
                for (int q = 0; q < 8; q++) { vv[q] = scS[b][g8 * 8 + q]; m = fmaxf(m, vv[q]); }
#pragma unroll
                for (int o = 1; o < 8; o <<= 1) m = fmaxf(m, __shfl_xor_sync(0xffffffffu, m, o));
                float sm = 0.f;
#pragma unroll
                for (int q = 0; q < 8; q++) { vv[q] = __expf(vv[q] - m); sm += vv[q]; }
#pragma unroll
                for (int o = 1; o < 8; o <<= 1) sm += __shfl_xor_sync(0xffffffffu, sm, o);
                float inv = 1.f / sm;
#pragma unroll
                for (int q = 0; q < 8; q++) scS[b][g8 * 8 + q] = vv[q] * inv;
            }
            __syncthreads();
            float ca[8] = {};
            {
                int s0 = csh << 5;
#pragma unroll 8
                for (int s5 = s0; s5 < s0 + 32; s5++) {
                    float sc = scS[cb][s5];
                    uint4 v = *reinterpret_cast<const uint4*>(ctx_base + (size_t)s5 * BB * G4U);
                    float2 f0 = __half22float2(*(const __half2*)&v.x);
                    float2 f1 = __half22float2(*(const __half2*)&v.y);
                    float2 f2 = __half22float2(*(const __half2*)&v.z);
                    float2 f3 = __half22float2(*(const __half2*)&v.w);
                    ca[0] += sc * f0.x; ca[1] += sc * f0.y;
                    ca[2] += sc * f1.x; ca[3] += sc * f1.y;
                    ca[4] += sc * f2.x; ca[5] += sc * f2.y;
                    ca[6] += sc * f3.x; ca[7] += sc * f3.y;
                }
            }
#pragma unroll
            for (int q = 0; q < 8; q++) ca[q] += __shfl_xor_sync(0xffffffffu, ca[q], 1);
            if (csh == 0) {
#pragma unroll
                for (int q = 0; q < 8; q++) ctxS[cb][cj4 * 8 + q] = ca[q];
            }
            if (t) {
                float ac0[4] = {}, ac1[4] = {};
#pragma unroll 8
                for (int ks = 0; ks < 256; ks += 16) {
                    int ks2 = ks + 256;
                    uint32_t b0 = lds32(&WhS[ncol + gid][ks + 2 * tig]);
                    uint32_t b1 = lds32(&WhS[ncol + gid][ks + 2 * tig + 8]);
                    uint32_t a0 = lds32(&hS[mrow + gid    ][ks + 2 * tig]);
                    uint32_t a1 = lds32(&hS[mrow + gid + 8][ks + 2 * tig]);
                    uint32_t a2 = lds32(&hS[mrow + gid    ][ks + 2 * tig + 8]);
                    uint32_t a3 = lds32(&hS[mrow + gid + 8][ks + 2 * tig + 8]);
                    mma16h(ac0, a0, a1, a2, a3, b0, b1);
                    uint32_t c0 = lds32(&WhS[ncol + gid][ks2 + 2 * tig]);
                    uint32_t c1 = lds32(&WhS[ncol + gid][ks2 + 2 * tig + 8]);
                    uint32_t e0 = lds32(&hS[mrow + gid    ][ks2 + 2 * tig]);
                    uint32_t e1 = lds32(&hS[mrow + gid + 8][ks2 + 2 * tig]);
                    uint32_t e2 = lds32(&hS[mrow + gid    ][ks2 + 2 * tig + 8]);
                    uint32_t e3 = lds32(&hS[mrow + gid + 8][ks2 + 2 * tig + 8]);
                    mma16h(ac1, e0, e1, e2, e3, c0, c1);
                }
                zS[mrow + gid    ][ncol + 2 * tig    ] = ac0[0] + ac1[0];
                zS[mrow + gid    ][ncol + 2 * tig + 1] = ac0[1] + ac1[1];
                zS[mrow + gid + 8][ncol + 2 * tig    ] = ac0[2] + ac1[2];
                zS[mrow + gid + 8][ncol + 2 * tig + 1] = ac0[3] + ac1[3];
            }
            __syncthreads();
            {
                float z[4];
#pragma unroll
                for (int gg = 0; gg < 4; gg++) {
                    float zz = ctxS[ub][gg * 8 + ud] + bdv[gg];
                    if (t) zz += zS[ub][gg * 8 + ud];
                    z[gg] = zz;
                }
                float ct = sigf(z[1]) * cst + sigf(z[0]) * tanhf(z[2]);
                float h  = sigf(z[3]) * tanhf(ct);
                cst = ct;
                g_HdH[(size_t)(t * BB + ub) * DD + d0 + ud] = __float2half(h);
            }
            // signal step completion to gemm role
            __syncthreads();
            if (tid == 0)
                asm volatile("red.release.gpu.global.add.s32 [%0], 1;" :: "l"(&g_dprog) : "memory");
        }
        __syncthreads();
        if (tid == 0) {
            __threadfence();
            if (atomicAdd(&g_dfin, 1) == 63) {
                for (int i = 0; i < TT; i++) g_dbar[i] = 0;
                g_dfin = 0;
            }
        }
        __syncthreads();
    }

    // ---------------- gemm role (all blocks; decoder blocks join after finishing) ----------------
    for (;;) {
        if (tid == 0) s_tile = atomicAdd(&g_tile, 1);
        __syncthreads();
        int tile = s_tile;
        __syncthreads();
        if (tile >= NTILES) break;
        int mt5 = tile / 250, nt5 = tile % 250;
        // wait until decoder finished steps covering rows [mt5*128, mt5*128+127]
        __syncthreads();
        if (tid == 0) {
            int thr = 256 * (mt5 + 1);
            int v;
            do {
                asm volatile("ld.acquire.gpu.global.b32 %0, [%1];" : "=r"(v) : "l"(&g_dprog) : "memory");
            } while (v < thr);
        }
        __syncthreads();
        gemm_tile(dsm, bo, out, mt5 << 7, nt5 << 7);
    }
    if (tid == 0) {
        if (atomicAdd(&g_gfin, 1) == 147) {
            g_tile = 0;
            g_gfin = 0;
            g_dprog = 0;
        }
    }
}

// ---------------- row softmax over V ----------------
__global__ void k_softmax_v(float* __restrict__ out) {
    extern __shared__ float row[];
    __shared__ float red[1024];
    int r = blockIdx.x;
    float* p = out + (size_t)r * VV;
    int tid = threadIdx.x;
    float mx = -3.4e38f;
    for (int i = tid; i < VV; i += 1024) { float v = p[i]; row[i] = v; mx = fmaxf(mx, v); }
    red[tid] = mx; __syncthreads();
    for (int s = 512; s > 0; s >>= 1) {
        if (tid < s) red[tid] = fmaxf(red[tid], red[tid + s]);
        __syncthreads();
    }
    mx = red[0]; __syncthreads();
    float sum = 0.f;
    for (int i = tid; i < VV; i += 1024) { float e = __expf(row[i] - mx); row[i] = e; sum += e; }
    red[tid] = sum; __syncthreads();
    for (int s = 512; s > 0; s >>= 1) {
        if (tid < s) red[tid] += red[tid + s];
        __syncthreads();
    }
    float inv = 1.f / red[0];
    for (int i = tid; i < VV; i += 1024) p[i] = row[i] * inv;
}

// ---------------- host driver ----------------
extern "C" void kernel_launch(void* const* d_in, const int* in_sizes, int n_in,
                              void* d_out, int out_size)
{
    (void)in_sizes; (void)n_in; (void)out_size;
    const int*   x   = (const int*)  d_in[0];
    const float* emb = (const float*)d_in[1];
    const float* Wxf = (const float*)d_in[2];
    const float* Whf = (const float*)d_in[3];
    const float* bf  = (const float*)d_in[4];
    const float* Wxb = (const float*)d_in[5];
    const float* Whb = (const float*)d_in[6];
    const float* bbv = (const float*)d_in[7];
    const float* W1  = (const float*)d_in[8];
    const float* b1  = (const float*)d_in[9];
    const float* W2  = (const float*)d_in[10];
    const float* b2  = (const float*)d_in[11];
    const float* Wxd = (const float*)d_in[12];
    const float* Whd = (const float*)d_in[13];
    const float* bd  = (const float*)d_in[14];
    const float* Wo  = (const float*)d_in[15];
    const float* bo  = (const float*)d_in[16];
    float* out = (float*)d_out;

    float *p_xe, *p_Zf, *p_Zb, *p_a;
    __half *p_aWxdH;
    cudaGetSymbolAddress((void**)&p_xe,    g_xe);
    cudaGetSymbolAddress((void**)&p_Zf,    g_Zf);
    cudaGetSymbolAddress((void**)&p_Zb,    g_Zb);
    cudaGetSymbolAddress((void**)&p_a,     g_a);
    cudaGetSymbolAddress((void**)&p_aWxdH, g_aWxdH);

    cudaFuncSetAttribute(k_gemm,      cudaFuncAttributeMaxDynamicSharedMemorySize, 75776);
    cudaFuncSetAttribute(k_encoder,   cudaFuncAttributeMaxDynamicSharedMemorySize, E_SMEM);
    cudaFuncSetAttribute(k_dec_gemm,  cudaFuncAttributeMaxDynamicSharedMemorySize, D_SMEM);
    cudaFuncSetAttribute(k_softmax_v, cudaFuncAttributeMaxDynamicSharedMemorySize, VV * 4);

    k_embed<<<NTOK, 64>>>(x, emb);
    k_cvt_wo<<<dim3(VV / 32, DD / 32), dim3(32, 8)>>>(Wo);
    k_gemm<<<dim3(G4U / 128, NTOK / 128), 256, 75776>>>(p_xe, Wxf, bf,  p_Zf, nullptr, NTOK, G4U, EE);
    k_gemm<<<dim3(G4U / 128, NTOK / 128), 256, 75776>>>(p_xe, Wxb, bbv, p_Zb, nullptr, NTOK, G4U, EE);
    k_encoder<<<128, 256, E_SMEM>>>(Whf, Whb);
    k_gemm<<<dim3(G4U / 128, NTOK / 128), 256, 75776>>>(p_a, Wxd, nullptr, nullptr, p_aWxdH, NTOK, G4U, G2U);
    k_aw1<<<NTOK, 128>>>(W1, b1);
    k_w1t<<<10, 512>>>(W1);
    k_dec_gemm<<<148, 256, D_SMEM>>>(W2, b2, Whd, bd, bo, out);
    k_softmax_v<<<NTOK, 1024, VV * 4>>>(out);
}